// round 4
// baseline (speedup 1.0000x reference)
#include <cuda_runtime.h>

// NonLocalModule (no softmax) collapsed via associativity:
//   Q = Wq X + bq, K = Wk X + bk, V = Wv X + bv   (all C x N, C=128, N=6400)
//   out = Wo * V * K^T * Q / N + bo + X
//       = (E + I) X + e0,  with G = X X^T,
//   E  = (1/N)[A G Bm + (A s) w2^T + u (Bm^T s)^T] + u w2^T   (+ I folded in)
//   e0 = (1/N)[A G kq + (A s) beta + u (s.kq)] + u beta + bo
//   A = Wo Wv, Bm = Wk^T Wq, u = Wo bv, w2 = Wq^T bk, kq = Wk^T bq,
//   beta = bk.bq, s = X 1 (row sums).

#define C     128
#define NPIX  6400
#define BATCH 2
#define NT    50   /* n tiles of 128 */

// ---------------- device scratch (no allocations allowed) --------------------
__device__ float g_Gp[BATCH*NT*C*C];   // per-tile partial grams (deterministic split-K)
__device__ float g_sp[BATCH*NT*C];     // per-tile partial row-sums of X
__device__ float g_G [BATCH*C*C];
__device__ float g_s [BATCH*C];
__device__ float g_A [C*C];            // Wo Wv
__device__ float g_Bm[C*C];            // Wk^T Wq
__device__ float g_P [BATCH*C*C];      // A G
__device__ float g_E [BATCH*C*C];      // E + I
__device__ float g_e0[BATCH*C];
__device__ float g_u [C];
__device__ float g_w2[C];
__device__ float g_kq[C];
__device__ float g_beta;

// ---------------- packed f32x2 helpers (Blackwell) ---------------------------
__device__ __forceinline__ void fma2(unsigned long long &acc,
                                     unsigned long long a, unsigned long long b) {
    asm("fma.rn.f32x2 %0, %1, %2, %0;" : "+l"(acc) : "l"(a), "l"(b));
}
__device__ __forceinline__ unsigned long long dup2(float a) {
    unsigned long long r; unsigned ai = __float_as_uint(a);
    asm("mov.b64 %0, {%1, %1};" : "=l"(r) : "r"(ai));
    return r;
}
__device__ __forceinline__ float2 unp2(unsigned long long v) {
    float2 r;
    r.x = __uint_as_float((unsigned)(v & 0xffffffffull));
    r.y = __uint_as_float((unsigned)(v >> 32));
    return r;
}

// ---------------- k_prep: A, Bm, bias vectors (64 blocks x 256) --------------
__global__ void k_prep(const float* __restrict__ w_q, const float* __restrict__ b_q,
                       const float* __restrict__ w_k, const float* __restrict__ b_k,
                       const float* __restrict__ w_v, const float* __restrict__ b_v,
                       const float* __restrict__ w_o, const float* __restrict__ b_o) {
    const int bid = blockIdx.x;
    const int t = threadIdx.x;

    if (bid == 0) {
        if (t < C) {
            float au = 0.f, aw = 0.f, ak = 0.f;
            #pragma unroll 8
            for (int j = 0; j < C; j++) {
                au += w_o[t*C + j] * b_v[j];
                aw += w_q[j*C + t] * b_k[j];
                ak += w_k[j*C + t] * b_q[j];
            }
            g_u[t] = au; g_w2[t] = aw; g_kq[t] = ak;
        }
        if (t == 128) {
            float bt = 0.f;
            for (int j = 0; j < C; j++) bt += b_k[j] * b_q[j];
            g_beta = bt;
        }
    }

    __shared__ float lhs[4][C];
    const bool isA = (bid < 32);
    const int r0 = (isA ? bid : bid - 32) * 4;
    for (int e = t; e < 4*C; e += 256) {
        int i = e >> 7, j = e & 127;
        lhs[i][j] = isA ? w_o[(r0 + i)*C + j] : w_k[j*C + (r0 + i)];
    }
    __syncthreads();

    const float* rhs = isA ? w_v : w_q;
    float* dst = isA ? g_A : g_Bm;
    const int c = t & 127;
    #pragma unroll
    for (int p = 0; p < 2; p++) {
        const int i = (t >> 7) + 2*p;
        float acc = 0.f;
        #pragma unroll 8
        for (int j = 0; j < C; j++) acc += lhs[i][j] * __ldg(&rhs[j*C + c]);
        dst[(r0 + i)*C + c] = acc;
    }
}

// ---------------- k_gram: partial G = X X^T per 128-n tile (100 x 256) -------
__global__ void __launch_bounds__(256) k_gram(const float* __restrict__ x) {
    const int b = blockIdx.x / NT;
    const int tile = blockIdx.x % NT;
    const int nb = tile * 128;
    const float* xb = x + b*C*NPIX;

    __shared__ __align__(16) float xs[16][132];   // [n within 16][channel]

    const int t = threadIdx.x;
    const int tx = t & 15, ty = t >> 4;
    const int r0 = ty * 8;        // output rows r0..r0+7
    const int cA = 4*tx;          // output cols cA..cA+3
    const int cB = 64 + 4*tx;     // output cols cB..cB+3

    unsigned long long acc[8][4];
    #pragma unroll
    for (int i = 0; i < 8; i++)
        #pragma unroll
        for (int j = 0; j < 4; j++) acc[i][j] = 0ull;

    float spart[8];
    #pragma unroll
    for (int i = 0; i < 8; i++) spart[i] = 0.f;

    for (int kc = 0; kc < 8; kc++) {          // 8 sub-chunks of 16 n
        const int n0 = nb + kc*16;
        __syncthreads();
        #pragma unroll
        for (int it = 0; it < 8; it++) {      // load 128c x 16n, n-major rows
            const int c = ty + it*16;
            const float v = __ldg(&xb[c*NPIX + n0 + tx]);
            xs[tx][c] = v;
            spart[it] += v;
        }
        __syncthreads();
        #pragma unroll
        for (int nn = 0; nn < 16; nn++) {
            const float4 a0 = *(const float4*)&xs[nn][r0];
            const float4 a1 = *(const float4*)&xs[nn][r0 + 4];
            const unsigned long long* bpA = (const unsigned long long*)&xs[nn][cA];
            const unsigned long long* bpB = (const unsigned long long*)&xs[nn][cB];
            const unsigned long long b2[4] = { bpA[0], bpA[1], bpB[0], bpB[1] };
            const float a[8] = {a0.x, a0.y, a0.z, a0.w, a1.x, a1.y, a1.z, a1.w};
            #pragma unroll
            for (int i = 0; i < 8; i++) {
                const unsigned long long ad = dup2(a[i]);
                fma2(acc[i][0], ad, b2[0]);
                fma2(acc[i][1], ad, b2[1]);
                fma2(acc[i][2], ad, b2[2]);
                fma2(acc[i][3], ad, b2[3]);
            }
        }
    }

    // row-sum reduction across the 16-thread tx group
    #pragma unroll
    for (int it = 0; it < 8; it++) {
        float v = spart[it];
        v += __shfl_down_sync(0xffffffffu, v, 8, 16);
        v += __shfl_down_sync(0xffffffffu, v, 4, 16);
        v += __shfl_down_sync(0xffffffffu, v, 2, 16);
        v += __shfl_down_sync(0xffffffffu, v, 1, 16);
        if (tx == 0) g_sp[(b*NT + tile)*C + ty + it*16] = v;
    }

    float* Gp = g_Gp + (size_t)(b*NT + tile)*C*C;
    #pragma unroll
    for (int i = 0; i < 8; i++) {
        const float2 p0 = unp2(acc[i][0]), p1 = unp2(acc[i][1]);
        const float2 p2 = unp2(acc[i][2]), p3 = unp2(acc[i][3]);
        *(float4*)&Gp[(r0 + i)*C + cA] = make_float4(p0.x, p0.y, p1.x, p1.y);
        *(float4*)&Gp[(r0 + i)*C + cB] = make_float4(p2.x, p2.y, p3.x, p3.y);
    }
}

// ---------------- k_red: deterministic reduction of partials (128 x 256) -----
__global__ void k_red() {
    const int idx = blockIdx.x*256 + threadIdx.x;   // 0..32767
    const int b = idx >> 14;
    const int e = idx & 16383;
    const float* base = g_Gp + (size_t)b*NT*C*C + e;
    float a = 0.f;
    #pragma unroll 10
    for (int ch = 0; ch < NT; ch++) a += base[(size_t)ch*C*C];
    g_G[idx] = a;
    if (e < C) {
        const float* sb = g_sp + b*NT*C + e;
        float sv = 0.f;
        #pragma unroll 10
        for (int ch = 0; ch < NT; ch++) sv += sb[ch*C];
        g_s[b*C + e] = sv;
    }
}

// ---------------- k_p: P = A G per batch (16 x 256) --------------------------
__global__ void k_p() {
    const int b = blockIdx.x >> 3;
    const int r0 = (blockIdx.x & 7) * 16;
    const int t = threadIdx.x;
    __shared__ float As[16][C];
    for (int e = t; e < 16*C; e += 256)
        As[e >> 7 | 0][e & 127] = g_A[(r0 + (e >> 7))*C + (e & 127)];
    __syncthreads();

    const int c = t & 127, i0 = t >> 7;
    float acc[8];
    #pragma unroll
    for (int q = 0; q < 8; q++) acc[q] = 0.f;
    const float* Gb = g_G + b*C*C;
    #pragma unroll 4
    for (int j = 0; j < C; j++) {
        const float gv = Gb[j*C + c];
        #pragma unroll
        for (int q = 0; q < 8; q++) acc[q] += As[i0 + 2*q][j] * gv;
    }
    #pragma unroll
    for (int q = 0; q < 8; q++) g_P[b*C*C + (r0 + i0 + 2*q)*C + c] = acc[q];
}

// ---------------- k_e: E = (1/N) P Bm + rank-1 terms + I; e0 (16 x 256) ------
__global__ void k_e(const float* __restrict__ b_o) {
    const int b = blockIdx.x >> 3;
    const int r0 = (blockIdx.x & 7) * 16;
    const int t = threadIdx.x;
    const float invN = 1.0f / (float)NPIX;

    __shared__ float Ps[16][C];
    __shared__ float ssh[C];
    __shared__ float kqsh[C];
    __shared__ float t2sh[16];
    __shared__ float skq_sh;

    const float* Pb = g_P + b*C*C;
    for (int e = t; e < 16*C; e += 256)
        Ps[e >> 7 | 0][e & 127] = Pb[(r0 + (e >> 7))*C + (e & 127)];
    // second pass fills rows 2..15
    for (int e = t + 512; e < 16*C; e += 256)
        Ps[e >> 7][e & 127] = Pb[(r0 + (e >> 7))*C + (e & 127)];
    if (t < C) { ssh[t] = g_s[b*C + t]; kqsh[t] = g_kq[t]; }
    __syncthreads();

    if (t < 16) {
        float a = 0.f;
        const float* Ar = g_A + (r0 + t)*C;
        #pragma unroll 8
        for (int j = 0; j < C; j++) a += Ar[j] * ssh[j];
        t2sh[t] = a;                                   // (A s)[r]
    }
    if (t == 16) {
        float a = 0.f;
        for (int j = 0; j < C; j++) a += ssh[j] * kqsh[j];
        skq_sh = a;                                    // s . kq
    }
    __syncthreads();

    const int c = t & 127, i0 = t >> 7;
    float t1 = 0.f;                                    // (Bm^T s)[c]
    float acc[8];
    #pragma unroll
    for (int q = 0; q < 8; q++) acc[q] = 0.f;
    #pragma unroll 4
    for (int j = 0; j < C; j++) {
        const float bm = g_Bm[j*C + c];
        t1 += bm * ssh[j];
        #pragma unroll
        for (int q = 0; q < 8; q++) acc[q] += Ps[i0 + 2*q][j] * bm;
    }
    const float w2c = g_w2[c];
    #pragma unroll
    for (int q = 0; q < 8; q++) {
        const int i = i0 + 2*q;
        const int r = r0 + i;
        const float ur = g_u[r];
        float val = invN*acc[q] + invN*ur*t1 + (invN*t2sh[i] + ur)*w2c;
        if (r == c) val += 1.0f;                       // fold residual: E + I
        g_E[b*C*C + r*C + c] = val;
    }
    if (t < 16) {
        float pk = 0.f;
        #pragma unroll 8
        for (int j = 0; j < C; j++) pk += Ps[t][j] * kqsh[j];   // (A G kq)[r]
        const int r = r0 + t;
        const float ur = g_u[r];
        g_e0[b*C + r] = invN*pk + invN*ur*skq_sh + (invN*t2sh[t] + ur)*g_beta + b_o[r];
    }
}

// ---------------- k_out: out = (E+I) X + e0 (100 x 256) ----------------------
__global__ void __launch_bounds__(256) k_out(const float* __restrict__ x,
                                             float* __restrict__ out) {
    const int b = blockIdx.x / NT;
    const int tile = blockIdx.x % NT;
    const int nb = tile * 128;
    const float* xb = x + b*C*NPIX;
    float* ob = out + b*C*NPIX;
    const float* Eb = g_E + b*C*C;

    __shared__ __align__(16) float Et[16][132];    // [cc][o] = E[o][cb+cc]
    __shared__ __align__(16) float xsh[16][132];   // [cc][nn] = x[cb+cc][nb+nn]

    const int t = threadIdx.x;
    const int tx = t & 15, ty = t >> 4;
    const int o0 = ty * 8;        // output rows o0..o0+7
    const int cA = 4*tx;          // local n cols
    const int cB = 64 + 4*tx;

    unsigned long long acc[8][4];
    #pragma unroll
    for (int i = 0; i < 8; i++)
        #pragma unroll
        for (int j = 0; j < 4; j++) acc[i][j] = 0ull;

    for (int kc = 0; kc < 8; kc++) {          // input-channel chunks of 16
        const int cb = kc * 16;
        __syncthreads();
        #pragma unroll
        for (int it = 0; it < 8; it++) {
            const int o = ty + it*16;
            Et[tx][o] = __ldg(&Eb[o*C + cb + tx]);
        }
        {
            const int nn = t & 127, ccg = t >> 7;
            #pragma unroll
            for (int it = 0; it < 8; it++) {
                const int cc = ccg*8 + it;
                xsh[cc][nn] = __ldg(&xb[(cb + cc)*NPIX + nb + nn]);
            }
        }
        __syncthreads();
        #pragma unroll
        for (int cc = 0; cc < 16; cc++) {
            const float4 a0 = *(const float4*)&Et[cc][o0];
            const float4 a1 = *(const float4*)&Et[cc][o0 + 4];
            const unsigned long long* bpA = (const unsigned long long*)&xsh[cc][cA];
            const unsigned long long* bpB = (const unsigned long long*)&xsh[cc][cB];
            const unsigned long long b2[4] = { bpA[0], bpA[1], bpB[0], bpB[1] };
            const float a[8] = {a0.x, a0.y, a0.z, a0.w, a1.x, a1.y, a1.z, a1.w};
            #pragma unroll
            for (int i = 0; i < 8; i++) {
                const unsigned long long ad = dup2(a[i]);
                fma2(acc[i][0], ad, b2[0]);
                fma2(acc[i][1], ad, b2[1]);
                fma2(acc[i][2], ad, b2[2]);
                fma2(acc[i][3], ad, b2[3]);
            }
        }
    }

    #pragma unroll
    for (int i = 0; i < 8; i++) {
        const int r = o0 + i;
        const float e0 = g_e0[b*C + r];
        const float2 p0 = unp2(acc[i][0]), p1 = unp2(acc[i][1]);
        const float2 p2 = unp2(acc[i][2]), p3 = unp2(acc[i][3]);
        *(float4*)&ob[r*NPIX + nb + cA] =
            make_float4(p0.x + e0, p0.y + e0, p1.x + e0, p1.y + e0);
        *(float4*)&ob[r*NPIX + nb + cB] =
            make_float4(p2.x + e0, p2.y + e0, p3.x + e0, p3.y + e0);
    }
}

// ---------------- host launcher ----------------------------------------------
extern "C" void kernel_launch(void* const* d_in, const int* in_sizes, int n_in,
                              void* d_out, int out_size) {
    (void)in_sizes; (void)n_in; (void)out_size;
    const float* x   = (const float*)d_in[0];
    const float* w_q = (const float*)d_in[1];
    const float* b_q = (const float*)d_in[2];
    const float* w_k = (const float*)d_in[3];
    const float* b_k = (const float*)d_in[4];
    const float* w_v = (const float*)d_in[5];
    const float* b_v = (const float*)d_in[6];
    const float* w_o = (const float*)d_in[7];
    const float* b_o = (const float*)d_in[8];
    float* out = (float*)d_out;

    k_prep<<<64, 256>>>(w_q, b_q, w_k, b_k, w_v, b_v, w_o, b_o);
    k_gram<<<BATCH*NT, 256>>>(x);
    k_red<<<128, 256>>>();
    k_p<<<BATCH*8, 256>>>();
    k_e<<<BATCH*8, 256>>>(b_o);
    k_out<<<BATCH*NT, 256>>>(x, out);
}

// round 5
// speedup vs baseline: 1.3665x; 1.3665x over previous
#include <cuda_runtime.h>

// NonLocalModule (no softmax) collapsed via associativity:
//   out = (E + I) X + e0, with G = X X^T (128x128 per batch),
//   A = Wo Wv, Bm = Wk^T Wq,
//   E  = (1/N)[A G Bm + (A s) w2^T + u (Bm^T s)^T] + u w2^T  (+ I folded in)
//   e0 = (1/N)[(A G) kq + (A s) beta + u (s.kq)] + u beta + bo
//   u = Wo bv, w2 = Wq^T bk, kq = Wk^T bq, beta = bk.bq, s = X 1.

#define C     128
#define NPIX  6400
#define BATCH 2
#define NT    50   /* n tiles of 128 */

// ---------------- device scratch (no allocations allowed) --------------------
__device__ float g_Gp[BATCH*NT*C*C];
__device__ float g_sp[BATCH*NT*C];
__device__ float g_G [BATCH*C*C];
__device__ float g_s [BATCH*C];
__device__ float g_A [C*C];
__device__ float g_Bm[C*C];
__device__ float g_P [BATCH*C*C];
__device__ float g_E [BATCH*C*C];
__device__ float g_e0[BATCH*C];
__device__ float g_u [C];
__device__ float g_w2[C];
__device__ float g_kq[C];
__device__ float g_t2[BATCH*C];
__device__ float g_skq[BATCH];
__device__ float g_beta;

// ---------------- packed f32x2 helpers (Blackwell) ---------------------------
__device__ __forceinline__ void fma2(unsigned long long &acc,
                                     unsigned long long a, unsigned long long b) {
    asm("fma.rn.f32x2 %0, %1, %2, %0;" : "+l"(acc) : "l"(a), "l"(b));
}
__device__ __forceinline__ unsigned long long dup2(float a) {
    unsigned long long r; unsigned ai = __float_as_uint(a);
    asm("mov.b64 %0, {%1, %1};" : "=l"(r) : "r"(ai));
    return r;
}
__device__ __forceinline__ float2 unp2(unsigned long long v) {
    float2 r;
    r.x = __uint_as_float((unsigned)(v & 0xffffffffull));
    r.y = __uint_as_float((unsigned)(v >> 32));
    return r;
}
__device__ __forceinline__ float red16(float p) {   // reduce within 16-lane group
    p += __shfl_down_sync(0xffffffffu, p, 8, 16);
    p += __shfl_down_sync(0xffffffffu, p, 4, 16);
    p += __shfl_down_sync(0xffffffffu, p, 2, 16);
    p += __shfl_down_sync(0xffffffffu, p, 1, 16);
    return p;
}

// ---------------- k_prep: A = Wo Wv, Bm = Wk^T Wq, bias vecs (32 x 256) ------
__global__ void __launch_bounds__(256) k_prep(
        const float* __restrict__ w_q, const float* __restrict__ b_q,
        const float* __restrict__ w_k, const float* __restrict__ b_k,
        const float* __restrict__ w_v, const float* __restrict__ b_v,
        const float* __restrict__ w_o, const float* __restrict__ b_o) {
    (void)b_o;
    const int bid = blockIdx.x, t = threadIdx.x;
    const bool isA = bid < 16;
    const int r0 = (bid & 15) * 8;

    __shared__ float lhsS[8][C];
    __shared__ float rhsS[16][C];

    for (int e = t; e < 8*C; e += 256) {
        const int i = e >> 7, j = e & 127;
        lhsS[i][j] = isA ? __ldg(&w_o[(r0 + i)*C + j])
                         : __ldg(&w_k[j*C + (r0 + i)]);
    }
    __syncthreads();

    // u[r] = sum_j Wo[r][j] bv[j]   (A blocks)
    // kq[r] = sum_j Wk[j][r] bq[j]  (Bm blocks)  -- both from lhsS
    if (t < 128) {
        const int row = t >> 4, l = t & 15;
        const float* bv = isA ? b_v : b_q;
        float p = 0.f;
        #pragma unroll
        for (int j = 0; j < 8; j++) p += lhsS[row][l*8 + j] * __ldg(&bv[l*8 + j]);
        p = red16(p);
        if (l == 0) (isA ? g_u : g_kq)[r0 + row] = p;
    }
    // beta = bk.bq (block 16, warp 0)
    if (bid == 16 && t < 32) {
        float p = 0.f;
        #pragma unroll
        for (int j = 0; j < 4; j++) p += __ldg(&b_k[t*4 + j]) * __ldg(&b_q[t*4 + j]);
        #pragma unroll
        for (int off = 16; off > 0; off >>= 1)
            p += __shfl_down_sync(0xffffffffu, p, off);
        if (t == 0) g_beta = p;
    }

    const float* rhs = isA ? w_v : w_q;
    float* dst = isA ? g_A : g_Bm;
    const int c = t & 127, i0 = t >> 7;
    float acc[4] = {0.f, 0.f, 0.f, 0.f};
    float w2acc = 0.f;

    for (int kc = 0; kc < 8; kc++) {
        __syncthreads();
        #pragma unroll
        for (int it = 0; it < 8; it++) {
            const int jj = i0*8 + it;
            rhsS[jj][c] = __ldg(&rhs[(kc*16 + jj)*C + c]);
        }
        __syncthreads();
        #pragma unroll
        for (int jj = 0; jj < 16; jj++) {
            const float rv = rhsS[jj][c];
            w2acc += rv * __ldg(&b_k[kc*16 + jj]);       // only used by Bm path
            #pragma unroll
            for (int q = 0; q < 4; q++)
                acc[q] += lhsS[i0 + 2*q][kc*16 + jj] * rv;
        }
    }
    #pragma unroll
    for (int q = 0; q < 4; q++) dst[(r0 + i0 + 2*q)*C + c] = acc[q];
    if (bid == 16 && i0 == 0) g_w2[c] = w2acc;   // w2[c] = sum_j Wq[j][c] bk[j]
}

// ---------------- k_gram: partial G = X X^T per 128-n tile (100 x 256) -------
__global__ void __launch_bounds__(256) k_gram(const float* __restrict__ x) {
    const int b = blockIdx.x / NT;
    const int tile = blockIdx.x % NT;
    const int nb = tile * 128;
    const float* xb = x + b*C*NPIX;

    __shared__ __align__(16) float xs[16][132];

    const int t = threadIdx.x;
    const int tx = t & 15, ty = t >> 4;
    const int r0 = ty * 8;
    const int cA = 4*tx;
    const int cB = 64 + 4*tx;

    unsigned long long acc[8][4];
    #pragma unroll
    for (int i = 0; i < 8; i++)
        #pragma unroll
        for (int j = 0; j < 4; j++) acc[i][j] = 0ull;

    float spart[8];
    #pragma unroll
    for (int i = 0; i < 8; i++) spart[i] = 0.f;

    for (int kc = 0; kc < 8; kc++) {
        const int n0 = nb + kc*16;
        __syncthreads();
        #pragma unroll
        for (int it = 0; it < 8; it++) {
            const int c = ty + it*16;
            const float v = __ldg(&xb[c*NPIX + n0 + tx]);
            xs[tx][c] = v;
            spart[it] += v;
        }
        __syncthreads();
        #pragma unroll
        for (int nn = 0; nn < 16; nn++) {
            const float4 a0 = *(const float4*)&xs[nn][r0];
            const float4 a1 = *(const float4*)&xs[nn][r0 + 4];
            const unsigned long long* bpA = (const unsigned long long*)&xs[nn][cA];
            const unsigned long long* bpB = (const unsigned long long*)&xs[nn][cB];
            const unsigned long long b2[4] = { bpA[0], bpA[1], bpB[0], bpB[1] };
            const float a[8] = {a0.x, a0.y, a0.z, a0.w, a1.x, a1.y, a1.z, a1.w};
            #pragma unroll
            for (int i = 0; i < 8; i++) {
                const unsigned long long ad = dup2(a[i]);
                fma2(acc[i][0], ad, b2[0]);
                fma2(acc[i][1], ad, b2[1]);
                fma2(acc[i][2], ad, b2[2]);
                fma2(acc[i][3], ad, b2[3]);
            }
        }
    }

    #pragma unroll
    for (int it = 0; it < 8; it++) {
        float v = red16(spart[it]);
        if (tx == 0) g_sp[(b*NT + tile)*C + ty + it*16] = v;
    }

    float* Gp = g_Gp + (size_t)(b*NT + tile)*C*C;
    #pragma unroll
    for (int i = 0; i < 8; i++) {
        const float2 p0 = unp2(acc[i][0]), p1 = unp2(acc[i][1]);
        const float2 p2 = unp2(acc[i][2]), p3 = unp2(acc[i][3]);
        *(float4*)&Gp[(r0 + i)*C + cA] = make_float4(p0.x, p0.y, p1.x, p1.y);
        *(float4*)&Gp[(r0 + i)*C + cB] = make_float4(p2.x, p2.y, p3.x, p3.y);
    }
}

// ---------------- k_red: reduce partials; also skq = s.kq (128 x 256) --------
__global__ void k_red() {
    const int t = threadIdx.x;
    const int idx = blockIdx.x*256 + t;
    const int b = idx >> 14;
    const int e = idx & 16383;
    const float* base = g_Gp + (size_t)b*NT*C*C + e;
    float a = 0.f;
    #pragma unroll 10
    for (int ch = 0; ch < NT; ch++) a += base[(size_t)ch*C*C];
    g_G[idx] = a;

    float sv = 0.f;
    if (e < C) {
        const float* sb = g_sp + b*NT*C + e;
        #pragma unroll 10
        for (int ch = 0; ch < NT; ch++) sv += sb[ch*C];
        g_s[b*C + e] = sv;
    }
    if (blockIdx.x == 0 || blockIdx.x == 64) {   // these blocks hold s[0..127]
        __shared__ float red[128];
        if (t < 128) red[t] = sv * g_kq[t];
        __syncthreads();
        if (t < 64) red[t] += red[t + 64];
        __syncthreads();
        if (t < 32) {
            float v = red[t] + red[t + 32];
            #pragma unroll
            for (int off = 16; off > 0; off >>= 1)
                v += __shfl_down_sync(0xffffffffu, v, off);
            if (t == 0) g_skq[blockIdx.x == 0 ? 0 : 1] = v;
        }
    }
}

// ---------------- k_p: P = A G; t2 = A s (32 x 256) --------------------------
__global__ void __launch_bounds__(256) k_p() {
    const int b = blockIdx.x >> 4;
    const int r0 = (blockIdx.x & 15) * 8;
    const int t = threadIdx.x;

    __shared__ float As[8][C];
    __shared__ float Gs[16][C];
    __shared__ float sS[C];

    if (t < C) sS[t] = g_s[b*C + t];
    for (int e = t; e < 8*C; e += 256)
        As[e >> 7][e & 127] = g_A[(r0 + (e >> 7))*C + (e & 127)];
    __syncthreads();

    if (t < 128) {                         // t2[r] = sum_j A[r][j] s[j]
        const int row = t >> 4, l = t & 15;
        float p = 0.f;
        #pragma unroll
        for (int j = 0; j < 8; j++) p += As[row][l*8 + j] * sS[l*8 + j];
        p = red16(p);
        if (l == 0) g_t2[b*C + r0 + row] = p;
    }

    const int c = t & 127, i0 = t >> 7;
    float acc[4] = {0.f, 0.f, 0.f, 0.f};
    const float* Gb = g_G + b*C*C;
    for (int kc = 0; kc < 8; kc++) {
        __syncthreads();
        #pragma unroll
        for (int it = 0; it < 8; it++) {
            const int jj = i0*8 + it;
            Gs[jj][c] = Gb[(kc*16 + jj)*C + c];
        }
        __syncthreads();
        #pragma unroll
        for (int jj = 0; jj < 16; jj++) {
            const float gv = Gs[jj][c];
            #pragma unroll
            for (int q = 0; q < 4; q++)
                acc[q] += As[i0 + 2*q][kc*16 + jj] * gv;
        }
    }
    #pragma unroll
    for (int q = 0; q < 4; q++)
        g_P[b*C*C + (r0 + i0 + 2*q)*C + c] = acc[q];
}

// ---------------- k_e: E = invN*P*Bm + rank-1 + I; e0 (32 x 256) -------------
__global__ void __launch_bounds__(256) k_e(const float* __restrict__ b_o) {
    const int b = blockIdx.x >> 4;
    const int r0 = (blockIdx.x & 15) * 8;
    const int t = threadIdx.x;
    const float invN = 1.0f / (float)NPIX;

    __shared__ float Ps[8][C];
    __shared__ float Bs[16][C];
    __shared__ float sS[C];

    if (t < C) sS[t] = g_s[b*C + t];
    const float* Pb = g_P + b*C*C;
    for (int e = t; e < 8*C; e += 256)
        Ps[e >> 7][e & 127] = Pb[(r0 + (e >> 7))*C + (e & 127)];
    __syncthreads();

    const int c = t & 127, i0 = t >> 7;
    float acc[4] = {0.f, 0.f, 0.f, 0.f};
    float t1 = 0.f;                               // (Bm^T s)[c]
    for (int kc = 0; kc < 8; kc++) {
        __syncthreads();
        #pragma unroll
        for (int it = 0; it < 8; it++) {
            const int jj = i0*8 + it;
            Bs[jj][c] = g_Bm[(kc*16 + jj)*C + c];
        }
        __syncthreads();
        #pragma unroll
        for (int jj = 0; jj < 16; jj++) {
            const float bm = Bs[jj][c];
            t1 += bm * sS[kc*16 + jj];
            #pragma unroll
            for (int q = 0; q < 4; q++)
                acc[q] += Ps[i0 + 2*q][kc*16 + jj] * bm;
        }
    }
    const float w2c = g_w2[c];
    #pragma unroll
    for (int q = 0; q < 4; q++) {
        const int i = i0 + 2*q;
        const int r = r0 + i;
        const float ur = g_u[r];
        float val = invN*acc[q] + invN*ur*t1 + (invN*g_t2[b*C + r] + ur)*w2c;
        if (r == c) val += 1.0f;                  // fold residual: E + I
        g_E[b*C*C + r*C + c] = val;
    }
    if (t < 8) {                                  // e0 rows of this block
        float pk = 0.f;
        #pragma unroll 8
        for (int j = 0; j < C; j++) pk += Ps[t][j] * g_kq[j];
        const int r = r0 + t;
        const float ur = g_u[r];
        g_e0[b*C + r] = invN*pk + invN*ur*g_skq[b]
                      + (invN*g_t2[b*C + r] + ur)*g_beta + b_o[r];
    }
}

// ---------------- k_out: out = (E+I) X + e0 (100 x 256) ----------------------
__global__ void __launch_bounds__(256) k_out(const float* __restrict__ x,
                                             float* __restrict__ out) {
    const int b = blockIdx.x / NT;
    const int tile = blockIdx.x % NT;
    const int nb = tile * 128;
    const float* xb = x + b*C*NPIX;
    float* ob = out + b*C*NPIX;
    const float* Eb = g_E + b*C*C;

    __shared__ __align__(16) float Et[16][132];    // [cc][o] = E[o][cb+cc]
    __shared__ __align__(16) float xsh[16][132];   // [cc][nn] = x[cb+cc][nb+nn]

    const int t = threadIdx.x;
    const int tx = t & 15, ty = t >> 4;
    const int o0 = ty * 8;
    const int cA = 4*tx;
    const int cB = 64 + 4*tx;

    unsigned long long acc[8][4];
    #pragma unroll
    for (int i = 0; i < 8; i++)
        #pragma unroll
        for (int j = 0; j < 4; j++) acc[i][j] = 0ull;

    for (int kc = 0; kc < 8; kc++) {
        const int cb = kc * 16;
        __syncthreads();
        #pragma unroll
        for (int it = 0; it < 8; it++) {
            const int o = ty + it*16;
            Et[tx][o] = __ldg(&Eb[o*C + cb + tx]);
        }
        {
            const int nn = t & 127, ccg = t >> 7;
            #pragma unroll
            for (int it = 0; it < 8; it++) {
                const int cc = ccg*8 + it;
                xsh[cc][nn] = __ldg(&xb[(cb + cc)*NPIX + nb + nn]);
            }
        }
        __syncthreads();
        #pragma unroll
        for (int cc = 0; cc < 16; cc++) {
            const float4 a0 = *(const float4*)&Et[cc][o0];
            const float4 a1 = *(const float4*)&Et[cc][o0 + 4];
            const unsigned long long* bpA = (const unsigned long long*)&xsh[cc][cA];
            const unsigned long long* bpB = (const unsigned long long*)&xsh[cc][cB];
            const unsigned long long b2[4] = { bpA[0], bpA[1], bpB[0], bpB[1] };
            const float a[8] = {a0.x, a0.y, a0.z, a0.w, a1.x, a1.y, a1.z, a1.w};
            #pragma unroll
            for (int i = 0; i < 8; i++) {
                const unsigned long long ad = dup2(a[i]);
                fma2(acc[i][0], ad, b2[0]);
                fma2(acc[i][1], ad, b2[1]);
                fma2(acc[i][2], ad, b2[2]);
                fma2(acc[i][3], ad, b2[3]);
            }
        }
    }

    #pragma unroll
    for (int i = 0; i < 8; i++) {
        const int r = o0 + i;
        const float e0 = g_e0[b*C + r];
        const float2 p0 = unp2(acc[i][0]), p1 = unp2(acc[i][1]);
        const float2 p2 = unp2(acc[i][2]), p3 = unp2(acc[i][3]);
        *(float4*)&ob[r*NPIX + nb + cA] =
            make_float4(p0.x + e0, p0.y + e0, p1.x + e0, p1.y + e0);
        *(float4*)&ob[r*NPIX + nb + cB] =
            make_float4(p2.x + e0, p2.y + e0, p3.x + e0, p3.y + e0);
    }
}

// ---------------- host launcher ----------------------------------------------
extern "C" void kernel_launch(void* const* d_in, const int* in_sizes, int n_in,
                              void* d_out, int out_size) {
    (void)in_sizes; (void)n_in; (void)out_size;
    const float* x   = (const float*)d_in[0];
    const float* w_q = (const float*)d_in[1];
    const float* b_q = (const float*)d_in[2];
    const float* w_k = (const float*)d_in[3];
    const float* b_k = (const float*)d_in[4];
    const float* w_v = (const float*)d_in[5];
    const float* b_v = (const float*)d_in[6];
    const float* w_o = (const float*)d_in[7];
    const float* b_o = (const float*)d_in[8];
    float* out = (float*)d_out;

    k_prep<<<32, 256>>>(w_q, b_q, w_k, b_k, w_v, b_v, w_o, b_o);
    k_gram<<<BATCH*NT, 256>>>(x);
    k_red<<<128, 256>>>();
    k_p<<<BATCH*16, 256>>>();
    k_e<<<BATCH*16, 256>>>(b_o);
    k_out<<<BATCH*NT, 256>>>(x, out);
}

// round 6
// speedup vs baseline: 1.5039x; 1.1006x over previous
#include <cuda_runtime.h>

// NonLocalModule (no softmax) collapsed via associativity:
//   out = (E + I) X + e0, with G = X X^T (128x128 per batch),
//   A = Wo Wv, Bm = Wk^T Wq,
//   E  = (1/N)[A G Bm + (A s) w2^T + u (Bm^T s)^T] + u w2^T  (+ I folded in)
//   e0 = (1/N)[(A G) kq + (A s) beta + u (s.kq)] + u beta + bo
//   u = Wo bv, w2 = Wq^T bk, kq = Wk^T bq, beta = bk.bq, s = X 1.

#define C     128
#define NPIX  6400
#define BATCH 2
#define NT    50   /* n tiles of 128 */

// ---------------- device scratch (no allocations allowed) --------------------
__device__ float g_Gp[BATCH*NT*C*C];
__device__ float g_sp[BATCH*NT*C];
__device__ float g_G [BATCH*C*C];
__device__ float g_s [BATCH*C];
__device__ float g_A [C*C];
__device__ float g_Bm[C*C];
__device__ float g_E [BATCH*C*C];
__device__ float g_e0[BATCH*C];
__device__ float g_u [C];
__device__ float g_w2[C];
__device__ float g_kq[C];
__device__ float g_skq[BATCH];
__device__ float g_beta;
__device__ int   g_cnt[BATCH];   // zero-init; re-zeroed by k_gram each replay

// ---------------- packed f32x2 helpers (Blackwell) ---------------------------
__device__ __forceinline__ void fma2(unsigned long long &acc,
                                     unsigned long long a, unsigned long long b) {
    asm("fma.rn.f32x2 %0, %1, %2, %0;" : "+l"(acc) : "l"(a), "l"(b));
}
__device__ __forceinline__ unsigned long long dup2(float a) {
    unsigned long long r; unsigned ai = __float_as_uint(a);
    asm("mov.b64 %0, {%1, %1};" : "=l"(r) : "r"(ai));
    return r;
}
__device__ __forceinline__ float2 unp2(unsigned long long v) {
    float2 r;
    r.x = __uint_as_float((unsigned)(v & 0xffffffffull));
    r.y = __uint_as_float((unsigned)(v >> 32));
    return r;
}
__device__ __forceinline__ float red16(float p) {
    p += __shfl_down_sync(0xffffffffu, p, 8, 16);
    p += __shfl_down_sync(0xffffffffu, p, 4, 16);
    p += __shfl_down_sync(0xffffffffu, p, 2, 16);
    p += __shfl_down_sync(0xffffffffu, p, 1, 16);
    return p;
}

// ---------------- k_prep: A = Wo Wv, Bm = Wk^T Wq, bias vecs (32 x 256) ------
__global__ void __launch_bounds__(256) k_prep(
        const float* __restrict__ w_q, const float* __restrict__ b_q,
        const float* __restrict__ w_k, const float* __restrict__ b_k,
        const float* __restrict__ w_v, const float* __restrict__ b_v,
        const float* __restrict__ w_o, const float* __restrict__ b_o) {
    (void)b_o;
    const int bid = blockIdx.x, t = threadIdx.x;
    const bool isA = bid < 16;
    const int r0 = (bid & 15) * 8;

    __shared__ float lhsS[8][C];
    __shared__ __align__(16) float rhsS[64][132];
    __shared__ float bkS[C];

    if (t < C) bkS[t] = __ldg(&b_k[t]);
    for (int e = t; e < 8*C; e += 256) {
        const int i = e >> 7, j = e & 127;
        lhsS[i][j] = isA ? __ldg(&w_o[(r0 + i)*C + j])
                         : __ldg(&w_k[j*C + (r0 + i)]);
    }
    __syncthreads();

    // u[r] (A blocks) / kq[r] (Bm blocks) from lhsS
    if (t < 128) {
        const int row = t >> 4, l = t & 15;
        const float* bv = isA ? b_v : b_q;
        float p = 0.f;
        #pragma unroll
        for (int j = 0; j < 8; j++) p += lhsS[row][l*8 + j] * __ldg(&bv[l*8 + j]);
        p = red16(p);
        if (l == 0) (isA ? g_u : g_kq)[r0 + row] = p;
    }
    if (bid == 16 && t >= 128 && t < 160) {     // beta = bk.bq
        const int l = t - 128;
        float p = 0.f;
        #pragma unroll
        for (int j = 0; j < 4; j++) p += bkS[l*4 + j] * __ldg(&b_q[l*4 + j]);
        #pragma unroll
        for (int off = 16; off > 0; off >>= 1)
            p += __shfl_down_sync(0xffffffffu, p, off);
        if (l == 0) g_beta = p;
    }

    const float* rhs = isA ? w_v : w_q;
    float* dst = isA ? g_A : g_Bm;
    const int c = t & 127, i0 = t >> 7;
    const int lrow = t >> 5, lcol = (t & 31) * 4;
    float acc[4] = {0.f, 0.f, 0.f, 0.f};
    float w2acc = 0.f;

    #pragma unroll
    for (int st = 0; st < 2; st++) {            // 64-row stages, MLP 8
        __syncthreads();
        #pragma unroll
        for (int it = 0; it < 8; it++) {
            const int row = lrow + it*8;
            const float4 v = *(const float4*)&rhs[(st*64 + row)*C + lcol];
            *(float4*)&rhsS[row][lcol] = v;
        }
        __syncthreads();
        #pragma unroll 16
        for (int jj = 0; jj < 64; jj++) {
            const float rv = rhsS[jj][c];
            w2acc += rv * bkS[st*64 + jj];
            #pragma unroll
            for (int q = 0; q < 4; q++)
                acc[q] += lhsS[i0 + 2*q][st*64 + jj] * rv;
        }
    }
    #pragma unroll
    for (int q = 0; q < 4; q++) dst[(r0 + i0 + 2*q)*C + c] = acc[q];
    if (bid == 16 && i0 == 0) g_w2[c] = w2acc;   // w2[c] = sum_j Wq[j][c] bk[j]
}

// ---------------- k_gram: partial G = X X^T per 128-n tile (100 x 256) -------
__global__ void __launch_bounds__(256) k_gram(const float* __restrict__ x) {
    if (blockIdx.x == 0 && threadIdx.x == 0) { g_cnt[0] = 0; g_cnt[1] = 0; }

    const int b = blockIdx.x / NT;
    const int tile = blockIdx.x % NT;
    const int nb = tile * 128;
    const float* xb = x + b*C*NPIX;

    __shared__ __align__(16) float xs[16][132];

    const int t = threadIdx.x;
    const int tx = t & 15, ty = t >> 4;
    const int r0 = ty * 8;
    const int cA = 4*tx;
    const int cB = 64 + 4*tx;

    unsigned long long acc[8][4];
    #pragma unroll
    for (int i = 0; i < 8; i++)
        #pragma unroll
        for (int j = 0; j < 4; j++) acc[i][j] = 0ull;

    float spart[8];
    #pragma unroll
    for (int i = 0; i < 8; i++) spart[i] = 0.f;

    for (int kc = 0; kc < 8; kc++) {
        const int n0 = nb + kc*16;
        __syncthreads();
        #pragma unroll
        for (int it = 0; it < 8; it++) {
            const int c = ty + it*16;
            const float v = __ldg(&xb[c*NPIX + n0 + tx]);
            xs[tx][c] = v;
            spart[it] += v;
        }
        __syncthreads();
        #pragma unroll
        for (int nn = 0; nn < 16; nn++) {
            const float4 a0 = *(const float4*)&xs[nn][r0];
            const float4 a1 = *(const float4*)&xs[nn][r0 + 4];
            const unsigned long long* bpA = (const unsigned long long*)&xs[nn][cA];
            const unsigned long long* bpB = (const unsigned long long*)&xs[nn][cB];
            const unsigned long long b2[4] = { bpA[0], bpA[1], bpB[0], bpB[1] };
            const float a[8] = {a0.x, a0.y, a0.z, a0.w, a1.x, a1.y, a1.z, a1.w};
            #pragma unroll
            for (int i = 0; i < 8; i++) {
                const unsigned long long ad = dup2(a[i]);
                fma2(acc[i][0], ad, b2[0]);
                fma2(acc[i][1], ad, b2[1]);
                fma2(acc[i][2], ad, b2[2]);
                fma2(acc[i][3], ad, b2[3]);
            }
        }
    }

    #pragma unroll
    for (int it = 0; it < 8; it++) {
        float v = red16(spart[it]);
        if (tx == 0) g_sp[(b*NT + tile)*C + ty + it*16] = v;
    }

    float* Gp = g_Gp + (size_t)(b*NT + tile)*C*C;
    #pragma unroll
    for (int i = 0; i < 8; i++) {
        const float2 p0 = unp2(acc[i][0]), p1 = unp2(acc[i][1]);
        const float2 p2 = unp2(acc[i][2]), p3 = unp2(acc[i][3]);
        *(float4*)&Gp[(r0 + i)*C + cA] = make_float4(p0.x, p0.y, p1.x, p1.y);
        *(float4*)&Gp[(r0 + i)*C + cB] = make_float4(p2.x, p2.y, p3.x, p3.y);
    }
}

// ---------------- k_pe: fused G-reduce + P=A G + E + e0 (32 x 256) -----------
// Phase 1: each block reduces its 8 rows of G (fixed order -> deterministic);
//          block rg==0 also reduces s and computes skq.
// Intra-kernel barrier per batch (16 blocks, all co-resident at grid=32).
// Phase 2: Pr = A_rows G (via 64-row smem stages), then E rows = Pr Bm.
__global__ void __launch_bounds__(256) k_pe(const float* __restrict__ b_o) {
    const int b  = blockIdx.x >> 4;
    const int rg = blockIdx.x & 15;
    const int r0 = rg * 8;
    const int t  = threadIdx.x;
    const float invN = 1.0f / (float)NPIX;

    __shared__ float As[8][C];
    __shared__ __align__(16) float stg[64][132];   // G then Bm stages
    __shared__ __align__(16) float Ps[8][132];
    __shared__ float sS[C];
    __shared__ float kqS[C];
    __shared__ float t2S[8];
    __shared__ float redS[C];

    // ---- phase 1: reduce assigned G rows ------------------------------------
    {
        const float* base = g_Gp + (size_t)b*NT*C*C + r0*C;
        #pragma unroll
        for (int k = 0; k < 4; k++) {
            const int e = t + 256*k;               // 0..1023 within 8 rows
            float a = 0.f;
            #pragma unroll 10
            for (int ch = 0; ch < NT; ch++) a += base[(size_t)ch*C*C + e];
            g_G[b*C*C + r0*C + e] = a;
        }
        float sv = 0.f;
        if (rg == 0) {
            if (t < C) {
                const float* sb = g_sp + b*NT*C + t;
                #pragma unroll 10
                for (int ch = 0; ch < NT; ch++) sv += sb[ch*C];
                g_s[b*C + t] = sv;
                redS[t] = sv * __ldg(&g_kq[t]);
            }
            __syncthreads();
            if (t < 64) redS[t] += redS[t + 64];
            __syncthreads();
            if (t < 32) {
                float v = redS[t] + redS[t + 32];
                #pragma unroll
                for (int off = 16; off > 0; off >>= 1)
                    v += __shfl_down_sync(0xffffffffu, v, off);
                if (t == 0) g_skq[b] = v;
            }
        }
    }
    // barrier across the 16 blocks of this batch
    __syncthreads();
    if (t == 0) {
        __threadfence();
        atomicAdd(&g_cnt[b], 1);
        while (atomicAdd(&g_cnt[b], 0) < 16) {}
    }
    __syncthreads();
    __threadfence();

    // ---- phase 2 -------------------------------------------------------------
    if (t < C) { sS[t] = __ldcg(&g_s[b*C + t]); kqS[t] = __ldg(&g_kq[t]); }
    for (int e = t; e < 8*C; e += 256)
        As[e >> 7][e & 127] = __ldg(&g_A[(r0 + (e >> 7))*C + (e & 127)]);
    __syncthreads();

    if (t < 128) {                         // t2[r] = A_rows . s
        const int row = t >> 4, l = t & 15;
        float p = 0.f;
        #pragma unroll
        for (int j = 0; j < 8; j++) p += As[row][l*8 + j] * sS[l*8 + j];
        p = red16(p);
        if (l == 0) t2S[row] = p;
    }

    const int c = t & 127, i0 = t >> 7;
    const int lrow = t >> 5, lcol = (t & 31) * 4;

    // P = A_rows @ G
    {
        float acc[4] = {0.f, 0.f, 0.f, 0.f};
        const float* Gb = g_G + b*C*C;
        #pragma unroll
        for (int st = 0; st < 2; st++) {
            __syncthreads();
            #pragma unroll
            for (int it = 0; it < 8; it++) {
                const int row = lrow + it*8;
                const float4 v = __ldcg((const float4*)&Gb[(st*64 + row)*C + lcol]);
                *(float4*)&stg[row][lcol] = v;
            }
            __syncthreads();
            #pragma unroll 16
            for (int jj = 0; jj < 64; jj++) {
                const float gv = stg[jj][c];
                #pragma unroll
                for (int q = 0; q < 4; q++)
                    acc[q] += As[i0 + 2*q][st*64 + jj] * gv;
            }
        }
        #pragma unroll
        for (int q = 0; q < 4; q++) Ps[i0 + 2*q][c] = acc[q];
    }

    // E rows = invN * Pr @ Bm + rank-1 terms (+ I)
    {
        float acc[4] = {0.f, 0.f, 0.f, 0.f};
        float t1 = 0.f;                    // (Bm^T s)[c]
        #pragma unroll
        for (int st = 0; st < 2; st++) {
            __syncthreads();               // also orders Ps writes vs reads
            #pragma unroll
            for (int it = 0; it < 8; it++) {
                const int row = lrow + it*8;
                const float4 v = __ldg((const float4*)&g_Bm[(st*64 + row)*C + lcol]);
                *(float4*)&stg[row][lcol] = v;
            }
            __syncthreads();
            #pragma unroll 16
            for (int jj = 0; jj < 64; jj++) {
                const float bm = stg[jj][c];
                t1 += bm * sS[st*64 + jj];
                #pragma unroll
                for (int q = 0; q < 4; q++)
                    acc[q] += Ps[i0 + 2*q][st*64 + jj] * bm;
            }
        }
        const float w2c = __ldg(&g_w2[c]);
        #pragma unroll
        for (int q = 0; q < 4; q++) {
            const int i = i0 + 2*q;
            const int r = r0 + i;
            const float ur = __ldg(&g_u[r]);
            float val = invN*acc[q] + invN*ur*t1 + (invN*t2S[i] + ur)*w2c;
            if (r == c) val += 1.0f;       // fold residual: E + I
            g_E[b*C*C + r*C + c] = val;
        }
    }
    if (t < 8) {                           // e0 for this block's rows
        float pk = 0.f;
        #pragma unroll 16
        for (int j = 0; j < C; j++) pk += Ps[t][j] * kqS[j];
        const int r = r0 + t;
        const float ur = __ldg(&g_u[r]);
        g_e0[b*C + r] = invN*pk + invN*ur*g_skq[b]
                      + (invN*t2S[t] + ur)*g_beta + __ldg(&b_o[r]);
    }
}

// ---------------- k_out: out = (E+I) X + e0 (100 x 256) ----------------------
__global__ void __launch_bounds__(256) k_out(const float* __restrict__ x,
                                             float* __restrict__ out) {
    const int b = blockIdx.x / NT;
    const int tile = blockIdx.x % NT;
    const int nb = tile * 128;
    const float* xb = x + b*C*NPIX;
    float* ob = out + b*C*NPIX;
    const float* Eb = g_E + b*C*C;

    __shared__ __align__(16) float Et[16][132];
    __shared__ __align__(16) float xsh[16][132];

    const int t = threadIdx.x;
    const int tx = t & 15, ty = t >> 4;
    const int o0 = ty * 8;
    const int cA = 4*tx;
    const int cB = 64 + 4*tx;

    unsigned long long acc[8][4];
    #pragma unroll
    for (int i = 0; i < 8; i++)
        #pragma unroll
        for (int j = 0; j < 4; j++) acc[i][j] = 0ull;

    for (int kc = 0; kc < 8; kc++) {
        const int cb = kc * 16;
        __syncthreads();
        #pragma unroll
        for (int it = 0; it < 8; it++) {
            const int o = ty + it*16;
            Et[tx][o] = __ldg(&Eb[o*C + cb + tx]);
        }
        {
            const int nn = t & 127, ccg = t >> 7;
            #pragma unroll
            for (int it = 0; it < 8; it++) {
                const int cc = ccg*8 + it;
                xsh[cc][nn] = __ldg(&xb[(cb + cc)*NPIX + nb + nn]);
            }
        }
        __syncthreads();
        #pragma unroll
        for (int cc = 0; cc < 16; cc++) {
            const float4 a0 = *(const float4*)&Et[cc][o0];
            const float4 a1 = *(const float4*)&Et[cc][o0 + 4];
            const unsigned long long* bpA = (const unsigned long long*)&xsh[cc][cA];
            const unsigned long long* bpB = (const unsigned long long*)&xsh[cc][cB];
            const unsigned long long b2[4] = { bpA[0], bpA[1], bpB[0], bpB[1] };
            const float a[8] = {a0.x, a0.y, a0.z, a0.w, a1.x, a1.y, a1.z, a1.w};
            #pragma unroll
            for (int i = 0; i < 8; i++) {
                const unsigned long long ad = dup2(a[i]);
                fma2(acc[i][0], ad, b2[0]);
                fma2(acc[i][1], ad, b2[1]);
                fma2(acc[i][2], ad, b2[2]);
                fma2(acc[i][3], ad, b2[3]);
            }
        }
    }

    #pragma unroll
    for (int i = 0; i < 8; i++) {
        const int r = o0 + i;
        const float e0 = g_e0[b*C + r];
        const float2 p0 = unp2(acc[i][0]), p1 = unp2(acc[i][1]);
        const float2 p2 = unp2(acc[i][2]), p3 = unp2(acc[i][3]);
        *(float4*)&ob[r*NPIX + nb + cA] =
            make_float4(p0.x + e0, p0.y + e0, p1.x + e0, p1.y + e0);
        *(float4*)&ob[r*NPIX + nb + cB] =
            make_float4(p2.x + e0, p2.y + e0, p3.x + e0, p3.y + e0);
    }
}

// ---------------- host launcher ----------------------------------------------
extern "C" void kernel_launch(void* const* d_in, const int* in_sizes, int n_in,
                              void* d_out, int out_size) {
    (void)in_sizes; (void)n_in; (void)out_size;
    const float* x   = (const float*)d_in[0];
    const float* w_q = (const float*)d_in[1];
    const float* b_q = (const float*)d_in[2];
    const float* w_k = (const float*)d_in[3];
    const float* b_k = (const float*)d_in[4];
    const float* w_v = (const float*)d_in[5];
    const float* b_v = (const float*)d_in[6];
    const float* w_o = (const float*)d_in[7];
    const float* b_o = (const float*)d_in[8];
    float* out = (float*)d_out;

    k_prep<<<32, 256>>>(w_q, b_q, w_k, b_k, w_v, b_v, w_o, b_o);
    k_gram<<<BATCH*NT, 256>>>(x);
    k_pe<<<BATCH*16, 256>>>(b_o);
    k_out<<<BATCH*NT, 256>>>(x, out);
}

// round 7
// speedup vs baseline: 1.6105x; 1.0709x over previous
#include <cuda_runtime.h>

// NonLocalModule (no softmax) collapsed via associativity:
//   out = (E + I) X + e0, with G = X X^T (128x128 per batch),
//   A = Wo Wv, Bm = Wk^T Wq,
//   E  = (1/N)[A G Bm + (A s) w2^T + u (Bm^T s)^T] + u w2^T  (+ I folded in)
//   e0 = (1/N)[(A G) kq + (A s) beta + u (s.kq)] + u beta + bo
//   u = Wo bv, w2 = Wq^T bk, kq = Wk^T bq, beta = bk.bq, s = X 1.

#define C     128
#define NPIX  6400
#define BATCH 2
#define NT    50   /* n tiles of 128 */

// ---------------- device scratch (no allocations allowed) --------------------
__device__ float g_Gp[BATCH*NT*C*C];
__device__ float g_sp[BATCH*NT*C];
__device__ float g_G [BATCH*C*C];
__device__ float g_s [BATCH*C];
__device__ float g_A [C*C];
__device__ float g_Bm[C*C];
__device__ float g_Et[BATCH*C*C];   // E+I stored TRANSPOSED: g_Et[c*C + r]
__device__ float g_e0[BATCH*C];
__device__ float g_u [C];
__device__ float g_w2[C];
__device__ float g_kq[C];
__device__ float g_skq[BATCH];
__device__ float g_beta;
__device__ int   g_cnt[BATCH];   // zero-init; re-zeroed by k_gram each replay

// ---------------- packed f32x2 helpers (Blackwell) ---------------------------
__device__ __forceinline__ void fma2(unsigned long long &acc,
                                     unsigned long long a, unsigned long long b) {
    asm("fma.rn.f32x2 %0, %1, %2, %0;" : "+l"(acc) : "l"(a), "l"(b));
}
__device__ __forceinline__ unsigned long long dup2(float a) {
    unsigned long long r; unsigned ai = __float_as_uint(a);
    asm("mov.b64 %0, {%1, %1};" : "=l"(r) : "r"(ai));
    return r;
}
__device__ __forceinline__ float2 unp2(unsigned long long v) {
    float2 r;
    r.x = __uint_as_float((unsigned)(v & 0xffffffffull));
    r.y = __uint_as_float((unsigned)(v >> 32));
    return r;
}
__device__ __forceinline__ float red16(float p) {
    p += __shfl_down_sync(0xffffffffu, p, 8, 16);
    p += __shfl_down_sync(0xffffffffu, p, 4, 16);
    p += __shfl_down_sync(0xffffffffu, p, 2, 16);
    p += __shfl_down_sync(0xffffffffu, p, 1, 16);
    return p;
}

// ---------------- k_prep: A = Wo Wv, Bm = Wk^T Wq, bias vecs (32 x 256) ------
__global__ void __launch_bounds__(256) k_prep(
        const float* __restrict__ w_q, const float* __restrict__ b_q,
        const float* __restrict__ w_k, const float* __restrict__ b_k,
        const float* __restrict__ w_v, const float* __restrict__ b_v,
        const float* __restrict__ w_o, const float* __restrict__ b_o) {
    (void)b_o;
    const int bid = blockIdx.x, t = threadIdx.x;
    const bool isA = bid < 16;
    const int r0 = (bid & 15) * 8;

    __shared__ float lhsS[8][C];
    __shared__ __align__(16) float rhsS[64][132];
    __shared__ float bkS[C];

    if (t < C) bkS[t] = __ldg(&b_k[t]);
    for (int e = t; e < 8*C; e += 256) {
        const int i = e >> 7, j = e & 127;
        lhsS[i][j] = isA ? __ldg(&w_o[(r0 + i)*C + j])
                         : __ldg(&w_k[j*C + (r0 + i)]);
    }
    __syncthreads();

    if (t < 128) {     // u[r] (A blocks) / kq[r] (Bm blocks)
        const int row = t >> 4, l = t & 15;
        const float* bv = isA ? b_v : b_q;
        float p = 0.f;
        #pragma unroll
        for (int j = 0; j < 8; j++) p += lhsS[row][l*8 + j] * __ldg(&bv[l*8 + j]);
        p = red16(p);
        if (l == 0) (isA ? g_u : g_kq)[r0 + row] = p;
    }
    if (bid == 16 && t >= 128 && t < 160) {     // beta = bk.bq
        const int l = t - 128;
        float p = 0.f;
        #pragma unroll
        for (int j = 0; j < 4; j++) p += bkS[l*4 + j] * __ldg(&b_q[l*4 + j]);
        #pragma unroll
        for (int off = 16; off > 0; off >>= 1)
            p += __shfl_down_sync(0xffffffffu, p, off);
        if (l == 0) g_beta = p;
    }

    const float* rhs = isA ? w_v : w_q;
    float* dst = isA ? g_A : g_Bm;
    const int c = t & 127, i0 = t >> 7;
    const int lrow = t >> 5, lcol = (t & 31) * 4;
    float acc[4] = {0.f, 0.f, 0.f, 0.f};
    float w2acc = 0.f;

    #pragma unroll
    for (int st = 0; st < 2; st++) {
        __syncthreads();
        #pragma unroll
        for (int it = 0; it < 8; it++) {
            const int row = lrow + it*8;
            const float4 v = *(const float4*)&rhs[(st*64 + row)*C + lcol];
            *(float4*)&rhsS[row][lcol] = v;
        }
        __syncthreads();
        #pragma unroll 16
        for (int jj = 0; jj < 64; jj++) {
            const float rv = rhsS[jj][c];
            w2acc += rv * bkS[st*64 + jj];
            #pragma unroll
            for (int q = 0; q < 4; q++)
                acc[q] += lhsS[i0 + 2*q][st*64 + jj] * rv;
        }
    }
    #pragma unroll
    for (int q = 0; q < 4; q++) dst[(r0 + i0 + 2*q)*C + c] = acc[q];
    if (bid == 16 && i0 == 0) g_w2[c] = w2acc;
}

// ---------------- k_gram: partial G = X X^T per 128-n tile (100 x 256) -------
// Double-buffered; per-lane output cols {2tx,2tx+1}+{0,32,64,96} (bank-clean).
__global__ void __launch_bounds__(256) k_gram(const float* __restrict__ x) {
    if (blockIdx.x == 0 && threadIdx.x == 0) { g_cnt[0] = 0; g_cnt[1] = 0; }

    const int b = blockIdx.x / NT;
    const int tile = blockIdx.x % NT;
    const int nb = tile * 128;
    const float* xb = x + b*C*NPIX;

    __shared__ __align__(16) float xs[2][16][132];

    const int t = threadIdx.x;
    const int tx = t & 15, ty = t >> 4;
    const int r0 = ty * 8;
    const int c0 = 2*tx;

    unsigned long long acc[8][4];
    #pragma unroll
    for (int i = 0; i < 8; i++)
        #pragma unroll
        for (int j = 0; j < 4; j++) acc[i][j] = 0ull;

    float spart[8];
    #pragma unroll
    for (int i = 0; i < 8; i++) spart[i] = 0.f;

    float ld[8];
    // prologue: chunk 0
    #pragma unroll
    for (int it = 0; it < 8; it++)
        ld[it] = __ldg(&xb[(ty + it*16)*NPIX + nb + tx]);
    #pragma unroll
    for (int it = 0; it < 8; it++) {
        xs[0][tx][ty + it*16] = ld[it];
        spart[it] += ld[it];
    }
    __syncthreads();

    for (int kc = 0; kc < 8; kc++) {
        if (kc < 7) {
            const int n0 = nb + (kc + 1)*16;
            #pragma unroll
            for (int it = 0; it < 8; it++)
                ld[it] = __ldg(&xb[(ty + it*16)*NPIX + n0 + tx]);
        }
        const int buf = kc & 1;
        #pragma unroll
        for (int nn = 0; nn < 16; nn++) {
            const float4 a0 = *(const float4*)&xs[buf][nn][r0];
            const float4 a1 = *(const float4*)&xs[buf][nn][r0 + 4];
            const unsigned long long b2[4] = {
                *(const unsigned long long*)&xs[buf][nn][c0],
                *(const unsigned long long*)&xs[buf][nn][32 + c0],
                *(const unsigned long long*)&xs[buf][nn][64 + c0],
                *(const unsigned long long*)&xs[buf][nn][96 + c0] };
            const float a[8] = {a0.x, a0.y, a0.z, a0.w, a1.x, a1.y, a1.z, a1.w};
            #pragma unroll
            for (int i = 0; i < 8; i++) {
                const unsigned long long ad = dup2(a[i]);
                fma2(acc[i][0], ad, b2[0]);
                fma2(acc[i][1], ad, b2[1]);
                fma2(acc[i][2], ad, b2[2]);
                fma2(acc[i][3], ad, b2[3]);
            }
        }
        if (kc < 7) {
            #pragma unroll
            for (int it = 0; it < 8; it++) {
                xs[buf ^ 1][tx][ty + it*16] = ld[it];
                spart[it] += ld[it];
            }
        }
        __syncthreads();
    }

    #pragma unroll
    for (int it = 0; it < 8; it++) {
        float v = red16(spart[it]);
        if (tx == 0) g_sp[(b*NT + tile)*C + ty + it*16] = v;
    }

    float* Gp = g_Gp + (size_t)(b*NT + tile)*C*C;
    #pragma unroll
    for (int i = 0; i < 8; i++) {
        *(float2*)&Gp[(r0 + i)*C +      c0] = unp2(acc[i][0]);
        *(float2*)&Gp[(r0 + i)*C + 32 + c0] = unp2(acc[i][1]);
        *(float2*)&Gp[(r0 + i)*C + 64 + c0] = unp2(acc[i][2]);
        *(float2*)&Gp[(r0 + i)*C + 96 + c0] = unp2(acc[i][3]);
    }
}

// ---------------- k_pe: fused G-reduce + P=A G + E(+I) + e0 (32 x 256) -------
__global__ void __launch_bounds__(256) k_pe(const float* __restrict__ b_o) {
    const int b  = blockIdx.x >> 4;
    const int rg = blockIdx.x & 15;
    const int r0 = rg * 8;
    const int t  = threadIdx.x;
    const float invN = 1.0f / (float)NPIX;

    __shared__ float As[8][C];
    __shared__ __align__(16) float stg[64][132];
    __shared__ __align__(16) float Ps[8][132];
    __shared__ float sS[C];
    __shared__ float kqS[C];
    __shared__ float t2S[8];
    __shared__ float redS[C];

    // ---- phase 1: reduce assigned G rows ------------------------------------
    {
        const float* base = g_Gp + (size_t)b*NT*C*C + r0*C;
        #pragma unroll
        for (int k = 0; k < 4; k++) {
            const int e = t + 256*k;
            float a = 0.f;
            #pragma unroll 10
            for (int ch = 0; ch < NT; ch++) a += base[(size_t)ch*C*C + e];
            g_G[b*C*C + r0*C + e] = a;
        }
        float sv = 0.f;
        if (rg == 0) {
            if (t < C) {
                const float* sb = g_sp + b*NT*C + t;
                #pragma unroll 10
                for (int ch = 0; ch < NT; ch++) sv += sb[ch*C];
                g_s[b*C + t] = sv;
                redS[t] = sv * __ldg(&g_kq[t]);
            }
            __syncthreads();
            if (t < 64) redS[t] += redS[t + 64];
            __syncthreads();
            if (t < 32) {
                float v = redS[t] + redS[t + 32];
                #pragma unroll
                for (int off = 16; off > 0; off >>= 1)
                    v += __shfl_down_sync(0xffffffffu, v, off);
                if (t == 0) g_skq[b] = v;
            }
        }
    }
    __syncthreads();
    if (t == 0) {
        __threadfence();
        atomicAdd(&g_cnt[b], 1);
        while (atomicAdd(&g_cnt[b], 0) < 16) {}
    }
    __syncthreads();
    __threadfence();

    // ---- phase 2 -------------------------------------------------------------
    if (t < C) { sS[t] = __ldcg(&g_s[b*C + t]); kqS[t] = __ldg(&g_kq[t]); }
    for (int e = t; e < 8*C; e += 256)
        As[e >> 7][e & 127] = __ldg(&g_A[(r0 + (e >> 7))*C + (e & 127)]);
    __syncthreads();

    if (t < 128) {                         // t2[r] = A_rows . s
        const int row = t >> 4, l = t & 15;
        float p = 0.f;
        #pragma unroll
        for (int j = 0; j < 8; j++) p += As[row][l*8 + j] * sS[l*8 + j];
        p = red16(p);
        if (l == 0) t2S[row] = p;
    }

    const int c = t & 127, i0 = t >> 7;
    const int lrow = t >> 5, lcol = (t & 31) * 4;

    // P = A_rows @ G
    {
        float acc[4] = {0.f, 0.f, 0.f, 0.f};
        const float* Gb = g_G + b*C*C;
        #pragma unroll
        for (int st = 0; st < 2; st++) {
            __syncthreads();
            #pragma unroll
            for (int it = 0; it < 8; it++) {
                const int row = lrow + it*8;
                const float4 v = __ldcg((const float4*)&Gb[(st*64 + row)*C + lcol]);
                *(float4*)&stg[row][lcol] = v;
            }
            __syncthreads();
            #pragma unroll 16
            for (int jj = 0; jj < 64; jj++) {
                const float gv = stg[jj][c];
                #pragma unroll
                for (int q = 0; q < 4; q++)
                    acc[q] += As[i0 + 2*q][st*64 + jj] * gv;
            }
        }
        #pragma unroll
        for (int q = 0; q < 4; q++) Ps[i0 + 2*q][c] = acc[q];
    }

    // E rows = invN * Pr @ Bm + rank-1 terms (+ I), stored TRANSPOSED
    {
        float acc[4] = {0.f, 0.f, 0.f, 0.f};
        float t1 = 0.f;
        #pragma unroll
        for (int st = 0; st < 2; st++) {
            __syncthreads();
            #pragma unroll
            for (int it = 0; it < 8; it++) {
                const int row = lrow + it*8;
                const float4 v = __ldg((const float4*)&g_Bm[(st*64 + row)*C + lcol]);
                *(float4*)&stg[row][lcol] = v;
            }
            __syncthreads();
            #pragma unroll 16
            for (int jj = 0; jj < 64; jj++) {
                const float bm = stg[jj][c];
                t1 += bm * sS[st*64 + jj];
                #pragma unroll
                for (int q = 0; q < 4; q++)
                    acc[q] += Ps[i0 + 2*q][st*64 + jj] * bm;
            }
        }
        const float w2c = __ldg(&g_w2[c]);
        #pragma unroll
        for (int q = 0; q < 4; q++) {
            const int i = i0 + 2*q;
            const int r = r0 + i;
            const float ur = __ldg(&g_u[r]);
            float val = invN*acc[q] + invN*ur*t1 + (invN*t2S[i] + ur)*w2c;
            if (r == c) val += 1.0f;
            g_Et[b*C*C + c*C + r] = val;      // transposed store
        }
    }
    if (t < 8) {
        float pk = 0.f;
        #pragma unroll 16
        for (int j = 0; j < C; j++) pk += Ps[t][j] * kqS[j];
        const int r = r0 + t;
        const float ur = __ldg(&g_u[r]);
        g_e0[b*C + r] = invN*pk + invN*ur*g_skq[b]
                      + (invN*t2S[t] + ur)*g_beta + __ldg(&b_o[r]);
    }
}

// ---------------- k_out: out = (E+I) X + e0 (100 x 256) ----------------------
// Double-buffered float4 staging; bank-clean per-lane cols {2tx,2tx+1}+{0,32,64,96}.
__global__ void __launch_bounds__(256) k_out(const float* __restrict__ x,
                                             float* __restrict__ out) {
    const int b = blockIdx.x / NT;
    const int tile = blockIdx.x % NT;
    const int nb = tile * 128;
    const float* xb = x + b*C*NPIX;
    float* ob = out + b*C*NPIX;
    const float* Etg = g_Et + b*C*C;

    __shared__ __align__(16) float Et[2][16][132];   // [cc][o] = E[o][cb+cc]
    __shared__ __align__(16) float xsh[2][16][132];  // [cc][nn]

    const int t = threadIdx.x;
    const int tx = t & 15, ty = t >> 4;
    const int o0 = ty * 8;
    const int c0 = 2*tx;

    // staging index: two float4s per array per thread
    const int cc0 = t >> 5,        f0 = (t & 31) * 4;         // idx = t
    const int cc1 = (t + 256) >> 5, f1 = f0;                  // idx = t+256

    unsigned long long acc[8][4];
    #pragma unroll
    for (int i = 0; i < 8; i++)
        #pragma unroll
        for (int j = 0; j < 4; j++) acc[i][j] = 0ull;

    float4 e0v, e1v, x0v, x1v;
    // prologue: chunk 0
    e0v = __ldg((const float4*)&Etg[cc0*C + f0]);
    e1v = __ldg((const float4*)&Etg[cc1*C + f1]);
    x0v = __ldg((const float4*)&xb[cc0*NPIX + nb + f0]);
    x1v = __ldg((const float4*)&xb[cc1*NPIX + nb + f1]);
    *(float4*)&Et[0][cc0][f0] = e0v;  *(float4*)&Et[0][cc1][f1] = e1v;
    *(float4*)&xsh[0][cc0][f0] = x0v; *(float4*)&xsh[0][cc1][f1] = x1v;
    __syncthreads();

    for (int kc = 0; kc < 8; kc++) {
        if (kc < 7) {
            const int cb = (kc + 1) * 16;
            e0v = __ldg((const float4*)&Etg[(cb + cc0)*C + f0]);
            e1v = __ldg((const float4*)&Etg[(cb + cc1)*C + f1]);
            x0v = __ldg((const float4*)&xb[(cb + cc0)*NPIX + nb + f0]);
            x1v = __ldg((const float4*)&xb[(cb + cc1)*NPIX + nb + f1]);
        }
        const int buf = kc & 1;
        #pragma unroll
        for (int cc = 0; cc < 16; cc++) {
            const float4 a0 = *(const float4*)&Et[buf][cc][o0];
            const float4 a1 = *(const float4*)&Et[buf][cc][o0 + 4];
            const unsigned long long b2[4] = {
                *(const unsigned long long*)&xsh[buf][cc][c0],
                *(const unsigned long long*)&xsh[buf][cc][32 + c0],
                *(const unsigned long long*)&xsh[buf][cc][64 + c0],
                *(const unsigned long long*)&xsh[buf][cc][96 + c0] };
            const float a[8] = {a0.x, a0.y, a0.z, a0.w, a1.x, a1.y, a1.z, a1.w};
            #pragma unroll
            for (int i = 0; i < 8; i++) {
                const unsigned long long ad = dup2(a[i]);
                fma2(acc[i][0], ad, b2[0]);
                fma2(acc[i][1], ad, b2[1]);
                fma2(acc[i][2], ad, b2[2]);
                fma2(acc[i][3], ad, b2[3]);
            }
        }
        if (kc < 7) {
            *(float4*)&Et[buf ^ 1][cc0][f0] = e0v;  *(float4*)&Et[buf ^ 1][cc1][f1] = e1v;
            *(float4*)&xsh[buf ^ 1][cc0][f0] = x0v; *(float4*)&xsh[buf ^ 1][cc1][f1] = x1v;
        }
        __syncthreads();
    }

    #pragma unroll
    for (int i = 0; i < 8; i++) {
        const int r = o0 + i;
        const float e0 = g_e0[b*C + r];
        float2 p0 = unp2(acc[i][0]), p1 = unp2(acc[i][1]);
        float2 p2 = unp2(acc[i][2]), p3 = unp2(acc[i][3]);
        p0.x += e0; p0.y += e0; p1.x += e0; p1.y += e0;
        p2.x += e0; p2.y += e0; p3.x += e0; p3.y += e0;
        *(float2*)&ob[r*NPIX + nb +      c0] = p0;
        *(float2*)&ob[r*NPIX + nb + 32 + c0] = p1;
        *(float2*)&ob[r*NPIX + nb + 64 + c0] = p2;
        *(float2*)&ob[r*NPIX + nb + 96 + c0] = p3;
    }
}

// ---------------- host launcher ----------------------------------------------
extern "C" void kernel_launch(void* const* d_in, const int* in_sizes, int n_in,
                              void* d_out, int out_size) {
    (void)in_sizes; (void)n_in; (void)out_size;
    const float* x   = (const float*)d_in[0];
    const float* w_q = (const float*)d_in[1];
    const float* b_q = (const float*)d_in[2];
    const float* w_k = (const float*)d_in[3];
    const float* b_k = (const float*)d_in[4];
    const float* w_v = (const float*)d_in[5];
    const float* b_v = (const float*)d_in[6];
    const float* w_o = (const float*)d_in[7];
    const float* b_o = (const float*)d_in[8];
    float* out = (float*)d_out;

    k_prep<<<32, 256>>>(w_q, b_q, w_k, b_k, w_v, b_v, w_o, b_o);
    k_gram<<<BATCH*NT, 256>>>(x);
    k_pe<<<BATCH*16, 256>>>(b_o);
    k_out<<<BATCH*NT, 256>>>(x, out);
}

// round 9
// speedup vs baseline: 1.6966x; 1.0535x over previous
#include <cuda_runtime.h>
#include <cuda_bf16.h>
#include <cstdint>

// NonLocalModule (no softmax) collapsed via associativity:
//   out = (E + I) X + e0, with G = X X^T (128x128 per batch),
//   A = Wo Wv, Bm = Wk^T Wq,
//   E  = (1/N)[A G Bm + (A s) w2^T + u (Bm^T s)^T] + u w2^T  (+ I folded in)
//   e0 = (1/N)[(A G) kq + (A s) beta + u (s.kq)] + u beta + bo
//   u = Wo bv, w2 = Wq^T bk, kq = Wk^T bq, beta = bk.bq, s = X 1.
// Gram in bf16 tensor cores (mma.sync, arch-portable): attention term is
// ~2e-5 of |out|, so bf16 gram error is invisible at 1e-3 tolerance.

#define C     128
#define NPIX  6400
#define BATCH 2
#define NT    50   /* n tiles of 128 */

// ---------------- device scratch (no allocations allowed) --------------------
__device__ float g_Gp[BATCH*NT*C*C];
__device__ float g_sp[BATCH*NT*C];
__device__ float g_G [BATCH*C*C];
__device__ float g_s [BATCH*C];
__device__ float g_A [C*C];
__device__ float g_Bm[C*C];
__device__ float g_Et[BATCH*C*C];   // E+I stored TRANSPOSED: g_Et[c*C + r]
__device__ float g_e0[BATCH*C];
__device__ float g_u [C];
__device__ float g_w2[C];
__device__ float g_kq[C];
__device__ float g_skq[BATCH];
__device__ float g_beta;
__device__ int   g_cnt[BATCH];   // re-zeroed by k_gram each replay

// ---------------- packed f32x2 helpers (Blackwell) ---------------------------
__device__ __forceinline__ void fma2(unsigned long long &acc,
                                     unsigned long long a, unsigned long long b) {
    asm("fma.rn.f32x2 %0, %1, %2, %0;" : "+l"(acc) : "l"(a), "l"(b));
}
__device__ __forceinline__ unsigned long long dup2(float a) {
    unsigned long long r; unsigned ai = __float_as_uint(a);
    asm("mov.b64 %0, {%1, %1};" : "=l"(r) : "r"(ai));
    return r;
}
__device__ __forceinline__ float2 unp2(unsigned long long v) {
    float2 r;
    r.x = __uint_as_float((unsigned)(v & 0xffffffffull));
    r.y = __uint_as_float((unsigned)(v >> 32));
    return r;
}
__device__ __forceinline__ float red16(float p) {
    p += __shfl_down_sync(0xffffffffu, p, 8, 16);
    p += __shfl_down_sync(0xffffffffu, p, 4, 16);
    p += __shfl_down_sync(0xffffffffu, p, 2, 16);
    p += __shfl_down_sync(0xffffffffu, p, 1, 16);
    return p;
}
__device__ __forceinline__ uint32_t smem_u32(const void* p) {
    uint32_t a;
    asm("{ .reg .u64 t; cvta.to.shared.u64 t, %1; cvt.u32.u64 %0, t; }"
        : "=r"(a) : "l"(p));
    return a;
}

// ---------------- warp-mma helpers (sm_80+, works on plain sm_100) -----------
__device__ __forceinline__ void ldsm_x4(uint32_t* r, uint32_t addr) {
    asm volatile("ldmatrix.sync.aligned.m8n8.x4.shared.b16 {%0,%1,%2,%3}, [%4];"
        : "=r"(r[0]), "=r"(r[1]), "=r"(r[2]), "=r"(r[3]) : "r"(addr));
}
__device__ __forceinline__ void ldsm_x2(uint32_t* r, uint32_t addr) {
    asm volatile("ldmatrix.sync.aligned.m8n8.x2.shared.b16 {%0,%1}, [%2];"
        : "=r"(r[0]), "=r"(r[1]) : "r"(addr));
}
__device__ __forceinline__ void mma16816(float* d, const uint32_t* a,
                                         const uint32_t* b) {
    asm volatile(
        "mma.sync.aligned.m16n8k16.row.col.f32.bf16.bf16.f32 "
        "{%0,%1,%2,%3}, {%4,%5,%6,%7}, {%8,%9}, {%0,%1,%2,%3};"
        : "+f"(d[0]), "+f"(d[1]), "+f"(d[2]), "+f"(d[3])
        : "r"(a[0]), "r"(a[1]), "r"(a[2]), "r"(a[3]), "r"(b[0]), "r"(b[1]));
}

// ---------------- k_prep: A = Wo Wv, Bm = Wk^T Wq, bias vecs (32 x 256) ------
__global__ void __launch_bounds__(256) k_prep(
        const float* __restrict__ w_q, const float* __restrict__ b_q,
        const float* __restrict__ w_k, const float* __restrict__ b_k,
        const float* __restrict__ w_v, const float* __restrict__ b_v,
        const float* __restrict__ w_o, const float* __restrict__ b_o) {
    (void)b_o;
    const int bid = blockIdx.x, t = threadIdx.x;
    const bool isA = bid < 16;
    const int r0 = (bid & 15) * 8;

    __shared__ float lhsS[8][C];
    __shared__ __align__(16) float rhsS[64][132];
    __shared__ float bkS[C];

    if (t < C) bkS[t] = __ldg(&b_k[t]);
    for (int e = t; e < 8*C; e += 256) {
        const int i = e >> 7, j = e & 127;
        lhsS[i][j] = isA ? __ldg(&w_o[(r0 + i)*C + j])
                         : __ldg(&w_k[j*C + (r0 + i)]);
    }
    __syncthreads();

    if (t < 128) {     // u[r] (A blocks) / kq[r] (Bm blocks)
        const int row = t >> 4, l = t & 15;
        const float* bv = isA ? b_v : b_q;
        float p = 0.f;
        #pragma unroll
        for (int j = 0; j < 8; j++) p += lhsS[row][l*8 + j] * __ldg(&bv[l*8 + j]);
        p = red16(p);
        if (l == 0) (isA ? g_u : g_kq)[r0 + row] = p;
    }
    if (bid == 16 && t >= 128 && t < 160) {     // beta = bk.bq
        const int l = t - 128;
        float p = 0.f;
        #pragma unroll
        for (int j = 0; j < 4; j++) p += bkS[l*4 + j] * __ldg(&b_q[l*4 + j]);
        #pragma unroll
        for (int off = 16; off > 0; off >>= 1)
            p += __shfl_down_sync(0xffffffffu, p, off);
        if (l == 0) g_beta = p;
    }

    const float* rhs = isA ? w_v : w_q;
    float* dst = isA ? g_A : g_Bm;
    const int c = t & 127, i0 = t >> 7;
    const int lrow = t >> 5, lcol = (t & 31) * 4;
    float acc[4] = {0.f, 0.f, 0.f, 0.f};
    float w2acc = 0.f;

    #pragma unroll
    for (int st = 0; st < 2; st++) {
        __syncthreads();
        #pragma unroll
        for (int it = 0; it < 8; it++) {
            const int row = lrow + it*8;
            const float4 v = *(const float4*)&rhs[(st*64 + row)*C + lcol];
            *(float4*)&rhsS[row][lcol] = v;
        }
        __syncthreads();
        #pragma unroll 16
        for (int jj = 0; jj < 64; jj++) {
            const float rv = rhsS[jj][c];
            w2acc += rv * bkS[st*64 + jj];
            #pragma unroll
            for (int q = 0; q < 4; q++)
                acc[q] += lhsS[i0 + 2*q][st*64 + jj] * rv;
        }
    }
    #pragma unroll
    for (int q = 0; q < 4; q++) dst[(r0 + i0 + 2*q)*C + c] = acc[q];
    if (bid == 16 && i0 == 0) g_w2[c] = w2acc;
}

// ---------------- k_gram: bf16 mma.sync partial G = X X^T (100 x 256) --------
// X tile (128c x 128n) -> bf16 smem [c][n], pitch 136 (ldmatrix conflict-free).
// SYRK: A frag (row, m16k16) and B frag (col == N x K row-major) both read the
// same tile. 8 warps x (64x32 tile) x 8 k-steps of mma.m16n8k16.
__global__ void __launch_bounds__(256) k_gram(const float* __restrict__ x) {
    if (blockIdx.x == 0 && threadIdx.x == 0) { g_cnt[0] = 0; g_cnt[1] = 0; }

    __shared__ __align__(16) __nv_bfloat16 xs[128][136];

    const int b = blockIdx.x / NT, tile = blockIdx.x % NT;
    const int nb = tile * 128;
    const float* xb = x + b*C*NPIX;
    const int t = threadIdx.x, wid = t >> 5, lane = t & 31;

    // fp32 -> bf16 into [c][n] smem (coalesced LDG.128, conflict-free STS.64)
    #pragma unroll
    for (int it = 0; it < 16; it++) {
        const int e = t + it*256;
        const int row = e >> 5, q = e & 31;
        const float4 v = __ldg((const float4*)&xb[row*NPIX + nb + q*4]);
        uint32_t p0, p1;
        asm("cvt.rn.bf16x2.f32 %0, %1, %2;" : "=r"(p0) : "f"(v.y), "f"(v.x));
        asm("cvt.rn.bf16x2.f32 %0, %1, %2;" : "=r"(p1) : "f"(v.w), "f"(v.z));
        *(uint2*)&xs[row][q*4] = make_uint2(p0, p1);
    }
    // s row sums in fp32 (L1-hot re-read)
    {
        const int c = t >> 1, half = (t & 1) * 64;
        float sv = 0.f;
        #pragma unroll
        for (int i = 0; i < 16; i++) {
            const float4 v = __ldg((const float4*)&xb[c*NPIX + nb + half + i*4]);
            sv += (v.x + v.y) + (v.z + v.w);
        }
        sv += __shfl_xor_sync(0xffffffffu, sv, 1);
        if (!(t & 1)) g_sp[(b*NT + tile)*C + c] = sv;
    }
    __syncthreads();

    // warp tile: wm = wid&1 -> m block of 64; wn = wid>>1 -> n block of 32
    const int m0 = (wid & 1) * 64;
    const int n0 = (wid >> 1) * 32;
    const uint32_t base = smem_u32(xs);

    float acc[4][4][4];
    #pragma unroll
    for (int i = 0; i < 4; i++)
        #pragma unroll
        for (int j = 0; j < 4; j++)
            #pragma unroll
            for (int q = 0; q < 4; q++) acc[i][j][q] = 0.f;

    const int arow = lane & 15, acol8 = (lane >> 4) << 3;   // A ldmatrix addr
    const int brow = lane & 7,  bcol8 = ((lane >> 3) & 1) << 3;  // B addr

    #pragma unroll
    for (int ks = 0; ks < 8; ks++) {
        const int k0 = ks * 16;
        uint32_t af[4][4], bf[4][2];
        #pragma unroll
        for (int i = 0; i < 4; i++)
            ldsm_x4(af[i], base + ((m0 + 16*i + arow)*136 + k0 + acol8)*2);
        #pragma unroll
        for (int j = 0; j < 4; j++)
            ldsm_x2(bf[j], base + ((n0 + 8*j + brow)*136 + k0 + bcol8)*2);
        #pragma unroll
        for (int i = 0; i < 4; i++)
            #pragma unroll
            for (int j = 0; j < 4; j++)
                mma16816(acc[i][j], af[i], bf[j]);
    }

    float* Gp = g_Gp + (size_t)(b*NT + tile)*C*C;
    const int group = lane >> 2, tig = lane & 3;
    #pragma unroll
    for (int i = 0; i < 4; i++)
        #pragma unroll
        for (int j = 0; j < 4; j++) {
            const int row = m0 + 16*i + group;
            const int col = n0 + 8*j + 2*tig;
            *(float2*)&Gp[row*C + col]       = make_float2(acc[i][j][0], acc[i][j][1]);
            *(float2*)&Gp[(row + 8)*C + col] = make_float2(acc[i][j][2], acc[i][j][3]);
        }
}

// ---------------- k_pe: fused G-reduce + P=A G + E(+I) + e0 (32 x 256) -------
__global__ void __launch_bounds__(256) k_pe(const float* __restrict__ b_o) {
    const int b  = blockIdx.x >> 4;
    const int rg = blockIdx.x & 15;
    const int r0 = rg * 8;
    const int t  = threadIdx.x;
    const float invN = 1.0f / (float)NPIX;

    __shared__ float As[8][C];
    __shared__ __align__(16) float stg[64][132];
    __shared__ __align__(16) float Ps[8][132];
    __shared__ float sS[C];
    __shared__ float kqS[C];
    __shared__ float t2S[8];
    __shared__ float redS[C];

    {
        const float* base = g_Gp + (size_t)b*NT*C*C + r0*C;
        #pragma unroll
        for (int k = 0; k < 4; k++) {
            const int e = t + 256*k;
            float a = 0.f;
            #pragma unroll 10
            for (int ch = 0; ch < NT; ch++) a += base[(size_t)ch*C*C + e];
            g_G[b*C*C + r0*C + e] = a;
        }
        float sv = 0.f;
        if (rg == 0) {
            if (t < C) {
                const float* sb = g_sp + b*NT*C + t;
                #pragma unroll 10
                for (int ch = 0; ch < NT; ch++) sv += sb[ch*C];
                g_s[b*C + t] = sv;
                redS[t] = sv * __ldg(&g_kq[t]);
            }
            __syncthreads();
            if (t < 64) redS[t] += redS[t + 64];
            __syncthreads();
            if (t < 32) {
                float v = redS[t] + redS[t + 32];
                #pragma unroll
                for (int off = 16; off > 0; off >>= 1)
                    v += __shfl_down_sync(0xffffffffu, v, off);
                if (t == 0) g_skq[b] = v;
            }
        }
    }
    __syncthreads();
    if (t == 0) {
        __threadfence();
        atomicAdd(&g_cnt[b], 1);
        while (atomicAdd(&g_cnt[b], 0) < 16) {}
    }
    __syncthreads();
    __threadfence();

    if (t < C) { sS[t] = __ldcg(&g_s[b*C + t]); kqS[t] = __ldg(&g_kq[t]); }
    for (int e = t; e < 8*C; e += 256)
        As[e >> 7][e & 127] = __ldg(&g_A[(r0 + (e >> 7))*C + (e & 127)]);
    __syncthreads();

    if (t < 128) {
        const int row = t >> 4, l = t & 15;
        float p = 0.f;
        #pragma unroll
        for (int j = 0; j < 8; j++) p += As[row][l*8 + j] * sS[l*8 + j];
        p = red16(p);
        if (l == 0) t2S[row] = p;
    }

    const int c = t & 127, i0 = t >> 7;
    const int lrow = t >> 5, lcol = (t & 31) * 4;

    {
        float acc[4] = {0.f, 0.f, 0.f, 0.f};
        const float* Gb = g_G + b*C*C;
        #pragma unroll
        for (int st = 0; st < 2; st++) {
            __syncthreads();
            #pragma unroll
            for (int it = 0; it < 8; it++) {
                const int row = lrow + it*8;
                const float4 v = __ldcg((const float4*)&Gb[(st*64 + row)*C + lcol]);
                *(float4*)&stg[row][lcol] = v;
            }
            __syncthreads();
            #pragma unroll 16
            for (int jj = 0; jj < 64; jj++) {
                const float gv = stg[jj][c];
                #pragma unroll
                for (int q = 0; q < 4; q++)
                    acc[q] += As[i0 + 2*q][st*64 + jj] * gv;
            }
        }
        #pragma unroll
        for (int q = 0; q < 4; q++) Ps[i0 + 2*q][c] = acc[q];
    }

    {
        float acc[4] = {0.f, 0.f, 0.f, 0.f};
        float t1 = 0.f;
        #pragma unroll
        for (int st = 0; st < 2; st++) {
            __syncthreads();
            #pragma unroll
            for (int it = 0; it < 8; it++) {
                const int row = lrow + it*8;
                const float4 v = __ldg((const float4*)&g_Bm[(st*64 + row)*C + lcol]);
                *(float4*)&stg[row][lcol] = v;
            }
            __syncthreads();
            #pragma unroll 16
            for (int jj = 0; jj < 64; jj++) {
                const float bm = stg[jj][c];
                t1 += bm * sS[st*64 + jj];
                #pragma unroll
                for (int q = 0; q < 4; q++)
                    acc[q] += Ps[i0 + 2*q][st*64 + jj] * bm;
            }
        }
        const float w2c = __ldg(&g_w2[c]);
        #pragma unroll
        for (int q = 0; q < 4; q++) {
            const int i = i0 + 2*q;
            const int r = r0 + i;
            const float ur = __ldg(&g_u[r]);
            float val = invN*acc[q] + invN*ur*t1 + (invN*t2S[i] + ur)*w2c;
            if (r == c) val += 1.0f;
            g_Et[b*C*C + c*C + r] = val;      // transposed store
        }
    }
    if (t < 8) {
        float pk = 0.f;
        #pragma unroll 16
        for (int j = 0; j < C; j++) pk += Ps[t][j] * kqS[j];
        const int r = r0 + t;
        const float ur = __ldg(&g_u[r]);
        g_e0[b*C + r] = invN*pk + invN*ur*g_skq[b]
                      + (invN*t2S[t] + ur)*g_beta + __ldg(&b_o[r]);
    }
}

// ---------------- k_out: out = (E+I) X + e0 (400 x 256) ----------------------
// 50 n-tiles x 4 row-groups (32 rows) x 2 batches; 3 blocks/SM co-resident.
__global__ void __launch_bounds__(256, 3) k_out(const float* __restrict__ x,
                                                float* __restrict__ out) {
    const int bid = blockIdx.x;
    const int b = bid / 200;
    const int rem = bid % 200;
    const int tile = rem >> 2;
    const int rg = rem & 3;
    const int r0 = rg * 32;
    const int nb = tile * 128;
    const float* xb = x + b*C*NPIX;
    float* ob = out + b*C*NPIX;
    const float* Etg = g_Et + b*C*C;

    __shared__ __align__(16) float Et[2][16][36];    // [cc][j] = E[r0+j][cb+cc]
    __shared__ __align__(16) float xsh[2][16][128];  // [cc][nn]

    const int t = threadIdx.x;
    const int tx = t & 15, ty = t >> 4;
    const int lr = ty * 2;          // local rows lr, lr+1
    const int c0 = 2*tx;

    const int ecc = t >> 3, ef = (t & 7) * 4;        // Et: first 128 threads
    const int xcc0 = t >> 5,          xq0 = (t & 31) * 4;
    const int xcc1 = (t + 256) >> 5,  xq1 = xq0;

    unsigned long long acc[2][4];
    #pragma unroll
    for (int i = 0; i < 2; i++)
        #pragma unroll
        for (int j = 0; j < 4; j++) acc[i][j] = 0ull;

    float4 ev, x0v, x1v;
    if (t < 128) ev = __ldg((const float4*)&Etg[ecc*C + r0 + ef]);
    x0v = __ldg((const float4*)&xb[xcc0*NPIX + nb + xq0]);
    x1v = __ldg((const float4*)&xb[xcc1*NPIX + nb + xq1]);
    if (t < 128) *(float4*)&Et[0][ecc][ef] = ev;
    *(float4*)&xsh[0][xcc0][xq0] = x0v;
    *(float4*)&xsh[0][xcc1][xq1] = x1v;
    __syncthreads();

    for (int kc = 0; kc < 8; kc++) {
        if (kc < 7) {
            const int cb = (kc + 1) * 16;
            if (t < 128) ev = __ldg((const float4*)&Etg[(cb + ecc)*C + r0 + ef]);
            x0v = __ldg((const float4*)&xb[(cb + xcc0)*NPIX + nb + xq0]);
            x1v = __ldg((const float4*)&xb[(cb + xcc1)*NPIX + nb + xq1]);
        }
        const int buf = kc & 1;
        #pragma unroll
        for (int cc = 0; cc < 16; cc++) {
            const float2 a = *(const float2*)&Et[buf][cc][lr];
            const unsigned long long b2[4] = {
                *(const unsigned long long*)&xsh[buf][cc][c0],
                *(const unsigned long long*)&xsh[buf][cc][32 + c0],
                *(const unsigned long long*)&xsh[buf][cc][64 + c0],
                *(const unsigned long long*)&xsh[buf][cc][96 + c0] };
            const unsigned long long a0 = dup2(a.x), a1 = dup2(a.y);
            fma2(acc[0][0], a0, b2[0]); fma2(acc[0][1], a0, b2[1]);
            fma2(acc[0][2], a0, b2[2]); fma2(acc[0][3], a0, b2[3]);
            fma2(acc[1][0], a1, b2[0]); fma2(acc[1][1], a1, b2[1]);
            fma2(acc[1][2], a1, b2[2]); fma2(acc[1][3], a1, b2[3]);
        }
        if (kc < 7) {
            if (t < 128) *(float4*)&Et[buf ^ 1][ecc][ef] = ev;
            *(float4*)&xsh[buf ^ 1][xcc0][xq0] = x0v;
            *(float4*)&xsh[buf ^ 1][xcc1][xq1] = x1v;
        }
        __syncthreads();
    }

    #pragma unroll
    for (int i = 0; i < 2; i++) {
        const int r = r0 + lr + i;
        const float e0 = __ldg(&g_e0[b*C + r]);
        float2 p0 = unp2(acc[i][0]), p1 = unp2(acc[i][1]);
        float2 p2 = unp2(acc[i][2]), p3 = unp2(acc[i][3]);
        p0.x += e0; p0.y += e0; p1.x += e0; p1.y += e0;
        p2.x += e0; p2.y += e0; p3.x += e0; p3.y += e0;
        *(float2*)&ob[r*NPIX + nb +      c0] = p0;
        *(float2*)&ob[r*NPIX + nb + 32 + c0] = p1;
        *(float2*)&ob[r*NPIX + nb + 64 + c0] = p2;
        *(float2*)&ob[r*NPIX + nb + 96 + c0] = p3;
    }
}

// ---------------- host launcher ----------------------------------------------
extern "C" void kernel_launch(void* const* d_in, const int* in_sizes, int n_in,
                              void* d_out, int out_size) {
    (void)in_sizes; (void)n_in; (void)out_size;
    const float* x   = (const float*)d_in[0];
    const float* w_q = (const float*)d_in[1];
    const float* b_q = (const float*)d_in[2];
    const float* w_k = (const float*)d_in[3];
    const float* b_k = (const float*)d_in[4];
    const float* w_v = (const float*)d_in[5];
    const float* b_v = (const float*)d_in[6];
    const float* w_o = (const float*)d_in[7];
    const float* b_o = (const float*)d_in[8];
    float* out = (float*)d_out;

    k_prep<<<32, 256>>>(w_q, b_q, w_k, b_k, w_v, b_v, w_o, b_o);
    k_gram<<<BATCH*NT, 256>>>(x);
    k_pe<<<BATCH*16, 256>>>(b_o);
    k_out<<<400, 256>>>(x, out);
}

// round 10
// speedup vs baseline: 2.0439x; 1.2047x over previous
#include <cuda_runtime.h>
#include <cuda_bf16.h>
#include <cstdint>

// NonLocalModule (no softmax) collapsed via associativity:
//   out = X + E' X + e0, with G = X X^T (128x128 per batch),
//   A = Wo Wv, Bm = Wk^T Wq,
//   E' = (1/N)[A G Bm + (A s) w2^T + u (Bm^T s)^T] + u w2^T   (NO identity)
//   e0 = (1/N)[(A G) kq + (A s) beta + u (s.kq)] + u beta + bo
// Both big GEMMs (gram, E'X) run on bf16 mma.sync: E'X is ~2e-4 of |out|,
// so bf16 error lands ~1e-7 relative. Residual X + e0 added in fp32.

#define C     128
#define NPIX  6400
#define BATCH 2
#define NT    50   /* n tiles of 128 */

// ---------------- device scratch (no allocations allowed) --------------------
__device__ float g_Gp[BATCH*NT*C*C];
__device__ float g_sp[BATCH*NT*C];
__device__ float g_G [BATCH*C*C];
__device__ float g_s [BATCH*C];
__device__ float g_A [C*C];
__device__ float g_Bm[C*C];
__device__ __nv_bfloat16 g_Ebf[BATCH*C*C];   // E' bf16, row-major [r][c]
__device__ float g_e0[BATCH*C];
__device__ float g_u [C];
__device__ float g_w2[C];
__device__ float g_kq[C];
__device__ float g_skq[BATCH];
__device__ float g_beta;
__device__ int   g_cnt[BATCH];   // re-zeroed by k_gram each replay

// ---------------- small helpers ----------------------------------------------
__device__ __forceinline__ float red16(float p) {
    p += __shfl_down_sync(0xffffffffu, p, 8, 16);
    p += __shfl_down_sync(0xffffffffu, p, 4, 16);
    p += __shfl_down_sync(0xffffffffu, p, 2, 16);
    p += __shfl_down_sync(0xffffffffu, p, 1, 16);
    return p;
}
__device__ __forceinline__ uint32_t smem_u32(const void* p) {
    uint32_t a;
    asm("{ .reg .u64 t; cvta.to.shared.u64 t, %1; cvt.u32.u64 %0, t; }"
        : "=r"(a) : "l"(p));
    return a;
}

// ---------------- warp-mma helpers (sm_80+, works on plain sm_100) -----------
__device__ __forceinline__ void ldsm_x4(uint32_t* r, uint32_t addr) {
    asm volatile("ldmatrix.sync.aligned.m8n8.x4.shared.b16 {%0,%1,%2,%3}, [%4];"
        : "=r"(r[0]), "=r"(r[1]), "=r"(r[2]), "=r"(r[3]) : "r"(addr));
}
__device__ __forceinline__ void ldsm_x2(uint32_t* r, uint32_t addr) {
    asm volatile("ldmatrix.sync.aligned.m8n8.x2.shared.b16 {%0,%1}, [%2];"
        : "=r"(r[0]), "=r"(r[1]) : "r"(addr));
}
__device__ __forceinline__ void ldsm_x2_trans(uint32_t* r, uint32_t addr) {
    asm volatile("ldmatrix.sync.aligned.m8n8.x2.trans.shared.b16 {%0,%1}, [%2];"
        : "=r"(r[0]), "=r"(r[1]) : "r"(addr));
}
__device__ __forceinline__ void mma16816(float* d, const uint32_t* a,
                                         const uint32_t* b) {
    asm volatile(
        "mma.sync.aligned.m16n8k16.row.col.f32.bf16.bf16.f32 "
        "{%0,%1,%2,%3}, {%4,%5,%6,%7}, {%8,%9}, {%0,%1,%2,%3};"
        : "+f"(d[0]), "+f"(d[1]), "+f"(d[2]), "+f"(d[3])
        : "r"(a[0]), "r"(a[1]), "r"(a[2]), "r"(a[3]), "r"(b[0]), "r"(b[1]));
}

// ---------------- k_prep: A = Wo Wv, Bm = Wk^T Wq, bias vecs (32 x 256) ------
__global__ void __launch_bounds__(256) k_prep(
        const float* __restrict__ w_q, const float* __restrict__ b_q,
        const float* __restrict__ w_k, const float* __restrict__ b_k,
        const float* __restrict__ w_v, const float* __restrict__ b_v,
        const float* __restrict__ w_o, const float* __restrict__ b_o) {
    (void)b_o;
    const int bid = blockIdx.x, t = threadIdx.x;
    const bool isA = bid < 16;
    const int r0 = (bid & 15) * 8;

    __shared__ float lhsS[8][C];
    __shared__ __align__(16) float rhsS[64][132];
    __shared__ float bkS[C];

    if (t < C) bkS[t] = __ldg(&b_k[t]);
    for (int e = t; e < 8*C; e += 256) {
        const int i = e >> 7, j = e & 127;
        lhsS[i][j] = isA ? __ldg(&w_o[(r0 + i)*C + j])
                         : __ldg(&w_k[j*C + (r0 + i)]);
    }
    __syncthreads();

    if (t < 128) {     // u[r] (A blocks) / kq[r] (Bm blocks)
        const int row = t >> 4, l = t & 15;
        const float* bv = isA ? b_v : b_q;
        float p = 0.f;
        #pragma unroll
        for (int j = 0; j < 8; j++) p += lhsS[row][l*8 + j] * __ldg(&bv[l*8 + j]);
        p = red16(p);
        if (l == 0) (isA ? g_u : g_kq)[r0 + row] = p;
    }
    if (bid == 16 && t >= 128 && t < 160) {     // beta = bk.bq
        const int l = t - 128;
        float p = 0.f;
        #pragma unroll
        for (int j = 0; j < 4; j++) p += bkS[l*4 + j] * __ldg(&b_q[l*4 + j]);
        #pragma unroll
        for (int off = 16; off > 0; off >>= 1)
            p += __shfl_down_sync(0xffffffffu, p, off);
        if (l == 0) g_beta = p;
    }

    const float* rhs = isA ? w_v : w_q;
    float* dst = isA ? g_A : g_Bm;
    const int c = t & 127, i0 = t >> 7;
    const int lrow = t >> 5, lcol = (t & 31) * 4;
    float acc[4] = {0.f, 0.f, 0.f, 0.f};
    float w2acc = 0.f;

    #pragma unroll
    for (int st = 0; st < 2; st++) {
        __syncthreads();
        #pragma unroll
        for (int it = 0; it < 8; it++) {
            const int row = lrow + it*8;
            const float4 v = *(const float4*)&rhs[(st*64 + row)*C + lcol];
            *(float4*)&rhsS[row][lcol] = v;
        }
        __syncthreads();
        #pragma unroll 16
        for (int jj = 0; jj < 64; jj++) {
            const float rv = rhsS[jj][c];
            w2acc += rv * bkS[st*64 + jj];
            #pragma unroll
            for (int q = 0; q < 4; q++)
                acc[q] += lhsS[i0 + 2*q][st*64 + jj] * rv;
        }
    }
    #pragma unroll
    for (int q = 0; q < 4; q++) dst[(r0 + i0 + 2*q)*C + c] = acc[q];
    if (bid == 16 && i0 == 0) g_w2[c] = w2acc;
}

// ---------------- k_gram: bf16 mma.sync partial G = X X^T (100 x 256) --------
__global__ void __launch_bounds__(256) k_gram(const float* __restrict__ x) {
    if (blockIdx.x == 0 && threadIdx.x == 0) { g_cnt[0] = 0; g_cnt[1] = 0; }

    __shared__ __align__(16) __nv_bfloat16 xs[128][136];

    const int b = blockIdx.x / NT, tile = blockIdx.x % NT;
    const int nb = tile * 128;
    const float* xb = x + b*C*NPIX;
    const int t = threadIdx.x, wid = t >> 5, lane = t & 31;

    #pragma unroll
    for (int it = 0; it < 16; it++) {
        const int e = t + it*256;
        const int row = e >> 5, q = e & 31;
        const float4 v = __ldg((const float4*)&xb[row*NPIX + nb + q*4]);
        uint32_t p0, p1;
        asm("cvt.rn.bf16x2.f32 %0, %1, %2;" : "=r"(p0) : "f"(v.y), "f"(v.x));
        asm("cvt.rn.bf16x2.f32 %0, %1, %2;" : "=r"(p1) : "f"(v.w), "f"(v.z));
        *(uint2*)&xs[row][q*4] = make_uint2(p0, p1);
    }
    // s row sums in fp32 (L1-hot re-read)
    {
        const int c = t >> 1, half = (t & 1) * 64;
        float sv = 0.f;
        #pragma unroll
        for (int i = 0; i < 16; i++) {
            const float4 v = __ldg((const float4*)&xb[c*NPIX + nb + half + i*4]);
            sv += (v.x + v.y) + (v.z + v.w);
        }
        sv += __shfl_xor_sync(0xffffffffu, sv, 1);
        if (!(t & 1)) g_sp[(b*NT + tile)*C + c] = sv;
    }
    __syncthreads();

    const int m0 = (wid & 1) * 64;
    const int n0 = (wid >> 1) * 32;
    const uint32_t base = smem_u32(xs);

    float acc[4][4][4];
    #pragma unroll
    for (int i = 0; i < 4; i++)
        #pragma unroll
        for (int j = 0; j < 4; j++)
            #pragma unroll
            for (int q = 0; q < 4; q++) acc[i][j][q] = 0.f;

    const int arow = lane & 15, acol8 = (lane >> 4) << 3;
    const int brow = lane & 7,  bcol8 = ((lane >> 3) & 1) << 3;

    #pragma unroll
    for (int ks = 0; ks < 8; ks++) {
        const int k0 = ks * 16;
        uint32_t af[4][4], bf[4][2];
        #pragma unroll
        for (int i = 0; i < 4; i++)
            ldsm_x4(af[i], base + ((m0 + 16*i + arow)*136 + k0 + acol8)*2);
        #pragma unroll
        for (int j = 0; j < 4; j++)
            ldsm_x2(bf[j], base + ((n0 + 8*j + brow)*136 + k0 + bcol8)*2);
        #pragma unroll
        for (int i = 0; i < 4; i++)
            #pragma unroll
            for (int j = 0; j < 4; j++)
                mma16816(acc[i][j], af[i], bf[j]);
    }

    float* Gp = g_Gp + (size_t)(b*NT + tile)*C*C;
    const int group = lane >> 2, tig = lane & 3;
    #pragma unroll
    for (int i = 0; i < 4; i++)
        #pragma unroll
        for (int j = 0; j < 4; j++) {
            const int row = m0 + 16*i + group;
            const int col = n0 + 8*j + 2*tig;
            *(float2*)&Gp[row*C + col]       = make_float2(acc[i][j][0], acc[i][j][1]);
            *(float2*)&Gp[(row + 8)*C + col] = make_float2(acc[i][j][2], acc[i][j][3]);
        }
}

// ---------------- k_pe: fused G-reduce + P=A G + E' bf16 + e0 (32 x 256) -----
__global__ void __launch_bounds__(256) k_pe(const float* __restrict__ b_o) {
    const int b  = blockIdx.x >> 4;
    const int rg = blockIdx.x & 15;
    const int r0 = rg * 8;
    const int t  = threadIdx.x;
    const float invN = 1.0f / (float)NPIX;

    __shared__ float As[8][C];
    __shared__ __align__(16) float stg[64][132];
    __shared__ __align__(16) float Ps[8][132];
    __shared__ float sS[C];
    __shared__ float kqS[C];
    __shared__ float t2S[8];
    __shared__ float redS[C];

    {
        const float* base = g_Gp + (size_t)b*NT*C*C + r0*C;
        #pragma unroll
        for (int k = 0; k < 4; k++) {
            const int e = t + 256*k;
            float a = 0.f;
            #pragma unroll 10
            for (int ch = 0; ch < NT; ch++) a += base[(size_t)ch*C*C + e];
            g_G[b*C*C + r0*C + e] = a;
        }
        float sv = 0.f;
        if (rg == 0) {
            if (t < C) {
                const float* sb = g_sp + b*NT*C + t;
                #pragma unroll 10
                for (int ch = 0; ch < NT; ch++) sv += sb[ch*C];
                g_s[b*C + t] = sv;
                redS[t] = sv * __ldg(&g_kq[t]);
            }
            __syncthreads();
            if (t < 64) redS[t] += redS[t + 64];
            __syncthreads();
            if (t < 32) {
                float v = redS[t] + redS[t + 32];
                #pragma unroll
                for (int off = 16; off > 0; off >>= 1)
                    v += __shfl_down_sync(0xffffffffu, v, off);
                if (t == 0) g_skq[b] = v;
            }
        }
    }
    __syncthreads();
    if (t == 0) {
        __threadfence();
        atomicAdd(&g_cnt[b], 1);
        while (atomicAdd(&g_cnt[b], 0) < 16) {}
    }
    __syncthreads();
    __threadfence();

    if (t < C) { sS[t] = __ldcg(&g_s[b*C + t]); kqS[t] = __ldg(&g_kq[t]); }
    for (int e = t; e < 8*C; e += 256)
        As[e >> 7][e & 127] = __ldg(&g_A[(r0 + (e >> 7))*C + (e & 127)]);
    __syncthreads();

    if (t < 128) {
        const int row = t >> 4, l = t & 15;
        float p = 0.f;
        #pragma unroll
        for (int j = 0; j < 8; j++) p += As[row][l*8 + j] * sS[l*8 + j];
        p = red16(p);
        if (l == 0) t2S[row] = p;
    }

    const int c = t & 127, i0 = t >> 7;
    const int lrow = t >> 5, lcol = (t & 31) * 4;

    {
        float acc[4] = {0.f, 0.f, 0.f, 0.f};
        const float* Gb = g_G + b*C*C;
        #pragma unroll
        for (int st = 0; st < 2; st++) {
            __syncthreads();
            #pragma unroll
            for (int it = 0; it < 8; it++) {
                const int row = lrow + it*8;
                const float4 v = __ldcg((const float4*)&Gb[(st*64 + row)*C + lcol]);
                *(float4*)&stg[row][lcol] = v;
            }
            __syncthreads();
            #pragma unroll 16
            for (int jj = 0; jj < 64; jj++) {
                const float gv = stg[jj][c];
                #pragma unroll
                for (int q = 0; q < 4; q++)
                    acc[q] += As[i0 + 2*q][st*64 + jj] * gv;
            }
        }
        #pragma unroll
        for (int q = 0; q < 4; q++) Ps[i0 + 2*q][c] = acc[q];
    }

    {
        float acc[4] = {0.f, 0.f, 0.f, 0.f};
        float t1 = 0.f;
        #pragma unroll
        for (int st = 0; st < 2; st++) {
            __syncthreads();
            #pragma unroll
            for (int it = 0; it < 8; it++) {
                const int row = lrow + it*8;
                const float4 v = __ldg((const float4*)&g_Bm[(st*64 + row)*C + lcol]);
                *(float4*)&stg[row][lcol] = v;
            }
            __syncthreads();
            #pragma unroll 16
            for (int jj = 0; jj < 64; jj++) {
                const float bm = stg[jj][c];
                t1 += bm * sS[st*64 + jj];
                #pragma unroll
                for (int q = 0; q < 4; q++)
                    acc[q] += Ps[i0 + 2*q][st*64 + jj] * bm;
            }
        }
        const float w2c = __ldg(&g_w2[c]);
        #pragma unroll
        for (int q = 0; q < 4; q++) {
            const int i = i0 + 2*q;
            const int r = r0 + i;
            const float ur = __ldg(&g_u[r]);
            const float val = invN*acc[q] + invN*ur*t1 + (invN*t2S[i] + ur)*w2c;
            g_Ebf[b*C*C + r*C + c] = __float2bfloat16(val);   // E', no identity
        }
    }
    if (t < 8) {
        float pk = 0.f;
        #pragma unroll 16
        for (int j = 0; j < C; j++) pk += Ps[t][j] * kqS[j];
        const int r = r0 + t;
        const float ur = __ldg(&g_u[r]);
        g_e0[b*C + r] = invN*pk + invN*ur*g_skq[b]
                      + (invN*t2S[t] + ur)*g_beta + __ldg(&b_o[r]);
    }
}

// ---------------- k_out: out = X + E' X + e0 via mma.sync (100 x 256) --------
// X tile -> bf16 smem [c][n] pitch 136; B frags via ldmatrix.trans;
// E' A-frags loaded directly from global bf16 (L2-hot, 32KB/batch).
// Epilogue adds fp32 X residual + e0 (bf16 only touches the ~2e-4 term).
__global__ void __launch_bounds__(256) k_out(const float* __restrict__ x,
                                             float* __restrict__ out) {
    __shared__ __align__(16) __nv_bfloat16 xs[128][136];

    const int b = blockIdx.x / NT, tile = blockIdx.x % NT;
    const int nb = tile * 128;
    const float* xb = x + b*C*NPIX;
    float* ob = out + b*C*NPIX;
    const __nv_bfloat16* Eb = g_Ebf + b*C*C;
    const int t = threadIdx.x, wid = t >> 5, lane = t & 31;

    #pragma unroll
    for (int it = 0; it < 16; it++) {
        const int e = t + it*256;
        const int row = e >> 5, q = e & 31;
        const float4 v = __ldg((const float4*)&xb[row*NPIX + nb + q*4]);
        uint32_t p0, p1;
        asm("cvt.rn.bf16x2.f32 %0, %1, %2;" : "=r"(p0) : "f"(v.y), "f"(v.x));
        asm("cvt.rn.bf16x2.f32 %0, %1, %2;" : "=r"(p1) : "f"(v.w), "f"(v.z));
        *(uint2*)&xs[row][q*4] = make_uint2(p0, p1);
    }
    __syncthreads();

    const int m0 = (wid & 1) * 64;
    const int n0 = (wid >> 1) * 32;
    const uint32_t base = smem_u32(xs);
    const int gr = lane >> 2, ci = lane & 3;

    float acc[4][4][4];
    #pragma unroll
    for (int i = 0; i < 4; i++)
        #pragma unroll
        for (int j = 0; j < 4; j++)
            #pragma unroll
            for (int q = 0; q < 4; q++) acc[i][j][q] = 0.f;

    #pragma unroll
    for (int ks = 0; ks < 8; ks++) {
        const int k0 = ks * 16;
        uint32_t af[4][4], bf[4][2];
        #pragma unroll
        for (int i = 0; i < 4; i++) {
            const __nv_bfloat16* ep = Eb + (m0 + 16*i + gr)*C + k0 + 2*ci;
            af[i][0] = *(const uint32_t*)ep;
            af[i][1] = *(const uint32_t*)(ep + 8*C);
            af[i][2] = *(const uint32_t*)(ep + 8);
            af[i][3] = *(const uint32_t*)(ep + 8*C + 8);
        }
        #pragma unroll
        for (int j = 0; j < 4; j++)
            ldsm_x2_trans(bf[j], base + ((k0 + (lane & 15))*136 + n0 + 8*j)*2);
        #pragma unroll
        for (int i = 0; i < 4; i++)
            #pragma unroll
            for (int j = 0; j < 4; j++)
                mma16816(acc[i][j], af[i], bf[j]);
    }

    #pragma unroll
    for (int i = 0; i < 4; i++) {
        const int row = m0 + 16*i + gr;
        const float e0a = __ldg(&g_e0[b*C + row]);
        const float e0b = __ldg(&g_e0[b*C + row + 8]);
        #pragma unroll
        for (int j = 0; j < 4; j++) {
            const int col = n0 + 8*j + 2*ci;
            const float2 xa = *(const float2*)&xb[row*NPIX + nb + col];
            const float2 xc = *(const float2*)&xb[(row + 8)*NPIX + nb + col];
            *(float2*)&ob[row*NPIX + nb + col] =
                make_float2(acc[i][j][0] + xa.x + e0a, acc[i][j][1] + xa.y + e0a);
            *(float2*)&ob[(row + 8)*NPIX + nb + col] =
                make_float2(acc[i][j][2] + xc.x + e0b, acc[i][j][3] + xc.y + e0b);
        }
    }
}

// ---------------- host launcher ----------------------------------------------
extern "C" void kernel_launch(void* const* d_in, const int* in_sizes, int n_in,
                              void* d_out, int out_size) {
    (void)in_sizes; (void)n_in; (void)out_size;
    const float* x   = (const float*)d_in[0];
    const float* w_q = (const float*)d_in[1];
    const float* b_q = (const float*)d_in[2];
    const float* w_k = (const float*)d_in[3];
    const float* b_k = (const float*)d_in[4];
    const float* w_v = (const float*)d_in[5];
    const float* b_v = (const float*)d_in[6];
    const float* w_o = (const float*)d_in[7];
    const float* b_o = (const float*)d_in[8];
    float* out = (float*)d_out;

    k_prep<<<32, 256>>>(w_q, b_q, w_k, b_k, w_v, b_v, w_o, b_o);
    k_gram<<<BATCH*NT, 256>>>(x);
    k_pe<<<BATCH*16, 256>>>(b_o);
    k_out<<<BATCH*NT, 256>>>(x, out);
}

// round 11
// speedup vs baseline: 2.4965x; 1.2215x over previous
#include <cuda_runtime.h>
#include <cuda_bf16.h>
#include <cstdint>

// NonLocalModule (no softmax) collapsed via associativity, fully fused:
//   out = X + E' X + e0, G = X X^T (128x128/batch), A = Wo Wv, Bm = Wk^T Wq,
//   E' = (1/N)[A G Bm + (A s) w2^T + u (Bm^T s)^T] + u w2^T
//   e0 = (1/N)[(A G) kq + (A s) beta + u (s.kq)] + u beta + bo
// Single persistent kernel, 132 blocks (all co-resident on 148 SMs):
//   blocks 0..99  : phase A gram (bf16 mma.sync, X tile stays in smem)
//                   phase C out  (reuses warm X tile; E' staged to smem)
//   blocks 100..131: phase A prep (concurrent with gram), phase B pe.
// Grid barriers: monotonic counters (no reset across graph replays).

#define C     128
#define NPIX  6400
#define BATCH 2
#define NT    50
#define NTILE 100
#define NPE   32
#define NTOT  132

// ---------------- device scratch (no allocations allowed) --------------------
__device__ float g_Gp[BATCH*NT*C*C];
__device__ float g_sp[BATCH*NT*C];
__device__ float g_G [BATCH*C*C];
__device__ float g_s [BATCH*C];
__device__ float g_A [C*C];
__device__ float g_Bm[C*C];
__device__ __nv_bfloat16 g_Ebf[BATCH*C*C];   // E' bf16, row-major [r][c]
__device__ float g_e0[BATCH*C];
__device__ float g_u [C];
__device__ float g_w2[C];
__device__ float g_kq[C];
__device__ float g_skq[BATCH];
__device__ float g_beta;
__device__ unsigned g_bar1, g_bar2;          // monotonic grid barriers
__device__ unsigned g_cnt[BATCH];            // monotonic per-batch pe barrier

// ---------------- helpers -----------------------------------------------------
__device__ __forceinline__ float red16(float p) {
    p += __shfl_down_sync(0xffffffffu, p, 8, 16);
    p += __shfl_down_sync(0xffffffffu, p, 4, 16);
    p += __shfl_down_sync(0xffffffffu, p, 2, 16);
    p += __shfl_down_sync(0xffffffffu, p, 1, 16);
    return p;
}
__device__ __forceinline__ uint32_t smem_u32(const void* p) {
    uint32_t a;
    asm("{ .reg .u64 t; cvta.to.shared.u64 t, %1; cvt.u32.u64 %0, t; }"
        : "=r"(a) : "l"(p));
    return a;
}
// monotonic grid barrier: safe across graph replays, no counter reset
__device__ __forceinline__ void gbar(unsigned* ctr, unsigned tot) {
    __syncthreads();
    if (threadIdx.x == 0) {
        __threadfence();
        const unsigned old = atomicAdd(ctr, 1u);
        const unsigned tgt = (old / tot + 1u) * tot;
        volatile unsigned* p = ctr;
        while (*p < tgt) { __nanosleep(64); }
    }
    __syncthreads();
    __threadfence();
}

__device__ __forceinline__ void ldsm_x4(uint32_t* r, uint32_t addr) {
    asm volatile("ldmatrix.sync.aligned.m8n8.x4.shared.b16 {%0,%1,%2,%3}, [%4];"
        : "=r"(r[0]), "=r"(r[1]), "=r"(r[2]), "=r"(r[3]) : "r"(addr));
}
__device__ __forceinline__ void ldsm_x2(uint32_t* r, uint32_t addr) {
    asm volatile("ldmatrix.sync.aligned.m8n8.x2.shared.b16 {%0,%1}, [%2];"
        : "=r"(r[0]), "=r"(r[1]) : "r"(addr));
}
__device__ __forceinline__ void ldsm_x2_trans(uint32_t* r, uint32_t addr) {
    asm volatile("ldmatrix.sync.aligned.m8n8.x2.trans.shared.b16 {%0,%1}, [%2];"
        : "=r"(r[0]), "=r"(r[1]) : "r"(addr));
}
__device__ __forceinline__ void mma16816(float* d, const uint32_t* a,
                                         const uint32_t* b) {
    asm volatile(
        "mma.sync.aligned.m16n8k16.row.col.f32.bf16.bf16.f32 "
        "{%0,%1,%2,%3}, {%4,%5,%6,%7}, {%8,%9}, {%0,%1,%2,%3};"
        : "+f"(d[0]), "+f"(d[1]), "+f"(d[2]), "+f"(d[3])
        : "r"(a[0]), "r"(a[1]), "r"(a[2]), "r"(a[3]), "r"(b[0]), "r"(b[1]));
}

// ---------------- fused kernel ------------------------------------------------
__global__ void __launch_bounds__(256) k_fused(
        const float* __restrict__ x,
        const float* __restrict__ w_q, const float* __restrict__ b_q,
        const float* __restrict__ w_k, const float* __restrict__ b_k,
        const float* __restrict__ w_v, const float* __restrict__ b_v,
        const float* __restrict__ w_o, const float* __restrict__ b_o,
        float* __restrict__ out) {
    extern __shared__ __align__(16) char dyn[];
    const int bid = blockIdx.x;
    const int t = threadIdx.x, wid = t >> 5, lane = t & 31;
    const float invN = 1.0f / (float)NPIX;

    if (bid < NTILE) {
        // =================== TILE BLOCK ======================================
        __nv_bfloat16 (*xs)[136] = (__nv_bfloat16(*)[136])dyn;           // 34816
        __nv_bfloat16 (*es)[136] = (__nv_bfloat16(*)[136])(dyn + 34816); // 34816

        const int b = bid / NT, tile = bid % NT;
        const int nb = tile * 128;
        const float* xb = x + b*C*NPIX;

        // ---- phase A: gram -------------------------------------------------
        #pragma unroll
        for (int it = 0; it < 16; it++) {
            const int e = t + it*256;
            const int row = e >> 5, q = e & 31;
            const float4 v = __ldg((const float4*)&xb[row*NPIX + nb + q*4]);
            uint32_t p0, p1;
            asm("cvt.rn.bf16x2.f32 %0, %1, %2;" : "=r"(p0) : "f"(v.y), "f"(v.x));
            asm("cvt.rn.bf16x2.f32 %0, %1, %2;" : "=r"(p1) : "f"(v.w), "f"(v.z));
            *(uint2*)&xs[row][q*4] = make_uint2(p0, p1);
        }
        {   // s row sums in fp32 (L1-hot re-read)
            const int c = t >> 1, half = (t & 1) * 64;
            float sv = 0.f;
            #pragma unroll
            for (int i = 0; i < 16; i++) {
                const float4 v = __ldg((const float4*)&xb[c*NPIX + nb + half + i*4]);
                sv += (v.x + v.y) + (v.z + v.w);
            }
            sv += __shfl_xor_sync(0xffffffffu, sv, 1);
            if (!(t & 1)) g_sp[(b*NT + tile)*C + c] = sv;
        }
        __syncthreads();

        const int m0 = (wid & 1) * 64;
        const int n0 = (wid >> 1) * 32;
        const uint32_t xbase = smem_u32(xs);
        const int arow = lane & 15, acol8 = (lane >> 4) << 3;
        const int brow = lane & 7,  bcol8 = ((lane >> 3) & 1) << 3;
        const int gr = lane >> 2, ci = lane & 3;

        {
            float acc[4][4][4];
            #pragma unroll
            for (int i = 0; i < 4; i++)
                #pragma unroll
                for (int j = 0; j < 4; j++)
                    #pragma unroll
                    for (int q = 0; q < 4; q++) acc[i][j][q] = 0.f;

            #pragma unroll
            for (int ks = 0; ks < 8; ks++) {
                const int k0 = ks * 16;
                uint32_t af[4][4], bf[4][2];
                #pragma unroll
                for (int i = 0; i < 4; i++)
                    ldsm_x4(af[i], xbase + ((m0 + 16*i + arow)*136 + k0 + acol8)*2);
                #pragma unroll
                for (int j = 0; j < 4; j++)
                    ldsm_x2(bf[j], xbase + ((n0 + 8*j + brow)*136 + k0 + bcol8)*2);
                #pragma unroll
                for (int i = 0; i < 4; i++)
                    #pragma unroll
                    for (int j = 0; j < 4; j++)
                        mma16816(acc[i][j], af[i], bf[j]);
            }
            float* Gp = g_Gp + (size_t)(b*NT + tile)*C*C;
            #pragma unroll
            for (int i = 0; i < 4; i++)
                #pragma unroll
                for (int j = 0; j < 4; j++) {
                    const int row = m0 + 16*i + gr;
                    const int col = n0 + 8*j + 2*ci;
                    *(float2*)&Gp[row*C + col]       = make_float2(acc[i][j][0], acc[i][j][1]);
                    *(float2*)&Gp[(row + 8)*C + col] = make_float2(acc[i][j][2], acc[i][j][3]);
                }
        }

        gbar(&g_bar1, NTOT);      // gram+prep done
        gbar(&g_bar2, NTOT);      // wait for pe (E', e0 ready)

        // ---- phase C: out = X + E' X + e0 (X tile still warm in smem) ------
        const __nv_bfloat16* Eb = g_Ebf + b*C*C;
        #pragma unroll
        for (int it = 0; it < 8; it++) {       // stage E' (32 KB) into es
            const int idx = t + it*256;
            const int row = idx >> 4, seg = idx & 15;
            *(uint4*)&es[row][seg*8] = *(const uint4*)&Eb[row*C + seg*8];
        }
        __syncthreads();
        const uint32_t ebase = smem_u32(es);

        float acc[4][4][4];
        #pragma unroll
        for (int i = 0; i < 4; i++)
            #pragma unroll
            for (int j = 0; j < 4; j++)
                #pragma unroll
                for (int q = 0; q < 4; q++) acc[i][j][q] = 0.f;

        #pragma unroll
        for (int ks = 0; ks < 8; ks++) {
            const int k0 = ks * 16;
            uint32_t af[4][4], bf[4][2];
            #pragma unroll
            for (int i = 0; i < 4; i++)
                ldsm_x4(af[i], ebase + ((m0 + 16*i + arow)*136 + k0 + acol8)*2);
            #pragma unroll
            for (int j = 0; j < 4; j++)
                ldsm_x2_trans(bf[j], xbase + ((k0 + (lane & 15))*136 + n0 + 8*j)*2);
            #pragma unroll
            for (int i = 0; i < 4; i++)
                #pragma unroll
                for (int j = 0; j < 4; j++)
                    mma16816(acc[i][j], af[i], bf[j]);
        }

        float* ob = out + b*C*NPIX;
        #pragma unroll
        for (int i = 0; i < 4; i++) {
            const int row = m0 + 16*i + gr;
            const float e0a = g_e0[b*C + row];
            const float e0b = g_e0[b*C + row + 8];
            #pragma unroll
            for (int j = 0; j < 4; j++) {
                const int col = n0 + 8*j + 2*ci;
                const float2 xa = *(const float2*)&xb[row*NPIX + nb + col];
                const float2 xc = *(const float2*)&xb[(row + 8)*NPIX + nb + col];
                *(float2*)&ob[row*NPIX + nb + col] =
                    make_float2(acc[i][j][0] + xa.x + e0a, acc[i][j][1] + xa.y + e0a);
                *(float2*)&ob[(row + 8)*NPIX + nb + col] =
                    make_float2(acc[i][j][2] + xc.x + e0b, acc[i][j][3] + xc.y + e0b);
            }
        }
    } else {
        // =================== PE BLOCK ========================================
        const int bid2 = bid - NTILE;          // 0..31
        float (*stg)[132] = (float(*)[132])dyn;                 // 33792
        float (*lhsS)[C]  = (float(*)[C])(dyn + 34816);         // 4096
        float (*Ps)[132]  = (float(*)[132])(dyn + 38912);       // 4224
        float* sS   = (float*)(dyn + 43152);
        float* kqS  = (float*)(dyn + 43664);
        float* redS = (float*)(dyn + 44176);
        float* t2S  = (float*)(dyn + 44688);
        float* bkS  = (float*)(dyn + 44752);

        // ---- phase A: prep (concurrent with gram) --------------------------
        {
            const bool isA = bid2 < 16;
            const int r0 = (bid2 & 15) * 8;

            if (t < C) bkS[t] = __ldg(&b_k[t]);
            for (int e = t; e < 8*C; e += 256) {
                const int i = e >> 7, j = e & 127;
                lhsS[i][j] = isA ? __ldg(&w_o[(r0 + i)*C + j])
                                 : __ldg(&w_k[j*C + (r0 + i)]);
            }
            __syncthreads();

            if (t < 128) {     // u[r] (A blocks) / kq[r] (Bm blocks)
                const int row = t >> 4, l = t & 15;
                const float* bv = isA ? b_v : b_q;
                float p = 0.f;
                #pragma unroll
                for (int j = 0; j < 8; j++)
                    p += lhsS[row][l*8 + j] * __ldg(&bv[l*8 + j]);
                p = red16(p);
                if (l == 0) (isA ? g_u : g_kq)[r0 + row] = p;
            }
            if (bid2 == 16 && t >= 128 && t < 160) {     // beta = bk.bq
                const int l = t - 128;
                float p = 0.f;
                #pragma unroll
                for (int j = 0; j < 4; j++) p += bkS[l*4 + j] * __ldg(&b_q[l*4 + j]);
                #pragma unroll
                for (int off = 16; off > 0; off >>= 1)
                    p += __shfl_down_sync(0xffffffffu, p, off);
                if (l == 0) g_beta = p;
            }

            const float* rhs = isA ? w_v : w_q;
            float* dst = isA ? g_A : g_Bm;
            const int c = t & 127, i0 = t >> 7;
            const int lrow = t >> 5, lcol = (t & 31) * 4;
            float acc[4] = {0.f, 0.f, 0.f, 0.f};
            float w2acc = 0.f;

            #pragma unroll
            for (int st = 0; st < 2; st++) {
                __syncthreads();
                #pragma unroll
                for (int it = 0; it < 8; it++) {
                    const int row = lrow + it*8;
                    const float4 v = *(const float4*)&rhs[(st*64 + row)*C + lcol];
                    *(float4*)&stg[row][lcol] = v;
                }
                __syncthreads();
                #pragma unroll 16
                for (int jj = 0; jj < 64; jj++) {
                    const float rv = stg[jj][c];
                    w2acc += rv * bkS[st*64 + jj];
                    #pragma unroll
                    for (int q = 0; q < 4; q++)
                        acc[q] += lhsS[i0 + 2*q][st*64 + jj] * rv;
                }
            }
            #pragma unroll
            for (int q = 0; q < 4; q++) dst[(r0 + i0 + 2*q)*C + c] = acc[q];
            if (bid2 == 16 && i0 == 0) g_w2[c] = w2acc;
        }

        gbar(&g_bar1, NTOT);      // gram partials now visible

        // ---- phase B: pe ---------------------------------------------------
        {
            const int b  = bid2 >> 4;
            const int rg = bid2 & 15;
            const int r0 = rg * 8;

            {   // reduce assigned G rows (fixed order -> deterministic)
                const float* base = g_Gp + (size_t)b*NT*C*C + r0*C;
                #pragma unroll
                for (int k = 0; k < 4; k++) {
                    const int e = t + 256*k;
                    float a = 0.f;
                    #pragma unroll 10
                    for (int ch = 0; ch < NT; ch++) a += base[(size_t)ch*C*C + e];
                    g_G[b*C*C + r0*C + e] = a;
                }
                if (rg == 0) {
                    float sv = 0.f;
                    if (t < C) {
                        const float* sb = g_sp + b*NT*C + t;
                        #pragma unroll 10
                        for (int ch = 0; ch < NT; ch++) sv += sb[ch*C];
                        g_s[b*C + t] = sv;
                        redS[t] = sv * __ldg(&g_kq[t]);
                    }
                    __syncthreads();
                    if (t < 64) redS[t] += redS[t + 64];
                    __syncthreads();
                    if (t < 32) {
                        float v = redS[t] + redS[t + 32];
                        #pragma unroll
                        for (int off = 16; off > 0; off >>= 1)
                            v += __shfl_down_sync(0xffffffffu, v, off);
                        if (t == 0) g_skq[b] = v;
                    }
                }
            }
            gbar(&g_cnt[b], 16);   // per-batch: full G visible

            if (t < C) { sS[t] = __ldcg(&g_s[b*C + t]); kqS[t] = __ldg(&g_kq[t]); }
            for (int e = t; e < 8*C; e += 256)
                lhsS[e >> 7][e & 127] = __ldg(&g_A[(r0 + (e >> 7))*C + (e & 127)]);
            __syncthreads();

            if (t < 128) {         // t2[r] = A_rows . s
                const int row = t >> 4, l = t & 15;
                float p = 0.f;
                #pragma unroll
                for (int j = 0; j < 8; j++) p += lhsS[row][l*8 + j] * sS[l*8 + j];
                p = red16(p);
                if (l == 0) t2S[row] = p;
            }

            const int c = t & 127, i0 = t >> 7;
            const int lrow = t >> 5, lcol = (t & 31) * 4;

            {   // P = A_rows @ G
                float acc[4] = {0.f, 0.f, 0.f, 0.f};
                const float* Gb = g_G + b*C*C;
                #pragma unroll
                for (int st = 0; st < 2; st++) {
                    __syncthreads();
                    #pragma unroll
                    for (int it = 0; it < 8; it++) {
                        const int row = lrow + it*8;
                        const float4 v = __ldcg((const float4*)&Gb[(st*64 + row)*C + lcol]);
                        *(float4*)&stg[row][lcol] = v;
                    }
                    __syncthreads();
                    #pragma unroll 16
                    for (int jj = 0; jj < 64; jj++) {
                        const float gv = stg[jj][c];
                        #pragma unroll
                        for (int q = 0; q < 4; q++)
                            acc[q] += lhsS[i0 + 2*q][st*64 + jj] * gv;
                    }
                }
                #pragma unroll
                for (int q = 0; q < 4; q++) Ps[i0 + 2*q][c] = acc[q];
            }

            {   // E' rows = invN * Pr @ Bm + rank-1 terms -> bf16
                float acc[4] = {0.f, 0.f, 0.f, 0.f};
                float t1 = 0.f;
                #pragma unroll
                for (int st = 0; st < 2; st++) {
                    __syncthreads();
                    #pragma unroll
                    for (int it = 0; it < 8; it++) {
                        const int row = lrow + it*8;
                        const float4 v = __ldg((const float4*)&g_Bm[(st*64 + row)*C + lcol]);
                        *(float4*)&stg[row][lcol] = v;
                    }
                    __syncthreads();
                    #pragma unroll 16
                    for (int jj = 0; jj < 64; jj++) {
                        const float bm = stg[jj][c];
                        t1 += bm * sS[st*64 + jj];
                        #pragma unroll
                        for (int q = 0; q < 4; q++)
                            acc[q] += Ps[i0 + 2*q][st*64 + jj] * bm;
                    }
                }
                const float w2c = __ldg(&g_w2[c]);
                #pragma unroll
                for (int q = 0; q < 4; q++) {
                    const int i = i0 + 2*q;
                    const int r = r0 + i;
                    const float ur = __ldg(&g_u[r]);
                    const float val = invN*acc[q] + invN*ur*t1 + (invN*t2S[i] + ur)*w2c;
                    g_Ebf[b*C*C + r*C + c] = __float2bfloat16(val);
                }
            }
            if (t < 8) {
                float pk = 0.f;
                #pragma unroll 16
                for (int j = 0; j < C; j++) pk += Ps[t][j] * kqS[j];
                const int r = r0 + t;
                const float ur = __ldg(&g_u[r]);
                g_e0[b*C + r] = invN*pk + invN*ur*g_skq[b]
                              + (invN*t2S[t] + ur)*g_beta + __ldg(&b_o[r]);
            }
        }

        gbar(&g_bar2, NTOT);      // release tile blocks into phase C
    }
}

// ---------------- host launcher ----------------------------------------------
#define DYN_SMEM 69632

extern "C" void kernel_launch(void* const* d_in, const int* in_sizes, int n_in,
                              void* d_out, int out_size) {
    (void)in_sizes; (void)n_in; (void)out_size;
    const float* x   = (const float*)d_in[0];
    const float* w_q = (const float*)d_in[1];
    const float* b_q = (const float*)d_in[2];
    const float* w_k = (const float*)d_in[3];
    const float* b_k = (const float*)d_in[4];
    const float* w_v = (const float*)d_in[5];
    const float* b_v = (const float*)d_in[6];
    const float* w_o = (const float*)d_in[7];
    const float* b_o = (const float*)d_in[8];
    float* out = (float*)d_out;

    cudaFuncSetAttribute(k_fused, cudaFuncAttributeMaxDynamicSharedMemorySize,
                         DYN_SMEM);
    k_fused<<<NTOT, 256, DYN_SMEM>>>(x, w_q, b_q, w_k, b_k, w_v, b_v,
                                     w_o, b_o, out);
}

// round 12
// speedup vs baseline: 3.1996x; 1.2816x over previous
#include <cuda_runtime.h>
#include <cuda_bf16.h>
#include <cstdint>

// NonLocalModule (no softmax) collapsed via associativity, fully fused:
//   out = X + E' X + e0, G = X X^T (128x128/batch), A = Wo Wv, Bm = Wk^T Wq,
//   E' = (1/N)[A G Bm + (A s) w2^T + u (Bm^T s)^T] + u w2^T
//   e0 = (1/N)[(A G) kq + (A s) beta + u (s.kq)] + u beta + bo
// Single persistent kernel, 132 blocks (all co-resident on 148 SMs):
//   phase A: blocks 0..99 gram (bf16 mma.sync, X tile stays in smem);
//            blocks 100..131 prep (A, Bm, bias vectors) -- concurrent.
//   bar1
//   phase R: blocks 0..127 reduce G partials (256 elems each, MLP~50);
//            blocks 128..129 reduce s + skq.  pe blocks prefetch A rows.
//   bar2
//   phase B: pe blocks compute P = A G, E' (bf16), e0.
//   bar3
//   phase C: tile blocks out = X + E' X + e0 (reuse warm X tile).
// Grid barriers: monotonic counters (safe across graph replays).

#define C     128
#define NPIX  6400
#define BATCH 2
#define NT    50
#define NTILE 100
#define NTOT  132

// ---------------- device scratch (no allocations allowed) --------------------
__device__ float g_Gp[BATCH*NT*C*C];
__device__ float g_sp[BATCH*NT*C];
__device__ float g_G [BATCH*C*C];
__device__ float g_s [BATCH*C];
__device__ float g_A [C*C];
__device__ float g_Bm[C*C];
__device__ __nv_bfloat16 g_Ebf[BATCH*C*C];   // E' bf16, row-major [r][c]
__device__ float g_e0[BATCH*C];
__device__ float g_u [C];
__device__ float g_w2[C];
__device__ float g_kq[C];
__device__ float g_skq[BATCH];
__device__ float g_beta;
__device__ unsigned g_bar1, g_bar2, g_bar3;  // monotonic grid barriers

// ---------------- helpers -----------------------------------------------------
__device__ __forceinline__ float red16(float p) {
    p += __shfl_down_sync(0xffffffffu, p, 8, 16);
    p += __shfl_down_sync(0xffffffffu, p, 4, 16);
    p += __shfl_down_sync(0xffffffffu, p, 2, 16);
    p += __shfl_down_sync(0xffffffffu, p, 1, 16);
    return p;
}
__device__ __forceinline__ uint32_t smem_u32(const void* p) {
    uint32_t a;
    asm("{ .reg .u64 t; cvta.to.shared.u64 t, %1; cvt.u32.u64 %0, t; }"
        : "=r"(a) : "l"(p));
    return a;
}
// monotonic grid barrier: safe across graph replays, no counter reset
__device__ __forceinline__ void gbar(unsigned* ctr, unsigned tot) {
    __syncthreads();
    if (threadIdx.x == 0) {
        __threadfence();
        const unsigned old = atomicAdd(ctr, 1u);
        const unsigned tgt = (old / tot + 1u) * tot;
        volatile unsigned* p = ctr;
        while (*p < tgt) { __nanosleep(64); }
    }
    __syncthreads();
    __threadfence();
}

__device__ __forceinline__ void ldsm_x4(uint32_t* r, uint32_t addr) {
    asm volatile("ldmatrix.sync.aligned.m8n8.x4.shared.b16 {%0,%1,%2,%3}, [%4];"
        : "=r"(r[0]), "=r"(r[1]), "=r"(r[2]), "=r"(r[3]) : "r"(addr));
}
__device__ __forceinline__ void ldsm_x2(uint32_t* r, uint32_t addr) {
    asm volatile("ldmatrix.sync.aligned.m8n8.x2.shared.b16 {%0,%1}, [%2];"
        : "=r"(r[0]), "=r"(r[1]) : "r"(addr));
}
__device__ __forceinline__ void ldsm_x2_trans(uint32_t* r, uint32_t addr) {
    asm volatile("ldmatrix.sync.aligned.m8n8.x2.trans.shared.b16 {%0,%1}, [%2];"
        : "=r"(r[0]), "=r"(r[1]) : "r"(addr));
}
__device__ __forceinline__ void mma16816(float* d, const uint32_t* a,
                                         const uint32_t* b) {
    asm volatile(
        "mma.sync.aligned.m16n8k16.row.col.f32.bf16.bf16.f32 "
        "{%0,%1,%2,%3}, {%4,%5,%6,%7}, {%8,%9}, {%0,%1,%2,%3};"
        : "+f"(d[0]), "+f"(d[1]), "+f"(d[2]), "+f"(d[3])
        : "r"(a[0]), "r"(a[1]), "r"(a[2]), "r"(a[3]), "r"(b[0]), "r"(b[1]));
}

// ---------------- fused kernel ------------------------------------------------
__global__ void __launch_bounds__(256) k_fused(
        const float* __restrict__ x,
        const float* __restrict__ w_q, const float* __restrict__ b_q,
        const float* __restrict__ w_k, const float* __restrict__ b_k,
        const float* __restrict__ w_v, const float* __restrict__ b_v,
        const float* __restrict__ w_o, const float* __restrict__ b_o,
        float* __restrict__ out) {
    extern __shared__ __align__(16) char dyn[];
    const int bid = blockIdx.x;
    const int t = threadIdx.x, wid = t >> 5, lane = t & 31;
    const float invN = 1.0f / (float)NPIX;

    // smem views (tile blocks use xs/es; pe blocks use the rest)
    __nv_bfloat16 (*xs)[136] = (__nv_bfloat16(*)[136])dyn;           // 34816 B
    __nv_bfloat16 (*es)[136] = (__nv_bfloat16(*)[136])(dyn + 34816); // 34816 B
    float (*stg)[132] = (float(*)[132])dyn;                 // 33792 B
    float (*lhsS)[C]  = (float(*)[C])(dyn + 34816);         // 4096 B
    float (*Ps)[132]  = (float(*)[132])(dyn + 38912);       // 4224 B
    float* sS   = (float*)(dyn + 43152);
    float* kqS  = (float*)(dyn + 43664);
    float* redS = (float*)(dyn + 44176);
    float* t2S  = (float*)(dyn + 44688);
    float* bkS  = (float*)(dyn + 44752);

    // mma lane geometry (shared by gram and out phases)
    const int m0 = (wid & 1) * 64;
    const int n0 = (wid >> 1) * 32;
    const int arow = lane & 15, acol8 = (lane >> 4) << 3;
    const int brow = lane & 7,  bcol8 = ((lane >> 3) & 1) << 3;
    const int gr = lane >> 2, ci = lane & 3;

    // =================== phase A =============================================
    if (bid < NTILE) {
        // ---- gram: partial G = X X^T, X tile -> bf16 smem (stays warm) -----
        const int b = bid / NT, tile = bid % NT;
        const int nb = tile * 128;
        const float* xb = x + b*C*NPIX;

        #pragma unroll
        for (int it = 0; it < 16; it++) {
            const int e = t + it*256;
            const int row = e >> 5, q = e & 31;
            const float4 v = __ldg((const float4*)&xb[row*NPIX + nb + q*4]);
            uint32_t p0, p1;
            asm("cvt.rn.bf16x2.f32 %0, %1, %2;" : "=r"(p0) : "f"(v.y), "f"(v.x));
            asm("cvt.rn.bf16x2.f32 %0, %1, %2;" : "=r"(p1) : "f"(v.w), "f"(v.z));
            *(uint2*)&xs[row][q*4] = make_uint2(p0, p1);
        }
        {   // s row sums in fp32 (L1-hot re-read)
            const int c = t >> 1, half = (t & 1) * 64;
            float sv = 0.f;
            #pragma unroll
            for (int i = 0; i < 16; i++) {
                const float4 v = __ldg((const float4*)&xb[c*NPIX + nb + half + i*4]);
                sv += (v.x + v.y) + (v.z + v.w);
            }
            sv += __shfl_xor_sync(0xffffffffu, sv, 1);
            if (!(t & 1)) g_sp[(b*NT + tile)*C + c] = sv;
        }
        __syncthreads();

        const uint32_t xbase = smem_u32(xs);
        float acc[4][4][4];
        #pragma unroll
        for (int i = 0; i < 4; i++)
            #pragma unroll
            for (int j = 0; j < 4; j++)
                #pragma unroll
                for (int q = 0; q < 4; q++) acc[i][j][q] = 0.f;

        #pragma unroll
        for (int ks = 0; ks < 8; ks++) {
            const int k0 = ks * 16;
            uint32_t af[4][4], bf[4][2];
            #pragma unroll
            for (int i = 0; i < 4; i++)
                ldsm_x4(af[i], xbase + ((m0 + 16*i + arow)*136 + k0 + acol8)*2);
            #pragma unroll
            for (int j = 0; j < 4; j++)
                ldsm_x2(bf[j], xbase + ((n0 + 8*j + brow)*136 + k0 + bcol8)*2);
            #pragma unroll
            for (int i = 0; i < 4; i++)
                #pragma unroll
                for (int j = 0; j < 4; j++)
                    mma16816(acc[i][j], af[i], bf[j]);
        }
        float* Gp = g_Gp + (size_t)(b*NT + tile)*C*C;
        #pragma unroll
        for (int i = 0; i < 4; i++)
            #pragma unroll
            for (int j = 0; j < 4; j++) {
                const int row = m0 + 16*i + gr;
                const int col = n0 + 8*j + 2*ci;
                *(float2*)&Gp[row*C + col]       = make_float2(acc[i][j][0], acc[i][j][1]);
                *(float2*)&Gp[(row + 8)*C + col] = make_float2(acc[i][j][2], acc[i][j][3]);
            }
    } else {
        // ---- prep: A = Wo Wv, Bm = Wk^T Wq, bias vectors -------------------
        const int bid2 = bid - NTILE;          // 0..31
        const bool isA = bid2 < 16;
        const int r0 = (bid2 & 15) * 8;

        if (t < C) bkS[t] = __ldg(&b_k[t]);
        for (int e = t; e < 8*C; e += 256) {
            const int i = e >> 7, j = e & 127;
            lhsS[i][j] = isA ? __ldg(&w_o[(r0 + i)*C + j])
                             : __ldg(&w_k[j*C + (r0 + i)]);
        }
        __syncthreads();

        if (t < 128) {     // u[r] (A blocks) / kq[r] (Bm blocks)
            const int row = t >> 4, l = t & 15;
            const float* bv = isA ? b_v : b_q;
            float p = 0.f;
            #pragma unroll
            for (int j = 0; j < 8; j++)
                p += lhsS[row][l*8 + j] * __ldg(&bv[l*8 + j]);
            p = red16(p);
            if (l == 0) (isA ? g_u : g_kq)[r0 + row] = p;
        }
        if (bid2 == 16 && t >= 128 && t < 160) {     // beta = bk.bq
            const int l = t - 128;
            float p = 0.f;
            #pragma unroll
            for (int j = 0; j < 4; j++) p += bkS[l*4 + j] * __ldg(&b_q[l*4 + j]);
            #pragma unroll
            for (int off = 16; off > 0; off >>= 1)
                p += __shfl_down_sync(0xffffffffu, p, off);
            if (l == 0) g_beta = p;
        }

        const float* rhs = isA ? w_v : w_q;
        float* dst = isA ? g_A : g_Bm;
        const int c = t & 127, i0 = t >> 7;
        const int lrow = t >> 5, lcol = (t & 31) * 4;
        float acc[4] = {0.f, 0.f, 0.f, 0.f};
        float w2acc = 0.f;

        #pragma unroll
        for (int st = 0; st < 2; st++) {
            __syncthreads();
            #pragma unroll
            for (int it = 0; it < 8; it++) {
                const int row = lrow + it*8;
                const float4 v = *(const float4*)&rhs[(st*64 + row)*C + lcol];
                *(float4*)&stg[row][lcol] = v;
            }
            __syncthreads();
            #pragma unroll 16
            for (int jj = 0; jj < 64; jj++) {
                const float rv = stg[jj][c];
                w2acc += rv * bkS[st*64 + jj];
                #pragma unroll
                for (int q = 0; q < 4; q++)
                    acc[q] += lhsS[i0 + 2*q][st*64 + jj] * rv;
            }
        }
        #pragma unroll
        for (int q = 0; q < 4; q++) dst[(r0 + i0 + 2*q)*C + c] = acc[q];
        if (bid2 == 16 && i0 == 0) g_w2[c] = w2acc;
    }

    gbar(&g_bar1, NTOT);      // gram partials + A/Bm/bias visible

    // =================== phase R: parallel reductions ========================
    if (bid >= NTILE) {       // pe blocks: prefetch A rows + kq under reduce
        const int bid2 = bid - NTILE;
        const int r0 = (bid2 & 15) * 8;
        for (int e = t; e < 8*C; e += 256)
            lhsS[e >> 7][e & 127] = __ldg(&g_A[(r0 + (e >> 7))*C + (e & 127)]);
        if (t < C) kqS[t] = __ldg(&g_kq[t]);
    }
    if (bid < 128) {
        // 256 elements per block, one per thread, 50-deep unrolled (high MLP)
        const int idx = bid*256 + t;           // 0..32767
        const int b = idx >> 14, e = idx & 16383;
        const float* base = g_Gp + (size_t)b*NT*C*C + e;
        float a = 0.f;
        #pragma unroll
        for (int ch = 0; ch < NT; ch++) a += base[(size_t)ch*C*C];
        g_G[idx] = a;
    } else if (bid < 130) {
        // s reduce + skq for batch b
        const int b = bid - 128;
        float sv = 0.f;
        if (t < C) {
            const float* sb = g_sp + b*NT*C + t;
            #pragma unroll
            for (int ch = 0; ch < NT; ch++) sv += sb[ch*C];
            g_s[b*C + t] = sv;
            redS[t] = sv * kqS[t];
        }
        __syncthreads();
        if (t < 64) redS[t] += redS[t + 64];
        __syncthreads();
        if (t < 32) {
            float v = redS[t] + redS[t + 32];
            #pragma unroll
            for (int off = 16; off > 0; off >>= 1)
                v += __shfl_down_sync(0xffffffffu, v, off);
            if (t == 0) g_skq[b] = v;
        }
    }

    gbar(&g_bar2, NTOT);      // G, s, skq complete

    // =================== phase B: pe blocks compute E', e0 ===================
    if (bid >= NTILE) {
        const int bid2 = bid - NTILE;
        const int b  = bid2 >> 4;
        const int rg = bid2 & 15;
        const int r0 = rg * 8;

        if (t < C) sS[t] = __ldcg(&g_s[b*C + t]);
        __syncthreads();

        if (t < 128) {         // t2[r] = A_rows . s
            const int row = t >> 4, l = t & 15;
            float p = 0.f;
            #pragma unroll
            for (int j = 0; j < 8; j++) p += lhsS[row][l*8 + j] * sS[l*8 + j];
            p = red16(p);
            if (l == 0) t2S[row] = p;
        }

        const int c = t & 127, i0 = t >> 7;
        const int lrow = t >> 5, lcol = (t & 31) * 4;

        {   // P = A_rows @ G
            float acc[4] = {0.f, 0.f, 0.f, 0.f};
            const float* Gb = g_G + b*C*C;
            #pragma unroll
            for (int st = 0; st < 2; st++) {
                __syncthreads();
                #pragma unroll
                for (int it = 0; it < 8; it++) {
                    const int row = lrow + it*8;
                    const float4 v = __ldcg((const float4*)&Gb[(st*64 + row)*C + lcol]);
                    *(float4*)&stg[row][lcol] = v;
                }
                __syncthreads();
                #pragma unroll 16
                for (int jj = 0; jj < 64; jj++) {
                    const float gv = stg[jj][c];
                    #pragma unroll
                    for (int q = 0; q < 4; q++)
                        acc[q] += lhsS[i0 + 2*q][st*64 + jj] * gv;
                }
            }
            #pragma unroll
            for (int q = 0; q < 4; q++) Ps[i0 + 2*q][c] = acc[q];
        }

        {   // E' rows = invN * Pr @ Bm + rank-1 terms -> bf16
            float acc[4] = {0.f, 0.f, 0.f, 0.f};
            float t1 = 0.f;
            #pragma unroll
            for (int st = 0; st < 2; st++) {
                __syncthreads();
                #pragma unroll
                for (int it = 0; it < 8; it++) {
                    const int row = lrow + it*8;
                    const float4 v = __ldg((const float4*)&g_Bm[(st*64 + row)*C + lcol]);
                    *(float4*)&stg[row][lcol] = v;
                }
                __syncthreads();
                #pragma unroll 16
                for (int jj = 0; jj < 64; jj++) {
                    const float bm = stg[jj][c];
                    t1 += bm * sS[st*64 + jj];
                    #pragma unroll
                    for (int q = 0; q < 4; q++)
                        acc[q] += Ps[i0 + 2*q][st*64 + jj] * bm;
                }
            }
            const float w2c = __ldg(&g_w2[c]);
            #pragma unroll
            for (int q = 0; q < 4; q++) {
                const int i = i0 + 2*q;
                const int r = r0 + i;
                const float ur = __ldg(&g_u[r]);
                const float val = invN*acc[q] + invN*ur*t1 + (invN*t2S[i] + ur)*w2c;
                g_Ebf[b*C*C + r*C + c] = __float2bfloat16(val);
            }
        }
        if (t < 8) {
            float pk = 0.f;
            #pragma unroll 16
            for (int j = 0; j < C; j++) pk += Ps[t][j] * kqS[j];
            const int r = r0 + t;
            const float ur = __ldg(&g_u[r]);
            g_e0[b*C + r] = invN*pk + invN*ur*g_skq[b]
                          + (invN*t2S[t] + ur)*g_beta + __ldg(&b_o[r]);
        }
    }

    gbar(&g_bar3, NTOT);      // E', e0 visible

    // =================== phase C: tile blocks out = X + E'X + e0 =============
    if (bid < NTILE) {
        const int b = bid / NT, tile = bid % NT;
        const int nb = tile * 128;
        const float* xb = x + b*C*NPIX;
        const __nv_bfloat16* Eb = g_Ebf + b*C*C;

        #pragma unroll
        for (int it = 0; it < 8; it++) {       // stage E' (32 KB) into es
            const int idx = t + it*256;
            const int row = idx >> 4, seg = idx & 15;
            *(uint4*)&es[row][seg*8] = *(const uint4*)&Eb[row*C + seg*8];
        }
        __syncthreads();
        const uint32_t xbase = smem_u32(xs);
        const uint32_t ebase = smem_u32(es);

        float acc[4][4][4];
        #pragma unroll
        for (int i = 0; i < 4; i++)
            #pragma unroll
            for (int j = 0; j < 4; j++)
                #pragma unroll
                for (int q = 0; q < 4; q++) acc[i][j][q] = 0.f;

        #pragma unroll
        for (int ks = 0; ks < 8; ks++) {
            const int k0 = ks * 16;
            uint32_t af[4][4], bf[4][2];
            #pragma unroll
            for (int i = 0; i < 4; i++)
                ldsm_x4(af[i], ebase + ((m0 + 16*i + arow)*136 + k0 + acol8)*2);
            #pragma unroll
            for (int j = 0; j < 4; j++)
                ldsm_x2_trans(bf[j], xbase + ((k0 + (lane & 15))*136 + n0 + 8*j)*2);
            #pragma unroll
            for (int i = 0; i < 4; i++)
                #pragma unroll
                for (int j = 0; j < 4; j++)
                    mma16816(acc[i][j], af[i], bf[j]);
        }

        float* ob = out + b*C*NPIX;
        #pragma unroll
        for (int i = 0; i < 4; i++) {
            const int row = m0 + 16*i + gr;
            const float e0a = g_e0[b*C + row];
            const float e0b = g_e0[b*C + row + 8];
            #pragma unroll
            for (int j = 0; j < 4; j++) {
                const int col = n0 + 8*j + 2*ci;
                const float2 xa = *(const float2*)&xb[row*NPIX + nb + col];
                const float2 xc = *(const float2*)&xb[(row + 8)*NPIX + nb + col];
                *(float2*)&ob[row*NPIX + nb + col] =
                    make_float2(acc[i][j][0] + xa.x + e0a, acc[i][j][1] + xa.y + e0a);
                *(float2*)&ob[(row + 8)*NPIX + nb + col] =
                    make_float2(acc[i][j][2] + xc.x + e0b, acc[i][j][3] + xc.y + e0b);
            }
        }
    }
}

// ---------------- host launcher ----------------------------------------------
#define DYN_SMEM 69632

extern "C" void kernel_launch(void* const* d_in, const int* in_sizes, int n_in,
                              void* d_out, int out_size) {
    (void)in_sizes; (void)n_in; (void)out_size;
    const float* x   = (const float*)d_in[0];
    const float* w_q = (const float*)d_in[1];
    const float* b_q = (const float*)d_in[2];
    const float* w_k = (const float*)d_in[3];
    const float* b_k = (const float*)d_in[4];
    const float* w_v = (const float*)d_in[5];
    const float* b_v = (const float*)d_in[6];
    const float* w_o = (const float*)d_in[7];
    const float* b_o = (const float*)d_in[8];
    float* out = (float*)d_out;

    cudaFuncSetAttribute(k_fused, cudaFuncAttributeMaxDynamicSharedMemorySize,
                         DYN_SMEM);
    k_fused<<<NTOT, 256, DYN_SMEM>>>(x, w_q, b_q, w_k, b_k, w_v, b_v,
                                     w_o, b_o, out);
}

// round 13
// speedup vs baseline: 3.4688x; 1.0841x over previous
#include <cuda_runtime.h>
#include <cuda_bf16.h>
#include <cstdint>

// NonLocalModule (no softmax) collapsed via associativity, fully fused:
//   out = X + E' X + e0, G = X X^T (128x128/batch), A = Wo Wv, Bm = Wk^T Wq,
//   E' = (1/N)[A G Bm + (A s) w2^T + u (Bm^T s)^T] + u w2^T
//   e0 = (1/N)[(A G) kq + (A s) beta + u (s.kq)] + u beta + bo
// Single persistent kernel, 132 blocks (all co-resident on 148 SMs):
//   phase A: blocks 0..99 gram (bf16 mma.sync; bf16 partials; s folded into
//            the convert loop); blocks 100..131 prep (packed f32x2).
//   bar1
//   phase R: blocks 0..31 reduce bf16 G partials (LDG.64 x50 chains);
//            blocks 128..129 reduce s + skq; pe blocks prefetch A, Bm, kq.
//   bar2
//   phase B: pe blocks: stage G once, P = A G and E' via packed f32x2; e0.
//   bar3
//   phase C: tile blocks out = X + E' X + e0 (reuse warm X tile).

#define C     128
#define NPIX  6400
#define BATCH 2
#define NT    50
#define NTILE 100
#define NTOT  132

// ---------------- device scratch (no allocations allowed) --------------------
__device__ __nv_bfloat16 g_Gpb[BATCH*NT*C*C];  // bf16 gram partials
__device__ float g_sp[BATCH*NT*C];
__device__ float g_G [BATCH*C*C];
__device__ float g_s [BATCH*C];
__device__ float g_A [C*C];
__device__ float g_Bm[C*C];
__device__ __nv_bfloat16 g_Ebf[BATCH*C*C];     // E' bf16, row-major [r][c]
__device__ float g_e0[BATCH*C];
__device__ float g_u [C];
__device__ float g_w2[C];
__device__ float g_kq[C];
__device__ float g_skq[BATCH];
__device__ float g_beta;
__device__ unsigned g_bar1, g_bar2, g_bar3;    // monotonic grid barriers

// ---------------- helpers -----------------------------------------------------
__device__ __forceinline__ void fma2(unsigned long long &acc,
                                     unsigned long long a, unsigned long long b) {
    asm("fma.rn.f32x2 %0, %1, %2, %0;" : "+l"(acc) : "l"(a), "l"(b));
}
__device__ __forceinline__ unsigned long long dup2(float a) {
    unsigned long long r; unsigned ai = __float_as_uint(a);
    asm("mov.b64 %0, {%1, %1};" : "=l"(r) : "r"(ai));
    return r;
}
__device__ __forceinline__ float2 unp2(unsigned long long v) {
    float2 r;
    r.x = __uint_as_float((unsigned)(v & 0xffffffffull));
    r.y = __uint_as_float((unsigned)(v >> 32));
    return r;
}
__device__ __forceinline__ float red16(float p) {
    p += __shfl_down_sync(0xffffffffu, p, 8, 16);
    p += __shfl_down_sync(0xffffffffu, p, 4, 16);
    p += __shfl_down_sync(0xffffffffu, p, 2, 16);
    p += __shfl_down_sync(0xffffffffu, p, 1, 16);
    return p;
}
__device__ __forceinline__ uint32_t smem_u32(const void* p) {
    uint32_t a;
    asm("{ .reg .u64 t; cvta.to.shared.u64 t, %1; cvt.u32.u64 %0, t; }"
        : "=r"(a) : "l"(p));
    return a;
}
// monotonic grid barrier (pure spin; safe across graph replays)
__device__ __forceinline__ void gbar(unsigned* ctr, unsigned tot) {
    __syncthreads();
    if (threadIdx.x == 0) {
        __threadfence();
        const unsigned old = atomicAdd(ctr, 1u);
        const unsigned tgt = (old / tot + 1u) * tot;
        volatile unsigned* p = ctr;
        while (*p < tgt) {}
    }
    __syncthreads();
    __threadfence();
}
__device__ __forceinline__ void ldsm_x4(uint32_t* r, uint32_t addr) {
    asm volatile("ldmatrix.sync.aligned.m8n8.x4.shared.b16 {%0,%1,%2,%3}, [%4];"
        : "=r"(r[0]), "=r"(r[1]), "=r"(r[2]), "=r"(r[3]) : "r"(addr));
}
__device__ __forceinline__ void ldsm_x2(uint32_t* r, uint32_t addr) {
    asm volatile("ldmatrix.sync.aligned.m8n8.x2.shared.b16 {%0,%1}, [%2];"
        : "=r"(r[0]), "=r"(r[1]) : "r"(addr));
}
__device__ __forceinline__ void ldsm_x2_trans(uint32_t* r, uint32_t addr) {
    asm volatile("ldmatrix.sync.aligned.m8n8.x2.trans.shared.b16 {%0,%1}, [%2];"
        : "=r"(r[0]), "=r"(r[1]) : "r"(addr));
}
__device__ __forceinline__ void mma16816(float* d, const uint32_t* a,
                                         const uint32_t* b) {
    asm volatile(
        "mma.sync.aligned.m16n8k16.row.col.f32.bf16.bf16.f32 "
        "{%0,%1,%2,%3}, {%4,%5,%6,%7}, {%8,%9}, {%0,%1,%2,%3};"
        : "+f"(d[0]), "+f"(d[1]), "+f"(d[2]), "+f"(d[3])
        : "r"(a[0]), "r"(a[1]), "r"(a[2]), "r"(a[3]), "r"(b[0]), "r"(b[1]));
}
__device__ __forceinline__ uint32_t pack_bf16(float lo, float hi) {
    uint32_t r;
    asm("cvt.rn.bf16x2.f32 %0, %1, %2;" : "=r"(r) : "f"(hi), "f"(lo));
    return r;
}

// smem offsets (pe view; tile view aliases xs/es over Gs/Bs)
#define OFF_GS   0        /* float[128][132] 67584 */
#define OFF_BS   67584    /* float[128][132] 67584 */
#define OFF_AS   135168   /* float[8][128]   4096  */
#define OFF_PS   139264   /* float[8][132]   4224  */
#define OFF_SS   143488
#define OFF_KQ   144000
#define OFF_RED  144512
#define OFF_T2   145024
#define OFF_BK   145088
#define DYN_SMEM 145664
#define OFF_ES   34816    /* tile blocks: xs at 0 (34816), es at 34816 */

// ---------------- fused kernel ------------------------------------------------
__global__ void __launch_bounds__(256) k_fused(
        const float* __restrict__ x,
        const float* __restrict__ w_q, const float* __restrict__ b_q,
        const float* __restrict__ w_k, const float* __restrict__ b_k,
        const float* __restrict__ w_v, const float* __restrict__ b_v,
        const float* __restrict__ w_o, const float* __restrict__ b_o,
        float* __restrict__ out) {
    extern __shared__ __align__(16) char dyn[];
    const int bid = blockIdx.x;
    const int t = threadIdx.x, wid = t >> 5, lane = t & 31;
    const float invN = 1.0f / (float)NPIX;

    // tile views
    __nv_bfloat16 (*xs)[136] = (__nv_bfloat16(*)[136])dyn;
    __nv_bfloat16 (*es)[136] = (__nv_bfloat16(*)[136])(dyn + OFF_ES);
    // pe views
    float (*Gs)[132]  = (float(*)[132])(dyn + OFF_GS);
    float (*Bs)[132]  = (float(*)[132])(dyn + OFF_BS);
    float (*As)[128]  = (float(*)[128])(dyn + OFF_AS);
    float (*Ps)[132]  = (float(*)[132])(dyn + OFF_PS);
    float* sS   = (float*)(dyn + OFF_SS);
    float* kqS  = (float*)(dyn + OFF_KQ);
    float* redS = (float*)(dyn + OFF_RED);
    float* t2S  = (float*)(dyn + OFF_T2);
    float* bkS  = (float*)(dyn + OFF_BK);

    // mma lane geometry (tile blocks)
    const int m0 = (wid & 1) * 64;
    const int n0 = (wid >> 1) * 32;
    const int arow = lane & 15, acol8 = (lane >> 4) << 3;
    const int brow = lane & 7,  bcol8 = ((lane >> 3) & 1) << 3;
    const int gr = lane >> 2, ci = lane & 3;
    // packed-matmul geometry (pe blocks)
    const int c0 = t & 63;     // colpair -> cols 2c0, 2c0+1
    const int rr = t >> 6;     // rows rr, rr+4 of the 8-row slab

    // =================== phase A =============================================
    if (bid < NTILE) {
        // ---- gram: X tile -> bf16 smem; s folded into convert loop ---------
        const int b = bid / NT, tile = bid % NT;
        const int nb = tile * 128;
        const float* xb = x + b*C*NPIX;

        #pragma unroll
        for (int it = 0; it < 16; it++) {
            const int e = t + it*256;
            const int row = e >> 5, q = e & 31;   // row = wid + it*8 (warp-uniform)
            const float4 v = __ldg((const float4*)&xb[row*NPIX + nb + q*4]);
            *(uint2*)&xs[row][q*4] =
                make_uint2(pack_bf16(v.x, v.y), pack_bf16(v.z, v.w));
            float sv = (v.x + v.y) + (v.z + v.w);
            #pragma unroll
            for (int off = 16; off > 0; off >>= 1)
                sv += __shfl_down_sync(0xffffffffu, sv, off);
            if (lane == 0) g_sp[(b*NT + tile)*C + row] = sv;
        }
        __syncthreads();

        const uint32_t xbase = smem_u32(xs);
        float acc[4][4][4];
        #pragma unroll
        for (int i = 0; i < 4; i++)
            #pragma unroll
            for (int j = 0; j < 4; j++)
                #pragma unroll
                for (int q = 0; q < 4; q++) acc[i][j][q] = 0.f;

        #pragma unroll
        for (int ks = 0; ks < 8; ks++) {
            const int k0 = ks * 16;
            uint32_t af[4][4], bf[4][2];
            #pragma unroll
            for (int i = 0; i < 4; i++)
                ldsm_x4(af[i], xbase + ((m0 + 16*i + arow)*136 + k0 + acol8)*2);
            #pragma unroll
            for (int j = 0; j < 4; j++)
                ldsm_x2(bf[j], xbase + ((n0 + 8*j + brow)*136 + k0 + bcol8)*2);
            #pragma unroll
            for (int i = 0; i < 4; i++)
                #pragma unroll
                for (int j = 0; j < 4; j++)
                    mma16816(acc[i][j], af[i], bf[j]);
        }
        __nv_bfloat16* Gp = g_Gpb + (size_t)(b*NT + tile)*C*C;
        #pragma unroll
        for (int i = 0; i < 4; i++)
            #pragma unroll
            for (int j = 0; j < 4; j++) {
                const int row = m0 + 16*i + gr;
                const int col = n0 + 8*j + 2*ci;
                *(uint32_t*)&Gp[row*C + col] =
                    pack_bf16(acc[i][j][0], acc[i][j][1]);
                *(uint32_t*)&Gp[(row + 8)*C + col] =
                    pack_bf16(acc[i][j][2], acc[i][j][3]);
            }
    } else {
        // ---- prep: A = Wo Wv, Bm = Wk^T Wq (packed f32x2), bias vectors ----
        const int bid2 = bid - NTILE;          // 0..31
        const bool isA = bid2 < 16;
        const int r0s = (bid2 & 15) * 8;

        if (t < C) bkS[t] = __ldg(&b_k[t]);
        for (int e = t; e < 8*C; e += 256) {
            const int i = e >> 7, j = e & 127;
            As[i][j] = isA ? __ldg(&w_o[(r0s + i)*C + j])
                           : __ldg(&w_k[j*C + (r0s + i)]);
        }
        {   // stage rhs (full 128x128) into Gs
            const float* rhs = isA ? w_v : w_q;
            #pragma unroll
            for (int k = 0; k < 16; k++) {
                const int idx = t + k*256;
                const int row = idx >> 5, seg = idx & 31;
                *(float4*)&Gs[row][seg*4] = __ldg((const float4*)&rhs[row*C + seg*4]);
            }
        }
        __syncthreads();

        if (t < 128) {     // u[r] (A blocks) / kq[r] (Bm blocks)
            const int row = t >> 4, l = t & 15;
            const float* bv = isA ? b_v : b_q;
            float p = 0.f;
            #pragma unroll
            for (int j = 0; j < 8; j++)
                p += As[row][l*8 + j] * __ldg(&bv[l*8 + j]);
            p = red16(p);
            if (l == 0) (isA ? g_u : g_kq)[r0s + row] = p;
        }
        if (bid2 == 16 && t >= 128 && t < 160) {     // beta = bk.bq
            const int l = t - 128;
            float p = 0.f;
            #pragma unroll
            for (int j = 0; j < 4; j++) p += bkS[l*4 + j] * __ldg(&b_q[l*4 + j]);
            #pragma unroll
            for (int off = 16; off > 0; off >>= 1)
                p += __shfl_down_sync(0xffffffffu, p, off);
            if (l == 0) g_beta = p;
        }

        unsigned long long a0 = 0ull, a1 = 0ull, aw = 0ull;
        #pragma unroll 16
        for (int j = 0; j < 128; j++) {
            const unsigned long long r2 = *(const unsigned long long*)&Gs[j][2*c0];
            fma2(a0, dup2(As[rr][j]), r2);
            fma2(a1, dup2(As[rr + 4][j]), r2);
            fma2(aw, dup2(bkS[j]), r2);
        }
        float* dst = isA ? g_A : g_Bm;
        *(float2*)&dst[(r0s + rr)*C + 2*c0]     = unp2(a0);
        *(float2*)&dst[(r0s + rr + 4)*C + 2*c0] = unp2(a1);
        if (bid2 == 16 && rr == 0) *(float2*)&g_w2[2*c0] = unp2(aw);
    }

    gbar(&g_bar1, NTOT);      // gram partials + A/Bm/bias visible

    // =================== phase R =============================================
    if (bid >= NTILE) {       // pe blocks: prefetch A, Bm, kq
        const int bid2 = bid - NTILE;
        const int r0s = (bid2 & 15) * 8;
        {
            const int row = t >> 5, seg = (t & 31);
            *(float4*)&As[row][seg*4] =
                __ldg((const float4*)&g_A[(r0s + row)*C + seg*4]);
        }
        #pragma unroll
        for (int k = 0; k < 16; k++) {
            const int idx = t + k*256;
            const int row = idx >> 5, seg = idx & 31;
            *(float4*)&Bs[row][seg*4] = __ldcg((const float4*)&g_Bm[row*C + seg*4]);
        }
        if (t < C) kqS[t] = __ldcg(&g_kq[t]);
    }
    if (bid < 32) {
        // bf16 partial reduce: 4 elems/thread, 50-deep LDG.64 chain
        const int idx = bid*256 + t;               // 0..8191
        const int b = idx >> 12;
        const int e = (idx & 4095) * 4;
        const __nv_bfloat16* base = g_Gpb + (size_t)b*NT*C*C + e;
        float s0 = 0.f, s1 = 0.f, s2 = 0.f, s3 = 0.f;
        #pragma unroll
        for (int ch = 0; ch < NT; ch++) {
            const uint2 v = *(const uint2*)(base + (size_t)ch*C*C);
            const float2 lo = __bfloat1622float2(*(const __nv_bfloat162*)&v.x);
            const float2 hi = __bfloat1622float2(*(const __nv_bfloat162*)&v.y);
            s0 += lo.x; s1 += lo.y; s2 += hi.x; s3 += hi.y;
        }
        *(float4*)&g_G[b*C*C + e] = make_float4(s0, s1, s2, s3);
    } else if (bid == 128 || bid == 129) {
        // s reduce + skq for batch b (these are pe blocks; kqS just loaded by self)
        const int b = bid - 128;
        float sv = 0.f;
        if (t < C) {
            const float* sb = g_sp + b*NT*C + t;
            #pragma unroll
            for (int ch = 0; ch < NT; ch++) sv += sb[ch*C];
            g_s[b*C + t] = sv;
            redS[t] = sv * kqS[t];
        }
        __syncthreads();
        if (t < 64) redS[t] += redS[t + 64];
        __syncthreads();
        if (t < 32) {
            float v = redS[t] + redS[t + 32];
            #pragma unroll
            for (int off = 16; off > 0; off >>= 1)
                v += __shfl_down_sync(0xffffffffu, v, off);
            if (t == 0) g_skq[b] = v;
        }
    }

    gbar(&g_bar2, NTOT);      // G, s, skq complete

    // =================== phase B: pe blocks compute E', e0 ===================
    if (bid >= NTILE) {
        const int bid2 = bid - NTILE;
        const int b  = bid2 >> 4;
        const int r0s = (bid2 & 15) * 8;

        {   // stage full G in one wave
            const float* Gb = g_G + b*C*C;
            #pragma unroll
            for (int k = 0; k < 16; k++) {
                const int idx = t + k*256;
                const int row = idx >> 5, seg = idx & 31;
                *(float4*)&Gs[row][seg*4] = __ldcg((const float4*)&Gb[row*C + seg*4]);
            }
        }
        if (t < C) sS[t] = __ldcg(&g_s[b*C + t]);
        __syncthreads();

        if (t < 128) {         // t2[r] = A_rows . s
            const int row = t >> 4, l = t & 15;
            float p = 0.f;
            #pragma unroll
            for (int j = 0; j < 8; j++) p += As[row][l*8 + j] * sS[l*8 + j];
            p = red16(p);
            if (l == 0) t2S[row] = p;
        }

        {   // P = A_rows @ G (packed)
            unsigned long long a0 = 0ull, a1 = 0ull;
            #pragma unroll 16
            for (int j = 0; j < 128; j++) {
                const unsigned long long g2 = *(const unsigned long long*)&Gs[j][2*c0];
                fma2(a0, dup2(As[rr][j]), g2);
                fma2(a1, dup2(As[rr + 4][j]), g2);
            }
            *(float2*)&Ps[rr][2*c0]     = unp2(a0);
            *(float2*)&Ps[rr + 4][2*c0] = unp2(a1);
        }
        __syncthreads();

        {   // E' rows = invN * P @ Bm + rank-1 terms -> bf16 (packed)
            unsigned long long a0 = 0ull, a1 = 0ull, t1a = 0ull;
            #pragma unroll 16
            for (int j = 0; j < 128; j++) {
                const unsigned long long b2 = *(const unsigned long long*)&Bs[j][2*c0];
                fma2(a0, dup2(Ps[rr][j]), b2);
                fma2(a1, dup2(Ps[rr + 4][j]), b2);
                fma2(t1a, dup2(sS[j]), b2);
            }
            const float2 w2p = *(const float2*)&g_w2[2*c0];
            const float2 t1p = unp2(t1a);
            const float2 p0 = unp2(a0), p1 = unp2(a1);
            {
                const int r = r0s + rr;
                const float ur = __ldg(&g_u[r]);
                const float cmn = invN*t2S[rr] + ur;
                const float vx = invN*p0.x + invN*ur*t1p.x + cmn*w2p.x;
                const float vy = invN*p0.y + invN*ur*t1p.y + cmn*w2p.y;
                *(uint32_t*)&g_Ebf[b*C*C + r*C + 2*c0] = pack_bf16(vx, vy);
            }
            {
                const int r = r0s + rr + 4;
                const float ur = __ldg(&g_u[r]);
                const float cmn = invN*t2S[rr + 4] + ur;
                const float vx = invN*p1.x + invN*ur*t1p.x + cmn*w2p.x;
                const float vy = invN*p1.y + invN*ur*t1p.y + cmn*w2p.y;
                *(uint32_t*)&g_Ebf[b*C*C + r*C + 2*c0] = pack_bf16(vx, vy);
            }
        }
        if (t < 8) {           // e0 rows of this slab
            float pk = 0.f;
            #pragma unroll 16
            for (int j = 0; j < C; j++) pk += Ps[t][j] * kqS[j];
            const int r = r0s + t;
            const float ur = __ldg(&g_u[r]);
            g_e0[b*C + r] = invN*pk + invN*ur*g_skq[b]
                          + (invN*t2S[t] + ur)*g_beta + __ldg(&b_o[r]);
        }
    }

    gbar(&g_bar3, NTOT);      // E', e0 visible

    // =================== phase C: tile blocks out = X + E'X + e0 =============
    if (bid < NTILE) {
        const int b = bid / NT, tile = bid % NT;
        const int nb = tile * 128;
        const float* xb = x + b*C*NPIX;
        const __nv_bfloat16* Eb = g_Ebf + b*C*C;

        #pragma unroll
        for (int it = 0; it < 8; it++) {       // stage E' (32 KB) into es
            const int idx = t + it*256;
            const int row = idx >> 4, seg = idx & 15;
            *(uint4*)&es[row][seg*8] = __ldcg((const uint4*)&Eb[row*C + seg*8]);
        }
        __syncthreads();
        const uint32_t xbase = smem_u32(xs);
        const uint32_t ebase = smem_u32(es);

        float acc[4][4][4];
        #pragma unroll
        for (int i = 0; i < 4; i++)
            #pragma unroll
            for (int j = 0; j < 4; j++)
                #pragma unroll
                for (int q = 0; q < 4; q++) acc[i][j][q] = 0.f;

        #pragma unroll
        for (int ks = 0; ks < 8; ks++) {
            const int k0 = ks * 16;
            uint32_t af[4][4], bf[4][2];
            #pragma unroll
            for (int i = 0; i < 4; i++)
                ldsm_x4(af[i], ebase + ((m0 + 16*i + arow)*136 + k0 + acol8)*2);
            #pragma unroll
            for (int j = 0; j < 4; j++)
                ldsm_x2_trans(bf[j], xbase + ((k0 + (lane & 15))*136 + n0 + 8*j)*2);
            #pragma unroll
            for (int i = 0; i < 4; i++)
                #pragma unroll
                for (int j = 0; j < 4; j++)
                    mma16816(acc[i][j], af[i], bf[j]);
        }

        float* ob = out + b*C*NPIX;
        #pragma unroll
        for (int i = 0; i < 4; i++) {
            const int row = m0 + 16*i + gr;
            const float e0a = g_e0[b*C + row];
            const float e0b = g_e0[b*C + row + 8];
            #pragma unroll
            for (int j = 0; j < 4; j++) {
                const int col = n0 + 8*j + 2*ci;
                const float2 xa = *(const float2*)&xb[row*NPIX + nb + col];
                const float2 xc = *(const float2*)&xb[(row + 8)*NPIX + nb + col];
                *(float2*)&ob[row*NPIX + nb + col] =
                    make_float2(acc[i][j][0] + xa.x + e0a, acc[i][j][1] + xa.y + e0a);
                *(float2*)&ob[(row + 8)*NPIX + nb + col] =
                    make_float2(acc[i][j][2] + xc.x + e0b, acc[i][j][3] + xc.y + e0b);
            }
        }
    }
}

// ---------------- host launcher ----------------------------------------------
extern "C" void kernel_launch(void* const* d_in, const int* in_sizes, int n_in,
                              void* d_out, int out_size) {
    (void)in_sizes; (void)n_in; (void)out_size;
    const float* x   = (const float*)d_in[0];
    const float* w_q = (const float*)d_in[1];
    const float* b_q = (const float*)d_in[2];
    const float* w_k = (const float*)d_in[3];
    const float* b_k = (const float*)d_in[4];
    const float* w_v = (const float*)d_in[5];
    const float* b_v = (const float*)d_in[6];
    const float* w_o = (const float*)d_in[7];
    const float* b_o = (const float*)d_in[8];
    float* out = (float*)d_out;

    cudaFuncSetAttribute(k_fused, cudaFuncAttributeMaxDynamicSharedMemorySize,
                         DYN_SMEM);
    k_fused<<<NTOT, 256, DYN_SMEM>>>(x, w_q, b_q, w_k, b_k, w_v, b_v,
                                     w_o, b_o, out);
}

// round 14
// speedup vs baseline: 3.9212x; 1.1304x over previous
#include <cuda_runtime.h>
#include <cuda_bf16.h>
#include <cstdint>

// NonLocalModule (no softmax) collapsed via associativity, fully fused:
//   out = X + E' X + e0, G = X X^T (128x128/batch), A = Wo Wv, Bm = Wk^T Wq,
//   E' = (1/N)[A G Bm + (A s) w2^T + u (Bm^T s)^T] + u w2^T
//   e0 = (1/N)[(A G) kq + (A s) beta + u (s.kq)] + u beta + bo
// Single persistent kernel, 132 blocks (all co-resident):
//   phase A: blocks 0..99 gram (bf16 mma.sync, X tile stays warm in smem);
//            blocks 100..131 prep (A, Bm, bias vectors; packed f32x2).
//   bar1 (wait: R blocks 0..31, B blocks 100..115, s blocks 128..129)
//   phase R: blocks 0..31 reduce bf16 G partials -> bf16 G;
//            blocks 128/129 reduce s + skq; B blocks prefetch A/Bm as bf16.
//   bar2 (wait: B blocks)
//   phase B: 16 B blocks (16-row slabs): P = A G and E' = P Bm via bf16
//            mma.sync (G symmetric; Bm via ldsm.trans); e0 from fp32 P.
//   bar3 (wait: tile blocks)
//   phase C: tile blocks out = X + E' X + e0 (reuse warm X tile).
// Barriers: monotonic counters; ALL blocks arrive at all three (replay-safe).

#define C     128
#define NPIX  6400
#define BATCH 2
#define NT    50
#define NTILE 100
#define NTOT  132

// ---------------- device scratch (no allocations allowed) --------------------
__device__ __nv_bfloat16 g_Gpb[BATCH*NT*C*C];  // bf16 gram partials
__device__ float g_sp[BATCH*NT*C];
__device__ __nv_bfloat16 g_Gb16[BATCH*C*C];    // reduced G, bf16
__device__ float g_s [BATCH*C];
__device__ float g_A [C*C];
__device__ float g_Bm[C*C];
__device__ __nv_bfloat16 g_Ebf[BATCH*C*C];     // E' bf16, row-major [r][c]
__device__ float g_e0[BATCH*C];
__device__ float g_u [C];
__device__ float g_w2[C];
__device__ float g_kq[C];
__device__ float g_skq[BATCH];
__device__ float g_beta;
__device__ unsigned g_bar1, g_bar2, g_bar3;    // monotonic grid barriers

// ---------------- helpers -----------------------------------------------------
__device__ __forceinline__ void fma2(unsigned long long &acc,
                                     unsigned long long a, unsigned long long b) {
    asm("fma.rn.f32x2 %0, %1, %2, %0;" : "+l"(acc) : "l"(a), "l"(b));
}
__device__ __forceinline__ unsigned long long dup2(float a) {
    unsigned long long r; unsigned ai = __float_as_uint(a);
    asm("mov.b64 %0, {%1, %1};" : "=l"(r) : "r"(ai));
    return r;
}
__device__ __forceinline__ float2 unp2(unsigned long long v) {
    float2 r;
    r.x = __uint_as_float((unsigned)(v & 0xffffffffull));
    r.y = __uint_as_float((unsigned)(v >> 32));
    return r;
}
__device__ __forceinline__ float red16(float p) {
    p += __shfl_down_sync(0xffffffffu, p, 8, 16);
    p += __shfl_down_sync(0xffffffffu, p, 4, 16);
    p += __shfl_down_sync(0xffffffffu, p, 2, 16);
    p += __shfl_down_sync(0xffffffffu, p, 1, 16);
    return p;
}
__device__ __forceinline__ uint32_t smem_u32(const void* p) {
    uint32_t a;
    asm("{ .reg .u64 t; cvta.to.shared.u64 t, %1; cvt.u32.u64 %0, t; }"
        : "=r"(a) : "l"(p));
    return a;
}
// monotonic barriers: every block arrives at every counter exactly once/launch
__device__ __forceinline__ void gbar_arrive(unsigned* ctr) {
    __syncthreads();
    if (threadIdx.x == 0) { __threadfence(); atomicAdd(ctr, 1u); }
}
__device__ __forceinline__ void gbar_wait(unsigned* ctr, unsigned tot) {
    __syncthreads();
    if (threadIdx.x == 0) {
        __threadfence();
        const unsigned old = atomicAdd(ctr, 1u);
        const unsigned tgt = (old / tot + 1u) * tot;
        volatile unsigned* p = ctr;
        while (*p < tgt) {}
    }
    __syncthreads();
    __threadfence();
}
__device__ __forceinline__ void ldsm_x4(uint32_t* r, uint32_t addr) {
    asm volatile("ldmatrix.sync.aligned.m8n8.x4.shared.b16 {%0,%1,%2,%3}, [%4];"
        : "=r"(r[0]), "=r"(r[1]), "=r"(r[2]), "=r"(r[3]) : "r"(addr));
}
__device__ __forceinline__ void ldsm_x2(uint32_t* r, uint32_t addr) {
    asm volatile("ldmatrix.sync.aligned.m8n8.x2.shared.b16 {%0,%1}, [%2];"
        : "=r"(r[0]), "=r"(r[1]) : "r"(addr));
}
__device__ __forceinline__ void ldsm_x2_trans(uint32_t* r, uint32_t addr) {
    asm volatile("ldmatrix.sync.aligned.m8n8.x2.trans.shared.b16 {%0,%1}, [%2];"
        : "=r"(r[0]), "=r"(r[1]) : "r"(addr));
}
__device__ __forceinline__ void mma16816(float* d, const uint32_t* a,
                                         const uint32_t* b) {
    asm volatile(
        "mma.sync.aligned.m16n8k16.row.col.f32.bf16.bf16.f32 "
        "{%0,%1,%2,%3}, {%4,%5,%6,%7}, {%8,%9}, {%0,%1,%2,%3};"
        : "+f"(d[0]), "+f"(d[1]), "+f"(d[2]), "+f"(d[3])
        : "r"(a[0]), "r"(a[1]), "r"(a[2]), "r"(a[3]), "r"(b[0]), "r"(b[1]));
}
__device__ __forceinline__ uint32_t pack_bf16(float lo, float hi) {
    uint32_t r;
    asm("cvt.rn.bf16x2.f32 %0, %1, %2;" : "=r"(r) : "f"(hi), "f"(lo));
    return r;
}

// smem offsets.  Tile blocks: xs@0 (34816), es@34816 (34816).
// Prep (pe) blocks: Gs fp32 @0 (67584), As fp32 @135168, bk @145088.
// B blocks (after prep done): Gbf@0, Bmbf@34816, Abf@69632, Pbf@73984,
//   t1S@78336, sSb@78848, kqSb@79360, t2Sb@79872, pkS@80000.
#define OFF_GS   0
#define OFF_AS   135168
#define OFF_BK   145088
#define OFF_ES   34816
#define OFF_BMBF 34816
#define OFF_ABF  69632
#define OFF_PBF  73984
#define OFF_T1   78336
#define OFF_SSB  78848
#define OFF_KQB  79360
#define OFF_T2B  79872
#define OFF_PKS  80000
#define DYN_SMEM 145664

// ---------------- fused kernel ------------------------------------------------
__global__ void __launch_bounds__(256) k_fused(
        const float* __restrict__ x,
        const float* __restrict__ w_q, const float* __restrict__ b_q,
        const float* __restrict__ w_k, const float* __restrict__ b_k,
        const float* __restrict__ w_v, const float* __restrict__ b_v,
        const float* __restrict__ w_o, const float* __restrict__ b_o,
        float* __restrict__ out) {
    extern __shared__ __align__(16) char dyn[];
    const int bid = blockIdx.x;
    const int t = threadIdx.x, wid = t >> 5, lane = t & 31;
    const float invN = 1.0f / (float)NPIX;

    // views
    __nv_bfloat16 (*xs)[136]   = (__nv_bfloat16(*)[136])dyn;
    __nv_bfloat16 (*es)[136]   = (__nv_bfloat16(*)[136])(dyn + OFF_ES);
    float (*Gs)[132]           = (float(*)[132])(dyn + OFF_GS);
    float (*As)[128]           = (float(*)[128])(dyn + OFF_AS);
    float* bkS                 = (float*)(dyn + OFF_BK);
    __nv_bfloat16 (*Gbf)[136]  = (__nv_bfloat16(*)[136])dyn;
    __nv_bfloat16 (*Bmbf)[136] = (__nv_bfloat16(*)[136])(dyn + OFF_BMBF);
    __nv_bfloat16 (*Abf)[136]  = (__nv_bfloat16(*)[136])(dyn + OFF_ABF);
    __nv_bfloat16 (*Pbf)[136]  = (__nv_bfloat16(*)[136])(dyn + OFF_PBF);
    float* t1S  = (float*)(dyn + OFF_T1);
    float* sSb  = (float*)(dyn + OFF_SSB);
    float* kqSb = (float*)(dyn + OFF_KQB);
    float* t2Sb = (float*)(dyn + OFF_T2B);
    float (*pkS)[8] = (float(*)[8])(dyn + OFF_PKS);

    // mma lane geometry
    const int m0 = (wid & 1) * 64;
    const int n0 = (wid >> 1) * 32;
    const int arow = lane & 15, acol8 = (lane >> 4) << 3;
    const int brow = lane & 7,  bcol8 = ((lane >> 3) & 1) << 3;
    const int gr = lane >> 2, ci = lane & 3;
    // packed-prep geometry
    const int c0 = t & 63;
    const int rr = t >> 6;

    const bool isB = (bid >= 100 && bid < 116);   // E'-computing blocks

    // =================== phase A =============================================
    if (bid < NTILE) {
        const int b = bid / NT, tile = bid % NT;
        const int nb = tile * 128;
        const float* xb = x + b*C*NPIX;

        #pragma unroll
        for (int it = 0; it < 16; it++) {
            const int e = t + it*256;
            const int row = e >> 5, q = e & 31;
            const float4 v = __ldg((const float4*)&xb[row*NPIX + nb + q*4]);
            *(uint2*)&xs[row][q*4] =
                make_uint2(pack_bf16(v.x, v.y), pack_bf16(v.z, v.w));
            float sv = (v.x + v.y) + (v.z + v.w);
            #pragma unroll
            for (int off = 16; off > 0; off >>= 1)
                sv += __shfl_down_sync(0xffffffffu, sv, off);
            if (lane == 0) g_sp[(b*NT + tile)*C + row] = sv;
        }
        __syncthreads();

        const uint32_t xbase = smem_u32(xs);
        float acc[4][4][4];
        #pragma unroll
        for (int i = 0; i < 4; i++)
            #pragma unroll
            for (int j = 0; j < 4; j++)
                #pragma unroll
                for (int q = 0; q < 4; q++) acc[i][j][q] = 0.f;

        #pragma unroll
        for (int ks = 0; ks < 8; ks++) {
            const int k0 = ks * 16;
            uint32_t af[4][4], bf[4][2];
            #pragma unroll
            for (int i = 0; i < 4; i++)
                ldsm_x4(af[i], xbase + ((m0 + 16*i + arow)*136 + k0 + acol8)*2);
            #pragma unroll
            for (int j = 0; j < 4; j++)
                ldsm_x2(bf[j], xbase + ((n0 + 8*j + brow)*136 + k0 + bcol8)*2);
            #pragma unroll
            for (int i = 0; i < 4; i++)
                #pragma unroll
                for (int j = 0; j < 4; j++)
                    mma16816(acc[i][j], af[i], bf[j]);
        }
        __nv_bfloat16* Gp = g_Gpb + (size_t)(b*NT + tile)*C*C;
        #pragma unroll
        for (int i = 0; i < 4; i++)
            #pragma unroll
            for (int j = 0; j < 4; j++) {
                const int row = m0 + 16*i + gr;
                const int col = n0 + 8*j + 2*ci;
                *(uint32_t*)&Gp[row*C + col] =
                    pack_bf16(acc[i][j][0], acc[i][j][1]);
                *(uint32_t*)&Gp[(row + 8)*C + col] =
                    pack_bf16(acc[i][j][2], acc[i][j][3]);
            }
    } else {
        // ---- prep: A = Wo Wv, Bm = Wk^T Wq (packed f32x2), bias vectors ----
        const int bid2 = bid - NTILE;          // 0..31
        const bool isA = bid2 < 16;
        const int r0s = (bid2 & 15) * 8;

        if (t < C) bkS[t] = __ldg(&b_k[t]);
        for (int e = t; e < 8*C; e += 256) {
            const int i = e >> 7, j = e & 127;
            As[i][j] = isA ? __ldg(&w_o[(r0s + i)*C + j])
                           : __ldg(&w_k[j*C + (r0s + i)]);
        }
        {
            const float* rhs = isA ? w_v : w_q;
            #pragma unroll
            for (int k = 0; k < 16; k++) {
                const int idx = t + k*256;
                const int row = idx >> 5, seg = idx & 31;
                *(float4*)&Gs[row][seg*4] = __ldg((const float4*)&rhs[row*C + seg*4]);
            }
        }
        __syncthreads();

        if (t < 128) {     // u[r] (A blocks) / kq[r] (Bm blocks)
            const int row = t >> 4, l = t & 15;
            const float* bv = isA ? b_v : b_q;
            float p = 0.f;
            #pragma unroll
            for (int j = 0; j < 8; j++)
                p += As[row][l*8 + j] * __ldg(&bv[l*8 + j]);
            p = red16(p);
            if (l == 0) (isA ? g_u : g_kq)[r0s + row] = p;
        }
        if (bid2 == 16 && t >= 128 && t < 160) {     // beta = bk.bq
            const int l = t - 128;
            float p = 0.f;
            #pragma unroll
            for (int j = 0; j < 4; j++) p += bkS[l*4 + j] * __ldg(&b_q[l*4 + j]);
            #pragma unroll
            for (int off = 16; off > 0; off >>= 1)
                p += __shfl_down_sync(0xffffffffu, p, off);
            if (l == 0) g_beta = p;
        }

        unsigned long long a0 = 0ull, a1 = 0ull, aw = 0ull;
        #pragma unroll 16
        for (int j = 0; j < 128; j++) {
            const unsigned long long r2 = *(const unsigned long long*)&Gs[j][2*c0];
            fma2(a0, dup2(As[rr][j]), r2);
            fma2(a1, dup2(As[rr + 4][j]), r2);
            fma2(aw, dup2(bkS[j]), r2);
        }
        float* dst = isA ? g_A : g_Bm;
        *(float2*)&dst[(r0s + rr)*C + 2*c0]     = unp2(a0);
        *(float2*)&dst[(r0s + rr + 4)*C + 2*c0] = unp2(a1);
        if (bid2 == 16 && rr == 0) *(float2*)&g_w2[2*c0] = unp2(aw);
    }

    // bar1: wait only where needed
    if (bid < 32 || isB || bid == 128 || bid == 129) gbar_wait(&g_bar1, NTOT);
    else                                            gbar_arrive(&g_bar1);

    // =================== phase R =============================================
    if (isB) {
        // prefetch A slab + Bm as bf16 (fp32 -> bf16 convert)
        const int bb = bid - 100;              // 0..15
        const int b = bb >> 3, slab = bb & 7;
        const int r0s = slab * 16;
        (void)b;
        #pragma unroll
        for (int k = 0; k < 4; k++) {          // Abf: 16x128 -> 1024 pairs
            const int idx = t + k*256;
            const int row = idx >> 6, cp = idx & 63;
            const float2 v = __ldcg((const float2*)&g_A[(r0s + row)*C + cp*2]);
            *(uint32_t*)&Abf[row][cp*2] = pack_bf16(v.x, v.y);
        }
        #pragma unroll
        for (int k = 0; k < 16; k++) {         // Bmbf: 128x128
            const int idx = t + k*256;
            const int row = idx >> 5, seg = idx & 31;
            const float4 v = __ldcg((const float4*)&g_Bm[row*C + seg*4]);
            *(uint2*)&Bmbf[row][seg*4] =
                make_uint2(pack_bf16(v.x, v.y), pack_bf16(v.z, v.w));
        }
        if (t < C) kqSb[t] = __ldcg(&g_kq[t]);
    }
    if (bid < 32) {
        // bf16 partial reduce -> bf16 G
        const int idx = bid*256 + t;               // 0..8191
        const int b = idx >> 12;
        const int e = (idx & 4095) * 4;
        const __nv_bfloat16* base = g_Gpb + (size_t)b*NT*C*C + e;
        float s0 = 0.f, s1 = 0.f, s2 = 0.f, s3 = 0.f;
        #pragma unroll
        for (int ch = 0; ch < NT; ch++) {
            const uint2 v = *(const uint2*)(base + (size_t)ch*C*C);
            const float2 lo = __bfloat1622float2(*(const __nv_bfloat162*)&v.x);
            const float2 hi = __bfloat1622float2(*(const __nv_bfloat162*)&v.y);
            s0 += lo.x; s1 += lo.y; s2 += hi.x; s3 += hi.y;
        }
        *(uint2*)&g_Gb16[b*C*C + e] =
            make_uint2(pack_bf16(s0, s1), pack_bf16(s2, s3));
    } else if (bid == 128 || bid == 129) {
        // s reduce + skq for batch b
        const int b = bid - 128;
        float sv = 0.f;
        float* redS = (float*)(dyn + OFF_T1);   // scratch (no conflict: not a B block)
        if (t < C) {
            const float* sb = g_sp + b*NT*C + t;
            #pragma unroll
            for (int ch = 0; ch < NT; ch++) sv += sb[ch*C];
            g_s[b*C + t] = sv;
            redS[t] = sv * __ldcg(&g_kq[t]);
        }
        __syncthreads();
        if (t < 64) redS[t] += redS[t + 64];
        __syncthreads();
        if (t < 32) {
            float v = redS[t] + redS[t + 32];
            #pragma unroll
            for (int off = 16; off > 0; off >>= 1)
                v += __shfl_down_sync(0xffffffffu, v, off);
            if (t == 0) g_skq[b] = v;
        }
    }

    if (isB) gbar_wait(&g_bar2, NTOT);
    else     gbar_arrive(&g_bar2);

    // =================== phase B: 16 blocks, tensor-core E' ==================
    if (isB) {
        const int bb = bid - 100;
        const int b = bb >> 3, slab = bb & 7;
        const int r0s = slab * 16;

        #pragma unroll
        for (int k = 0; k < 8; k++) {          // stage bf16 G (32 KB)
            const int idx = t + k*256;
            const int row = idx >> 4, seg = idx & 15;
            *(uint4*)&Gbf[row][seg*8] =
                __ldcg((const uint4*)&g_Gb16[b*C*C + row*C + seg*8]);
        }
        if (t < C) sSb[t] = __ldcg(&g_s[b*C + t]);
        __syncthreads();

        // t1[c] = (Bm^T s)[c]; t2[r] = (A s)[r]
        if (t < C) {
            float p = 0.f;
            #pragma unroll 16
            for (int j = 0; j < 128; j++)
                p += __bfloat162float(Bmbf[j][t]) * sSb[j];
            t1S[t] = p;
        }
        {
            const int row = t >> 4, l = t & 15;
            float p = 0.f;
            #pragma unroll
            for (int j = 0; j < 8; j++)
                p += __ldg(&g_A[(r0s + row)*C + l*8 + j]) * sSb[l*8 + j];
            p = red16(p);
            if (l == 0) t2Sb[row] = p;
        }

        // mma1: P[16][128] = Abf @ G  (G symmetric => row-major = col operand)
        const uint32_t abase = smem_u32(Abf);
        const uint32_t gbase = smem_u32(Gbf);
        const int nw = wid * 16;               // warp's 16-col slice
        float accP[2][4];
        #pragma unroll
        for (int j = 0; j < 2; j++)
            #pragma unroll
            for (int q = 0; q < 4; q++) accP[j][q] = 0.f;
        #pragma unroll
        for (int ks = 0; ks < 8; ks++) {
            const int k0 = ks * 16;
            uint32_t af[4], bf[2][2];
            ldsm_x4(af, abase + (arow*136 + k0 + acol8)*2);
            #pragma unroll
            for (int j = 0; j < 2; j++)
                ldsm_x2(bf[j], gbase + ((nw + 8*j + brow)*136 + k0 + bcol8)*2);
            #pragma unroll
            for (int j = 0; j < 2; j++)
                mma16816(accP[j], af, bf[j]);
        }

        // e0 partials: pk[r] = sum_c P[r][c] kq[c]
        {
            const int cA0 = nw + 2*ci, cA1 = nw + 8 + 2*ci;
            float pk0 = accP[0][0]*kqSb[cA0] + accP[0][1]*kqSb[cA0+1]
                      + accP[1][0]*kqSb[cA1] + accP[1][1]*kqSb[cA1+1];
            float pk1 = accP[0][2]*kqSb[cA0] + accP[0][3]*kqSb[cA0+1]
                      + accP[1][2]*kqSb[cA1] + accP[1][3]*kqSb[cA1+1];
            pk0 += __shfl_down_sync(0xffffffffu, pk0, 2, 4);
            pk0 += __shfl_down_sync(0xffffffffu, pk0, 1, 4);
            pk1 += __shfl_down_sync(0xffffffffu, pk1, 2, 4);
            pk1 += __shfl_down_sync(0xffffffffu, pk1, 1, 4);
            if (ci == 0) { pkS[gr][wid] = pk0; pkS[gr + 8][wid] = pk1; }
        }
        // P -> bf16
        #pragma unroll
        for (int j = 0; j < 2; j++) {
            const int col = nw + 8*j + 2*ci;
            *(uint32_t*)&Pbf[gr][col]     = pack_bf16(accP[j][0], accP[j][1]);
            *(uint32_t*)&Pbf[gr + 8][col] = pack_bf16(accP[j][2], accP[j][3]);
        }
        __syncthreads();

        if (t < 16) {   // finalize e0 rows
            float pk = 0.f;
            #pragma unroll
            for (int w = 0; w < 8; w++) pk += pkS[t][w];
            const int r = r0s + t;
            const float ur = __ldg(&g_u[r]);
            g_e0[b*C + r] = invN*pk + invN*ur*g_skq[b]
                          + (invN*t2Sb[t] + ur)*g_beta + __ldg(&b_o[r]);
        }

        // mma2: E'[16][128] = Pbf @ Bm  (Bm col operand via ldsm.trans)
        const uint32_t pbase = smem_u32(Pbf);
        const uint32_t bmbase = smem_u32(Bmbf);
        float accE[2][4];
        #pragma unroll
        for (int j = 0; j < 2; j++)
            #pragma unroll
            for (int q = 0; q < 4; q++) accE[j][q] = 0.f;
        #pragma unroll
        for (int ks = 0; ks < 8; ks++) {
            const int k0 = ks * 16;
            uint32_t af[4], bf[2][2];
            ldsm_x4(af, pbase + (arow*136 + k0 + acol8)*2);
            #pragma unroll
            for (int j = 0; j < 2; j++)
                ldsm_x2_trans(bf[j], bmbase + ((k0 + (lane & 15))*136 + nw + 8*j)*2);
            #pragma unroll
            for (int j = 0; j < 2; j++)
                mma16816(accE[j], af, bf[j]);
        }
        // epilogue: rank-1 terms + pack to g_Ebf
        #pragma unroll
        for (int j = 0; j < 2; j++) {
            const int col = nw + 8*j + 2*ci;
            const float w20 = __ldg(&g_w2[col]), w21 = __ldg(&g_w2[col + 1]);
            const float t10 = t1S[col], t11 = t1S[col + 1];
            {
                const int r = r0s + gr;
                const float ur = __ldg(&g_u[r]);
                const float cmn = invN*t2Sb[gr] + ur;
                *(uint32_t*)&g_Ebf[b*C*C + r*C + col] = pack_bf16(
                    invN*accE[j][0] + invN*ur*t10 + cmn*w20,
                    invN*accE[j][1] + invN*ur*t11 + cmn*w21);
            }
            {
                const int r = r0s + gr + 8;
                const float ur = __ldg(&g_u[r]);
                const float cmn = invN*t2Sb[gr + 8] + ur;
                *(uint32_t*)&g_Ebf[b*C*C + r*C + col] = pack_bf16(
                    invN*accE[j][2] + invN*ur*t10 + cmn*w20,
                    invN*accE[j][3] + invN*ur*t11 + cmn*w21);
            }
        }
    }

    if (bid < NTILE) gbar_wait(&g_bar3, NTOT);
    else             gbar_arrive(&g_bar3);

    // =================== phase C: tile blocks out = X + E'X + e0 =============
    if (bid < NTILE) {
        const int b = bid / NT, tile = bid % NT;
        const int nb = tile * 128;
        const float* xb = x + b*C*NPIX;
        const __nv_bfloat16* Eb = g_Ebf + b*C*C;

        #pragma unroll
        for (int it = 0; it < 8; it++) {       // stage E' (32 KB) into es
            const int idx = t + it*256;
            const int row = idx >> 4, seg = idx & 15;
            *(uint4*)&es[row][seg*8] = __ldcg((const uint4*)&Eb[row*C + seg*8]);
        }
        __syncthreads();
        const uint32_t xbase = smem_u32(xs);
        const uint32_t ebase = smem_u32(es);

        float acc[4][4][4];
        #pragma unroll
        for (int i = 0; i < 4; i++)
            #pragma unroll
            for (int j = 0; j < 4; j++)
                #pragma unroll
                for (int q = 0; q < 4; q++) acc[i][j][q] = 0.f;

        #pragma unroll
        for (int ks = 0; ks < 8; ks++) {
            const int k0 = ks * 16;
            uint32_t af[4][4], bf[4][2];
            #pragma unroll
            for (int i = 0; i < 4; i++)
                ldsm_x4(af[i], ebase + ((m0 + 16*i + arow)*136 + k0 + acol8)*2);
            #pragma unroll
            for (int j = 0; j < 4; j++)
                ldsm_x2_trans(bf[j], xbase + ((k0 + (lane & 15))*136 + n0 + 8*j)*2);
            #pragma unroll
            for (int i = 0; i < 4; i++)
                #pragma unroll
                for (int j = 0; j < 4; j++)
                    mma16816(acc[i][j], af[i], bf[j]);
        }

        float* ob = out + b*C*NPIX;
        #pragma unroll
        for (int i = 0; i < 4; i++) {
            const int row = m0 + 16*i + gr;
            const float e0a = g_e0[b*C + row];
            const float e0b = g_e0[b*C + row + 8];
            #pragma unroll
            for (int j = 0; j < 4; j++) {
                const int col = n0 + 8*j + 2*ci;
                const float2 xa = *(const float2*)&xb[row*NPIX + nb + col];
                const float2 xc = *(const float2*)&xb[(row + 8)*NPIX + nb + col];
                *(float2*)&ob[row*NPIX + nb + col] =
                    make_float2(acc[i][j][0] + xa.x + e0a, acc[i][j][1] + xa.y + e0a);
                *(float2*)&ob[(row + 8)*NPIX + nb + col] =
                    make_float2(acc[i][j][2] + xc.x + e0b, acc[i][j][3] + xc.y + e0b);
            }
        }
    }
}

// ---------------- host launcher ----------------------------------------------
extern "C" void kernel_launch(void* const* d_in, const int* in_sizes, int n_in,
                              void* d_out, int out_size) {
    (void)in_sizes; (void)n_in; (void)out_size;
    const float* x   = (const float*)d_in[0];
    const float* w_q = (const float*)d_in[1];
    const float* b_q = (const float*)d_in[2];
    const float* w_k = (const float*)d_in[3];
    const float* b_k = (const float*)d_in[4];
    const float* w_v = (const float*)d_in[5];
    const float* b_v = (const float*)d_in[6];
    const float* w_o = (const float*)d_in[7];
    const float* b_o = (const float*)d_in[8];
    float* out = (float*)d_out;

    cudaFuncSetAttribute(k_fused, cudaFuncAttributeMaxDynamicSharedMemorySize,
                         DYN_SMEM);
    k_fused<<<NTOT, 256, DYN_SMEM>>>(x, w_q, b_q, w_k, b_k, w_v, b_v,
                                     w_o, b_o, out);
}